// round 6
// baseline (speedup 1.0000x reference)
#include <cuda_runtime.h>
#include <cuda_bf16.h>
#include <math.h>

#define NJc 50000
#define NSc 50000
#define Ec  1600000
#define DIMc 256
#define D4c  64
#define Lc   2
#define Bc   1024
#define NNEGc 32
#define NEGRc (NNEGc*Bc)
#define WSZc (Lc*DIMc*DIMc)

typedef unsigned long long u64;
typedef unsigned int u32;
typedef unsigned short ushort_t;

// ---------------- scratch (device globals; no allocation allowed) ----------------
__device__ float g_Ej[NJc*DIMc];
__device__ float g_Es[NSc*DIMc];
__device__ float g_Gj[NJc*DIMc];
__device__ float g_Gs[NSc*DIMc];
__device__ float g_sEj[NJc*DIMc];
__device__ float g_sEs[NSc*DIMc];
__device__ float g_sGj[NJc*DIMc];
__device__ float g_sGs[NSc*DIMc];
__device__ float g_Tje[NJc*DIMc];
__device__ float g_Tjg[NJc*DIMc];
__device__ float g_Tse[NSc*DIMc];
__device__ float g_Tsg[NSc*DIMc];
__device__ int   g_cnt_j[NJc];
__device__ int   g_cnt_s[NSc];
__device__ int   g_ptr_j[NJc+1];
__device__ int   g_ptr_s[NSc+1];
__device__ int   g_cur_j[NJc];
__device__ int   g_cur_s[NSc];
__device__ int   g_ccol_j[Ec];
__device__ float g_cval_j[Ec];
__device__ int   g_ccol_s[Ec];
__device__ float g_cval_s[Ec];
__device__ float g_gjsel[Bc*DIMc];
__device__ float g_ejsel[Bc*DIMc];
__device__ float g_gssel[Bc*DIMc];
__device__ float g_essel[Bc*DIMc];
__device__ float g_negemb[NEGRc*DIMc];
__device__ float g_sumexp_j[Bc];
__device__ float g_sumexp_s[Bc*NNEGc];
__device__ float g_scalars[8];
// pre-split weights: 4 tensors x 2 layers x 256 x 256, hi & lo bf16
__device__ ushort_t g_Wh[4*Lc*DIMc*DIMc];
__device__ ushort_t g_Wl[4*Lc*DIMc*DIMc];

// ---------------- helpers ----------------
__device__ __forceinline__ u32 smem_u32(const void* p) {
    u32 a;
    asm("{ .reg .u64 t; cvta.to.shared.u64 t, %1; cvt.u32.u64 %0, t; }" : "=r"(a) : "l"(p));
    return a;
}
__device__ __forceinline__ ushort_t f2bf(float x) {
    return __bfloat16_as_ushort(__float2bfloat16_rn(x));
}
__device__ __forceinline__ float bf2f(ushort_t u) {
    return __bfloat162float(__ushort_as_bfloat16(u));
}
// split a pair of fp32 into packed-bf16 hi + packed-bf16 residual (memory order x0,x1)
__device__ __forceinline__ void split2(float x0, float x1, u32& h, u32& lo) {
    asm("cvt.rn.bf16x2.f32 %0, %1, %2;" : "=r"(h) : "f"(x1), "f"(x0));
    float r0 = x0 - __uint_as_float(h << 16);
    float r1 = x1 - __uint_as_float(h & 0xffff0000u);
    asm("cvt.rn.bf16x2.f32 %0, %1, %2;" : "=r"(lo) : "f"(r1), "f"(r0));
}

#define LDSM4(r0, r1, r2, r3, addr) \
    asm volatile("ldmatrix.sync.aligned.m8n8.x4.shared.b16 {%0,%1,%2,%3}, [%4];" \
        : "=r"(r0), "=r"(r1), "=r"(r2), "=r"(r3) : "r"(addr))

#define MMA16816(c, a, b) \
    asm volatile("mma.sync.aligned.m16n8k16.row.col.f32.bf16.bf16.f32 " \
        "{%0,%1,%2,%3}, {%4,%5,%6,%7}, {%8,%9}, {%0,%1,%2,%3};" \
        : "+f"((c)[0]), "+f"((c)[1]), "+f"((c)[2]), "+f"((c)[3]) \
        : "r"((a)[0]), "r"((a)[1]), "r"((a)[2]), "r"((a)[3]), "r"((b)[0]), "r"((b)[1]))

// ---------------- small utility kernels ----------------
__global__ void zero_kernel() {
    int i = blockIdx.x * blockDim.x + threadIdx.x;
    int st = gridDim.x * blockDim.x;
    for (int k = i; k < NJc; k += st) g_cnt_j[k] = 0;
    for (int k = i; k < NSc; k += st) g_cnt_s[k] = 0;
    for (int k = i; k < Bc; k += st) g_sumexp_j[k] = 0.f;
    for (int k = i; k < Bc*NNEGc; k += st) g_sumexp_s[k] = 0.f;
    if (i < 8) g_scalars[i] = 0.f;
}

__global__ void count_kernel(const int* __restrict__ row_j, const int* __restrict__ col_s) {
    int i = blockIdx.x * blockDim.x + threadIdx.x;
    if (i < Ec) {
        atomicAdd(&g_cnt_j[row_j[i]], 1);
        atomicAdd(&g_cnt_s[col_s[i]], 1);
    }
}

// split W into bf16 hi/lo once
__global__ void wconv_kernel(const float* __restrict__ W_j, const float* __restrict__ W_s,
                             const float* __restrict__ W_j_aug, const float* __restrict__ W_s_aug) {
    int i = blockIdx.x * blockDim.x + threadIdx.x;
    if (i >= 4*Lc*DIMc*DIMc) return;
    int t = i >> 17;                // 131072 per tensor
    int r = i & 131071;
    const float* src = (t == 0) ? W_j : (t == 1) ? W_s : (t == 2) ? W_j_aug : W_s_aug;
    float x = src[r];
    ushort_t h = f2bf(x);
    ushort_t l = f2bf(x - bf2f(h));
    g_Wh[i] = h; g_Wl[i] = l;
}

__global__ void scan2_kernel() {
    const int* cnt = blockIdx.x ? g_cnt_s : g_cnt_j;
    int* ptr = blockIdx.x ? g_ptr_s : g_ptr_j;
    int* cur = blockIdx.x ? g_cur_s : g_cur_j;
    int n = blockIdx.x ? NSc : NJc;
    __shared__ int warp_sums[32];
    __shared__ int s_carry;
    int tid = threadIdx.x;
    if (tid == 0) { s_carry = 0; ptr[0] = 0; }
    __syncthreads();
    for (int base = 0; base < n; base += 1024) {
        int i = base + tid;
        int v = (i < n) ? cnt[i] : 0;
        int inc = v;
        #pragma unroll
        for (int off = 1; off < 32; off <<= 1) {
            int t = __shfl_up_sync(0xffffffffu, inc, off);
            if ((tid & 31) >= off) inc += t;
        }
        if ((tid & 31) == 31) warp_sums[tid >> 5] = inc;
        __syncthreads();
        if (tid < 32) {
            int ws = warp_sums[tid];
            int wi = ws;
            #pragma unroll
            for (int off = 1; off < 32; off <<= 1) {
                int t = __shfl_up_sync(0xffffffffu, wi, off);
                if (tid >= off) wi += t;
            }
            warp_sums[tid] = wi - ws;
        }
        __syncthreads();
        int excl = inc - v + warp_sums[tid >> 5];
        int carry = s_carry;
        if (i < n) {
            int start = carry + excl;
            cur[i] = start;
            ptr[i + 1] = start + v;
        }
        __syncthreads();
        if (tid == 1023) s_carry = carry + excl + v;
        __syncthreads();
    }
}

__global__ void scatter_kernel(const int* __restrict__ row_j, const int* __restrict__ col_j,
                               const float* __restrict__ val_j,
                               const int* __restrict__ row_s, const int* __restrict__ col_s,
                               const float* __restrict__ val_s) {
    int i = blockIdx.x * blockDim.x + threadIdx.x;
    if (i >= Ec) return;
    int p = atomicAdd(&g_cur_j[row_j[i]], 1);
    g_ccol_j[p] = col_j[i]; g_cval_j[p] = val_j[i];
    int q = atomicAdd(&g_cur_s[col_s[i]], 1);
    g_ccol_s[q] = row_s[i]; g_cval_s[q] = val_s[i];
}

// ---------------- fused row l2 normalize over up to 4 arrays ----------------
__global__ void l2norm4_kernel(const float4* s0, float4* d0, const float4* s1, float4* d1,
                               const float4* s2, float4* d2, const float4* s3, float4* d3,
                               int n) {
    const float4* src; float4* dst;
    switch (blockIdx.y) {
        case 0: src = s0; dst = d0; break;
        case 1: src = s1; dst = d1; break;
        case 2: src = s2; dst = d2; break;
        default: src = s3; dst = d3; break;
    }
    int w = (blockIdx.x * blockDim.x + threadIdx.x) >> 5;
    int lane = threadIdx.x & 31;
    if (w >= n) return;
    const float4* s = src + (size_t)w * D4c;
    float4 u0 = s[lane], u1 = s[lane + 32];
    float ss = u0.x*u0.x + u0.y*u0.y + u0.z*u0.z + u0.w*u0.w
             + u1.x*u1.x + u1.y*u1.y + u1.z*u1.z + u1.w*u1.w;
    #pragma unroll
    for (int o = 16; o; o >>= 1) ss += __shfl_xor_sync(0xffffffffu, ss, o);
    float inv = 1.f / fmaxf(sqrtf(ss), 1e-12f);
    float4* d = dst + (size_t)w * D4c;
    d[lane]      = make_float4(u0.x*inv, u0.y*inv, u0.z*inv, u0.w*inv);
    d[lane + 32] = make_float4(u1.x*inv, u1.y*inv, u1.z*inv, u1.w*inv);
}

// ---------------- fused dual SPMM (two CSR problems via blockIdx.y) ----------
__device__ __forceinline__ void fma4(float4& acc, float v, const float4& u) {
    acc.x = fmaf(v, u.x, acc.x);
    acc.y = fmaf(v, u.y, acc.y);
    acc.z = fmaf(v, u.z, acc.z);
    acc.w = fmaf(v, u.w, acc.w);
}

__global__ __launch_bounds__(256) void spmm_dual2_kernel(
    const int* __restrict__ ptrA, const int* __restrict__ colsA, const float* __restrict__ valsA,
    const float4* __restrict__ XA1, const float4* __restrict__ XA2,
    float4* __restrict__ OA1, float4* __restrict__ OA2,
    const int* __restrict__ ptrB, const int* __restrict__ colsB, const float* __restrict__ valsB,
    const float4* __restrict__ XB1, const float4* __restrict__ XB2,
    float4* __restrict__ OB1, float4* __restrict__ OB2, int n)
{
    const int *ptr, *cols; const float* vals;
    const float4 *X1, *X2; float4 *O1, *O2;
    if (blockIdx.y == 0) { ptr = ptrA; cols = colsA; vals = valsA; X1 = XA1; X2 = XA2; O1 = OA1; O2 = OA2; }
    else                 { ptr = ptrB; cols = colsB; vals = valsB; X1 = XB1; X2 = XB2; O1 = OB1; O2 = OB2; }
    int w = (blockIdx.x * blockDim.x + threadIdx.x) >> 5;
    int lane = threadIdx.x & 31;
    if (w >= n) return;
    int s = ptr[w], e = ptr[w + 1];
    float4 z = make_float4(0.f, 0.f, 0.f, 0.f);
    float4 a0 = z, a1 = z, b0 = z, b1 = z;
    int p = s;
    for (; p + 2 <= e; p += 2) {
        int c0 = cols[p], c1 = cols[p + 1];
        float v0 = vals[p], v1 = vals[p + 1];
        const float4* x10 = X1 + (size_t)c0 * D4c;
        const float4* x20 = X2 + (size_t)c0 * D4c;
        const float4* x11 = X1 + (size_t)c1 * D4c;
        const float4* x21 = X2 + (size_t)c1 * D4c;
        float4 p0 = x10[lane], p1 = x10[lane + 32];
        float4 q0 = x20[lane], q1 = x20[lane + 32];
        float4 r0 = x11[lane], r1 = x11[lane + 32];
        float4 t0 = x21[lane], t1 = x21[lane + 32];
        fma4(a0, v0, p0); fma4(a1, v0, p1); fma4(b0, v0, q0); fma4(b1, v0, q1);
        fma4(a0, v1, r0); fma4(a1, v1, r1); fma4(b0, v1, t0); fma4(b1, v1, t1);
    }
    if (p < e) {
        int c0 = cols[p]; float v0 = vals[p];
        const float4* x10 = X1 + (size_t)c0 * D4c;
        const float4* x20 = X2 + (size_t)c0 * D4c;
        float4 p0 = x10[lane], p1 = x10[lane + 32];
        float4 q0 = x20[lane], q1 = x20[lane + 32];
        fma4(a0, v0, p0); fma4(a1, v0, p1); fma4(b0, v0, q0); fma4(b1, v0, q1);
    }
    O1[(size_t)w * D4c + lane] = a0; O1[(size_t)w * D4c + 32 + lane] = a1;
    O2[(size_t)w * D4c + lane] = b0; O2[(size_t)w * D4c + 32 + lane] = b1;
}

// ---------------- HMMA (mma.sync bf16) update-GEMM, 4 problems x 2 col tiles ----------------
// C[128,128] = T[tile,256] @ W[colTile,256]^T with 2-term bf16 split (3 mma passes).
// out = old + relu(C); sum = first ? old + out : sum + out
#define APAD 40   // 32 k-elements + 8 pad (80B row stride; r*5 mod 8 -> conflict-free)

__global__ __launch_bounds__(256, 2) void gemm4_kernel(
    const float* __restrict__ T0, const float* __restrict__ old0, float* __restrict__ out0, float* __restrict__ sum0,
    const float* __restrict__ T1, const float* __restrict__ old1, float* __restrict__ out1, float* __restrict__ sum1,
    const float* __restrict__ T2, const float* __restrict__ old2, float* __restrict__ out2, float* __restrict__ sum2,
    const float* __restrict__ T3, const float* __restrict__ old3, float* __restrict__ out3, float* __restrict__ sum3,
    int l, int first, int M)
{
    __shared__ __align__(16) ushort_t sAh[128][APAD];
    __shared__ __align__(16) ushort_t sAl[128][APAD];
    __shared__ __align__(16) ushort_t sWh[128][APAD];
    __shared__ __align__(16) ushort_t sWl[128][APAD];

    int tid = threadIdx.x;
    int lane = tid & 31;
    int warp = tid >> 5;
    int prob = blockIdx.y >> 1;
    int colTile = (blockIdx.y & 1) * 128;
    int rowTile = blockIdx.x * 128;

    const float* T; const float* oldv; float* outv; float* sumv;
    switch (prob) {
        case 0: T = T0; oldv = old0; outv = out0; sumv = sum0; break;
        case 1: T = T1; oldv = old1; outv = out1; sumv = sum1; break;
        case 2: T = T2; oldv = old2; outv = out2; sumv = sum2; break;
        default: T = T3; oldv = old3; outv = out3; sumv = sum3; break;
    }
    int moff = prob * 131072 + l * 65536;
    const ushort_t* Wh = g_Wh + moff;
    const ushort_t* Wl = g_Wl + moff;

    int lrow = tid >> 1;             // 0..127
    int ks = (tid & 1) * 16;         // 0 or 16
    const float* Ag = T + (size_t)(rowTile + lrow) * DIMc + ks;
    bool aok = (rowTile + lrow) < M;
    const ushort_t* Wgh = Wh + (size_t)(colTile + lrow) * DIMc + ks;
    const ushort_t* Wgl = Wl + (size_t)(colTile + lrow) * DIMc + ks;

    int wm = (warp >> 2) * 64;       // 0 or 64
    int wn = (warp & 3) * 32;        // 0,32,64,96

    float acc[4][4][4];
    #pragma unroll
    for (int mi = 0; mi < 4; mi++)
        #pragma unroll
        for (int ni = 0; ni < 4; ni++)
            #pragma unroll
            for (int q = 0; q < 4; q++) acc[mi][ni][q] = 0.f;

    // precomputed ldmatrix smem addresses (byte offsets advance per chunk)
    int arow = lane & 15;
    int achk = (lane >> 4) * 16;     // byte offset
    int brow = ((lane >> 4) & 1) * 8 + (lane & 7);
    int bchk = ((lane >> 3) & 1) * 16;

    for (int kc = 0; kc < 8; kc++) {
        int k0 = kc * 32;
        float x[16];
        if (aok) {
            float4 v0 = *(const float4*)(Ag + k0);
            float4 v1 = *(const float4*)(Ag + k0 + 4);
            float4 v2 = *(const float4*)(Ag + k0 + 8);
            float4 v3 = *(const float4*)(Ag + k0 + 12);
            x[0]=v0.x; x[1]=v0.y; x[2]=v0.z; x[3]=v0.w;
            x[4]=v1.x; x[5]=v1.y; x[6]=v1.z; x[7]=v1.w;
            x[8]=v2.x; x[9]=v2.y; x[10]=v2.z; x[11]=v2.w;
            x[12]=v3.x; x[13]=v3.y; x[14]=v3.z; x[15]=v3.w;
        } else {
            #pragma unroll
            for (int q = 0; q < 16; q++) x[q] = 0.f;
        }
        uint4 wh0 = *(const uint4*)(Wgh + k0);
        uint4 wh1 = *(const uint4*)(Wgh + k0 + 8);
        uint4 wl0 = *(const uint4*)(Wgl + k0);
        uint4 wl1 = *(const uint4*)(Wgl + k0 + 8);

        u32 h[8], lo[8];
        #pragma unroll
        for (int q = 0; q < 8; q++) split2(x[2*q], x[2*q+1], h[q], lo[q]);

        __syncthreads();   // previous iteration's compute done
        *(uint4*)&sAh[lrow][ks]     = make_uint4(h[0], h[1], h[2], h[3]);
        *(uint4*)&sAh[lrow][ks + 8] = make_uint4(h[4], h[5], h[6], h[7]);
        *(uint4*)&sAl[lrow][ks]     = make_uint4(lo[0], lo[1], lo[2], lo[3]);
        *(uint4*)&sAl[lrow][ks + 8] = make_uint4(lo[4], lo[5], lo[6], lo[7]);
        *(uint4*)&sWh[lrow][ks]     = wh0;
        *(uint4*)&sWh[lrow][ks + 8] = wh1;
        *(uint4*)&sWl[lrow][ks]     = wl0;
        *(uint4*)&sWl[lrow][ks + 8] = wl1;
        __syncthreads();

        #pragma unroll
        for (int kk = 0; kk < 2; kk++) {
            int kb = kk * 32;        // byte offset of k16 within chunk
            u32 bh[4][2], bl[4][2];
            #pragma unroll
            for (int nh = 0; nh < 2; nh++) {
                int r = wn + nh * 16 + brow;
                u32 ah = smem_u32(&sWh[r][0]) + kb + bchk;
                u32 al = smem_u32(&sWl[r][0]) + kb + bchk;
                LDSM4(bh[nh*2][0], bh[nh*2][1], bh[nh*2+1][0], bh[nh*2+1][1], ah);
                LDSM4(bl[nh*2][0], bl[nh*2][1], bl[nh*2+1][0], bl[nh*2+1][1], al);
            }
            #pragma unroll
            for (int mi = 0; mi < 4; mi++) {
                int r = wm + mi * 16 + arow;
                u32 aah = smem_u32(&sAh[r][0]) + kb + achk;
                u32 aal = smem_u32(&sAl[r][0]) + kb + achk;
                u32 fh[4], fl[4];
                LDSM4(fh[0], fh[1], fh[2], fh[3], aah);
                LDSM4(fl[0], fl[1], fl[2], fl[3], aal);
                #pragma unroll
                for (int ni = 0; ni < 4; ni++) {
                    MMA16816(acc[mi][ni], fh, bh[ni]);
                    MMA16816(acc[mi][ni], fl, bh[ni]);
                    MMA16816(acc[mi][ni], fh, bl[ni]);
                }
            }
        }
    }

    // epilogue
    #pragma unroll
    for (int mi = 0; mi < 4; mi++) {
        #pragma unroll
        for (int half = 0; half < 2; half++) {
            int gr = rowTile + wm + mi * 16 + (lane >> 2) + half * 8;
            if (gr < M) {
                #pragma unroll
                for (int ni = 0; ni < 4; ni++) {
                    int gc = colTile + wn + ni * 8 + (lane & 3) * 2;
                    size_t idx = (size_t)gr * DIMc + gc;
                    float c0 = acc[mi][ni][half * 2];
                    float c1 = acc[mi][ni][half * 2 + 1];
                    float2 o = *(const float2*)(oldv + idx);
                    float2 nv;
                    nv.x = o.x + fmaxf(c0, 0.f);
                    nv.y = o.y + fmaxf(c1, 0.f);
                    *(float2*)(outv + idx) = nv;
                    float2 sv;
                    if (first) { sv.x = o.x + nv.x; sv.y = o.y + nv.y; }
                    else { float2 s = *(const float2*)(sumv + idx); sv.x = s.x + nv.x; sv.y = s.y + nv.y; }
                    *(float2*)(sumv + idx) = sv;
                }
            }
        }
    }
}

// ---------------- f32x2 GEMM + exp + per-(row,group) sum ----------------
__device__ __forceinline__ u64 dupf(float x) {
    u64 u;
    asm("mov.b64 %0, {%1, %1};" : "=l"(u) : "f"(x));
    return u;
}
__device__ __forceinline__ void unpackf(u64 v, float& lo, float& hi) {
    asm("mov.b64 {%0, %1}, %2;" : "=f"(lo), "=f"(hi) : "l"(v));
}
#define FMA2(d, a, b) asm("fma.rn.f32x2 %0, %1, %2, %0;" : "+l"(d) : "l"(a), "l"(b))

__global__ __launch_bounds__(256, 2) void expsum_kernel(
    const float* __restrict__ A, const float* __restrict__ Bm,
    float* __restrict__ sumexp, int ngroups)
{
    __shared__ float As2[16][256];
    __shared__ float Bs[16][128];
    __shared__ float red[128];
    int tid = threadIdx.x;
    int tx = tid & 15, ty = tid >> 4;
    int rowTile = blockIdx.y * 128;
    int colTile = blockIdx.x * 128;
    u64 acc2[8][4];
    #pragma unroll
    for (int i = 0; i < 8; i++)
        #pragma unroll
        for (int p = 0; p < 4; p++) acc2[i][p] = 0ull;

    int lrow = tid & 127;
    int khalf = (tid >> 7) * 8;
    const float* Ag = A + (size_t)(rowTile + lrow) * DIMc + khalf;
    const float* Bg = Bm + (size_t)(colTile + lrow) * DIMc + khalf;

    for (int k0 = 0; k0 < DIMc; k0 += 16) {
        float4 ra0 = *(const float4*)(Ag + k0);
        float4 ra1 = *(const float4*)(Ag + k0 + 4);
        float4 rb0 = *(const float4*)(Bg + k0);
        float4 rb1 = *(const float4*)(Bg + k0 + 4);
        __syncthreads();
        *(u64*)&As2[khalf+0][2*lrow] = dupf(ra0.x);
        *(u64*)&As2[khalf+1][2*lrow] = dupf(ra0.y);
        *(u64*)&As2[khalf+2][2*lrow] = dupf(ra0.z);
        *(u64*)&As2[khalf+3][2*lrow] = dupf(ra0.w);
        *(u64*)&As2[khalf+4][2*lrow] = dupf(ra1.x);
        *(u64*)&As2[khalf+5][2*lrow] = dupf(ra1.y);
        *(u64*)&As2[khalf+6][2*lrow] = dupf(ra1.z);
        *(u64*)&As2[khalf+7][2*lrow] = dupf(ra1.w);
        Bs[khalf+0][lrow] = rb0.x; Bs[khalf+1][lrow] = rb0.y;
        Bs[khalf+2][lrow] = rb0.z; Bs[khalf+3][lrow] = rb0.w;
        Bs[khalf+4][lrow] = rb1.x; Bs[khalf+5][lrow] = rb1.y;
        Bs[khalf+6][lrow] = rb1.z; Bs[khalf+7][lrow] = rb1.w;
        __syncthreads();
        #pragma unroll
        for (int kk = 0; kk < 16; kk++) {
            u64 a2[8], b2[4];
            #pragma unroll
            for (int i = 0; i < 4; i++) {
                a2[i]   = *(const u64*)&As2[kk][2*(ty*4 + i)];
                a2[i+4] = *(const u64*)&As2[kk][2*(ty*4 + i + 64)];
            }
            b2[0] = *(const u64*)&Bs[kk][tx*4];
            b2[1] = *(const u64*)&Bs[kk][tx*4 + 2];
            b2[2] = *(const u64*)&Bs[kk][tx*4 + 64];
            b2[3] = *(const u64*)&Bs[kk][tx*4 + 66];
            #pragma unroll
            for (int i = 0; i < 8; i++)
                #pragma unroll
                for (int p = 0; p < 4; p++)
                    FMA2(acc2[i][p], a2[i], b2[p]);
        }
    }
    float rsum[8];
    #pragma unroll
    for (int i = 0; i < 8; i++) {
        rsum[i] = 0.f;
        #pragma unroll
        for (int p = 0; p < 4; p++) {
            float lo, hi;
            unpackf(acc2[i][p], lo, hi);
            rsum[i] += expf(lo * 5.0f) + expf(hi * 5.0f);   // 1/TEMP = 5
        }
    }
    if (tid < 128) red[tid] = 0.f;
    __syncthreads();
    #pragma unroll
    for (int i = 0; i < 8; i++) {
        int r = ty*4 + (i & 3) + ((i >> 2) * 64);
        atomicAdd(&red[r], rsum[i]);
    }
    __syncthreads();
    if (tid < 128) {
        int gr = rowTile + tid;
        int group = blockIdx.x >> 3;
        atomicAdd(&sumexp[(size_t)gr * ngroups + group], red[tid]);
    }
}

// ---------------- gathers ----------------
__global__ void gather4_kernel(const int* __restrict__ j_ids, const int* __restrict__ s_ids) {
    float4* dst; const float4* src; const int* ids;
    switch (blockIdx.y) {
        case 0: dst = (float4*)g_gjsel; src = (const float4*)g_sGj; ids = j_ids; break;
        case 1: dst = (float4*)g_ejsel; src = (const float4*)g_sEj; ids = j_ids; break;
        case 2: dst = (float4*)g_gssel; src = (const float4*)g_sGs; ids = s_ids; break;
        default: dst = (float4*)g_essel; src = (const float4*)g_sEs; ids = s_ids; break;
    }
    int row = blockIdx.x;
    int id = ids[row];
    dst[(size_t)row * D4c + threadIdx.x] = src[(size_t)id * D4c + threadIdx.x];
}

__global__ void gather_kernel(float4* __restrict__ dst, const float4* __restrict__ src,
                              const int* __restrict__ ids) {
    int row = blockIdx.x;
    int id = ids[row];
    dst[(size_t)row * D4c + threadIdx.x] = src[(size_t)id * D4c + threadIdx.x];
}

// ---------------- pos score ----------------
__global__ void pos_kernel() {
    int w = (blockIdx.x * blockDim.x + threadIdx.x) >> 5;
    int lane = threadIdx.x & 31;
    if (w >= Bc) return;
    const float4* gj = (const float4*)g_gjsel + (size_t)w * D4c;
    const float4* ej = (const float4*)g_ejsel + (size_t)w * D4c;
    const float4* gs = (const float4*)g_gssel + (size_t)w * D4c;
    const float4* es = (const float4*)g_essel + (size_t)w * D4c;
    float4 a0 = gj[lane], a1 = gj[lane+32], b0 = ej[lane], b1 = ej[lane+32];
    float4 c0 = gs[lane], c1 = gs[lane+32], d0 = es[lane], d1 = es[lane+32];
    float s1 = a0.x*b0.x + a0.y*b0.y + a0.z*b0.z + a0.w*b0.w
             + a1.x*b1.x + a1.y*b1.y + a1.z*b1.z + a1.w*b1.w;
    float s2 = c0.x*d0.x + c0.y*d0.y + c0.z*d0.z + c0.w*d0.w
             + c1.x*d1.x + c1.y*d1.y + c1.z*d1.z + c1.w*d1.w;
    #pragma unroll
    for (int o = 16; o; o >>= 1) {
        s1 += __shfl_xor_sync(0xffffffffu, s1, o);
        s2 += __shfl_xor_sync(0xffffffffu, s2, o);
    }
    if (lane == 0) {
        float c1v = fminf(fmaxf(s1 * 5.0f, -1.f), 1.f);
        float c2v = fminf(fmaxf(s2 * 5.0f, -1.f), 1.f);
        atomicAdd(&g_scalars[0], c1v);
        atomicAdd(&g_scalars[1], c2v);
    }
}

// ---------------- weight L2 regularizer ----------------
__global__ void wsq_kernel(const float* __restrict__ a, const float* __restrict__ b,
                           const float* __restrict__ c, const float* __restrict__ d) {
    float s = 0.f;
    for (int i = blockIdx.x * blockDim.x + threadIdx.x; i < WSZc; i += gridDim.x * blockDim.x) {
        float x;
        x = a[i]; s += x * x;
        x = b[i]; s += x * x;
        x = c[i]; s += x * x;
        x = d[i]; s += x * x;
    }
    #pragma unroll
    for (int o = 16; o; o >>= 1) s += __shfl_xor_sync(0xffffffffu, s, o);
    __shared__ float sh[8];
    int lane = threadIdx.x & 31, wid = threadIdx.x >> 5;
    if (lane == 0) sh[wid] = s;
    __syncthreads();
    if (threadIdx.x == 0) {
        float t = 0.f;
        for (int i = 0; i < (int)(blockDim.x >> 5); i++) t += sh[i];
        atomicAdd(&g_scalars[2], t);
    }
}

// ---------------- finalize ----------------
__device__ double blk_reduce_1024(double v) {
    __shared__ double sh[32];
    __syncthreads();
    int lane = threadIdx.x & 31, wid = threadIdx.x >> 5;
    #pragma unroll
    for (int o = 16; o; o >>= 1) v += __shfl_down_sync(0xffffffffu, v, o);
    if (lane == 0) sh[wid] = v;
    __syncthreads();
    v = (threadIdx.x < 32) ? sh[threadIdx.x] : 0.0;
    if (wid == 0) {
        #pragma unroll
        for (int o = 16; o; o >>= 1) v += __shfl_down_sync(0xffffffffu, v, o);
    }
    return v;
}

__global__ void finalize_kernel(float* __restrict__ out) {
    int tid = threadIdx.x;
    double a = (tid < Bc) ? log((double)g_sumexp_j[tid] + 1e-8) : 0.0;
    double negj = blk_reduce_1024(a);
    double b = 0.0;
    for (int i = tid; i < Bc * NNEGc; i += 1024)
        b += log((double)g_sumexp_s[i] + 1e-8);
    double negs = blk_reduce_1024(b);
    if (tid == 0) {
        double pos = (double)g_scalars[0] / Bc + (double)g_scalars[1] / Bc;
        double neg = negj / Bc + negs / (double)(Bc * NNEGc);
        double cl = (-pos + neg) * 0.2;
        double reg = 1e-4 * (double)g_scalars[2];
        out[0] = (float)(cl + reg);
        out[1] = (float)cl;
        out[2] = (float)reg;
    }
}

// ---------------- launch ----------------
#define SYM(p, s) do { void* _t = 0; cudaGetSymbolAddress(&_t, s); p = (decltype(p))_t; } while (0)

extern "C" void kernel_launch(void* const* d_in, const int* in_sizes, int n_in,
                              void* d_out, int out_size) {
    (void)in_sizes; (void)n_in; (void)out_size;
    const float* e_j_f   = (const float*)d_in[0];
    const float* e_s_f   = (const float*)d_in[1];
    const float* aug_e_j = (const float*)d_in[2];
    const float* aug_e_s = (const float*)d_in[3];
    const float* val_j   = (const float*)d_in[4];
    const float* val_s   = (const float*)d_in[5];
    const float* W_j     = (const float*)d_in[6];
    const float* W_s     = (const float*)d_in[7];
    const float* W_j_aug = (const float*)d_in[8];
    const float* W_s_aug = (const float*)d_in[9];
    const int* row_j = (const int*)d_in[10];
    const int* col_j = (const int*)d_in[11];
    const int* row_s = (const int*)d_in[12];
    const int* col_s = (const int*)d_in[13];
    const int* j_ids = (const int*)d_in[14];
    const int* s_ids = (const int*)d_in[15];
    const int* negs  = (const int*)d_in[16];
    float* out = (float*)d_out;

    float *Ej, *Es, *Gj, *Gs, *sEj, *sEs, *sGj, *sGs;
    float *Tje, *Tjg, *Tse, *Tsg;
    int *ptr_j, *ptr_s, *ccol_j, *ccol_s;
    float *cval_j, *cval_s;
    float *gjsel, *ejsel, *gssel, *essel, *negemb, *sumexp_j, *sumexp_s;
    SYM(Ej, g_Ej); SYM(Es, g_Es); SYM(Gj, g_Gj); SYM(Gs, g_Gs);
    SYM(sEj, g_sEj); SYM(sEs, g_sEs); SYM(sGj, g_sGj); SYM(sGs, g_sGs);
    SYM(Tje, g_Tje); SYM(Tjg, g_Tjg); SYM(Tse, g_Tse); SYM(Tsg, g_Tsg);
    SYM(ptr_j, g_ptr_j); SYM(ptr_s, g_ptr_s);
    SYM(ccol_j, g_ccol_j); SYM(ccol_s, g_ccol_s);
    SYM(cval_j, g_cval_j); SYM(cval_s, g_cval_s);
    SYM(gjsel, g_gjsel); SYM(ejsel, g_ejsel); SYM(gssel, g_gssel); SYM(essel, g_essel);
    SYM(negemb, g_negemb); SYM(sumexp_j, g_sumexp_j); SYM(sumexp_s, g_sumexp_s);

    const int EB = (Ec + 255) / 256;         // 6250
    const int RB = (NJc * 32 + 255) / 256;   // 6250

    zero_kernel<<<256, 256>>>();
    count_kernel<<<EB, 256>>>(row_j, col_s);
    scan2_kernel<<<2, 1024>>>();
    scatter_kernel<<<EB, 256>>>(row_j, col_j, val_j, row_s, col_s, val_s);
    wconv_kernel<<<(4*Lc*DIMc*DIMc + 255) / 256, 256>>>(W_j, W_s, W_j_aug, W_s_aug);

    {
        dim3 g(RB, 2);
        l2norm4_kernel<<<g, 256>>>((const float4*)aug_e_j, (float4*)Gj,
                                   (const float4*)aug_e_s, (float4*)Gs,
                                   (const float4*)aug_e_j, (float4*)Gj,
                                   (const float4*)aug_e_s, (float4*)Gs, NJc);
    }

    dim3 spmm_grid(RB, 2);
    dim3 gemm_grid((NJc + 127) / 128, 8);    // 391 x (4 problems x 2 col tiles)
    for (int l = 0; l < Lc; l++) {
        const float* EjSrc = l ? Ej : e_j_f;
        const float* EsSrc = l ? Es : e_s_f;
        spmm_dual2_kernel<<<spmm_grid, 256>>>(
            ptr_j, ccol_j, cval_j, (const float4*)EsSrc, (const float4*)Gs,
            (float4*)Tje, (float4*)Tjg,
            ptr_s, ccol_s, cval_s, (const float4*)EjSrc, (const float4*)Gj,
            (float4*)Tse, (float4*)Tsg, NJc);
        gemm4_kernel<<<gemm_grid, 256>>>(
            Tje, EjSrc, Ej, sEj,
            Tse, EsSrc, Es, sEs,
            Tjg, Gj,    Gj, sGj,
            Tsg, Gs,    Gs, sGs,
            l, l == 0, NJc);
    }

    {
        dim3 g(RB, 4);
        l2norm4_kernel<<<g, 256>>>((const float4*)sEj, (float4*)sEj,
                                   (const float4*)sEs, (float4*)sEs,
                                   (const float4*)sGj, (float4*)sGj,
                                   (const float4*)sGs, (float4*)sGs, NJc);
    }

    {
        dim3 g(Bc, 4);
        gather4_kernel<<<g, 64>>>(j_ids, s_ids);
    }
    gather_kernel<<<NEGRc, 64>>>((float4*)negemb, (const float4*)sEs, negs);

    dim3 lg(Bc / 128, Bc / 128);
    expsum_kernel<<<lg, 256>>>(gjsel, ejsel, sumexp_j, 1);
    dim3 ng(NEGRc / 128, Bc / 128);
    expsum_kernel<<<ng, 256>>>(gssel, negemb, sumexp_s, NNEGc);

    pos_kernel<<<Bc / 8, 256>>>();
    wsq_kernel<<<256, 256>>>(W_j, W_s, W_j_aug, W_s_aug);
    finalize_kernel<<<1, 1024>>>(out);
}

// round 7
// speedup vs baseline: 1.0905x; 1.0905x over previous
#include <cuda_runtime.h>
#include <math.h>

#define NJc 50000
#define NSc 50000
#define Ec  1600000
#define DIMc 256
#define D4c  64
#define Lc   2
#define Bc   1024
#define NNEGc 32
#define NEGRc (NNEGc*Bc)
#define WSZc (Lc*DIMc*DIMc)

typedef unsigned long long u64;

// combo grid structure
#define NSPMM 12500          // 2 sides x 6250 blocks (8 warps x 1 row each)
#define NGEMM 1564           // 2 problems x 391 row tiles x 2 col tiles
#define NTOT  (NSPMM + NGEMM)

// ---------------- scratch (device globals; no allocation allowed) ----------------
__device__ float g_Ej[NJc*DIMc];
__device__ float g_Es[NSc*DIMc];
__device__ float g_Gj[NJc*DIMc];
__device__ float g_Gs[NSc*DIMc];
__device__ float g_sEj[NJc*DIMc];
__device__ float g_sEs[NSc*DIMc];
__device__ float g_sGj[NJc*DIMc];
__device__ float g_sGs[NSc*DIMc];
__device__ float g_Tje[NJc*DIMc];
__device__ float g_Tjg[NJc*DIMc];
__device__ float g_Tse[NSc*DIMc];
__device__ float g_Tsg[NSc*DIMc];
__device__ int   g_cnt_j[NJc];
__device__ int   g_cnt_s[NSc];
__device__ int   g_ptr_j[NJc+1];
__device__ int   g_ptr_s[NSc+1];
__device__ int   g_cur_j[NJc];
__device__ int   g_cur_s[NSc];
__device__ int   g_ccol_j[Ec];
__device__ float g_cval_j[Ec];
__device__ int   g_ccol_s[Ec];
__device__ float g_cval_s[Ec];
__device__ float g_gjsel[Bc*DIMc];
__device__ float g_ejsel[Bc*DIMc];
__device__ float g_gssel[Bc*DIMc];
__device__ float g_essel[Bc*DIMc];
__device__ float g_negemb[NEGRc*DIMc];
__device__ float g_sumexp_j[Bc];
__device__ float g_sumexp_s[Bc*NNEGc];
__device__ float g_scalars[8];   // [0]=pos_j sum, [1]=pos_s sum, [2]=wsq

// ---------------- small utility kernels ----------------
__global__ void zero_kernel() {
    int i = blockIdx.x * blockDim.x + threadIdx.x;
    int st = gridDim.x * blockDim.x;
    for (int k = i; k < NJc; k += st) g_cnt_j[k] = 0;
    for (int k = i; k < NSc; k += st) g_cnt_s[k] = 0;
    for (int k = i; k < Bc; k += st) g_sumexp_j[k] = 0.f;
    for (int k = i; k < Bc*NNEGc; k += st) g_sumexp_s[k] = 0.f;
    if (i < 8) g_scalars[i] = 0.f;
}

__global__ void count_kernel(const int* __restrict__ row_j, const int* __restrict__ col_s) {
    int i = blockIdx.x * blockDim.x + threadIdx.x;
    if (i < Ec) {
        atomicAdd(&g_cnt_j[row_j[i]], 1);
        atomicAdd(&g_cnt_s[col_s[i]], 1);
    }
}

// dual single-block exclusive scan: blockIdx.x = 0 -> j arrays, 1 -> s arrays
__global__ void scan2_kernel() {
    const int* cnt = blockIdx.x ? g_cnt_s : g_cnt_j;
    int* ptr = blockIdx.x ? g_ptr_s : g_ptr_j;
    int* cur = blockIdx.x ? g_cur_s : g_cur_j;
    int n = blockIdx.x ? NSc : NJc;
    __shared__ int warp_sums[32];
    __shared__ int s_carry;
    int tid = threadIdx.x;
    if (tid == 0) { s_carry = 0; ptr[0] = 0; }
    __syncthreads();
    for (int base = 0; base < n; base += 1024) {
        int i = base + tid;
        int v = (i < n) ? cnt[i] : 0;
        int inc = v;
        #pragma unroll
        for (int off = 1; off < 32; off <<= 1) {
            int t = __shfl_up_sync(0xffffffffu, inc, off);
            if ((tid & 31) >= off) inc += t;
        }
        if ((tid & 31) == 31) warp_sums[tid >> 5] = inc;
        __syncthreads();
        if (tid < 32) {
            int ws = warp_sums[tid];
            int wi = ws;
            #pragma unroll
            for (int off = 1; off < 32; off <<= 1) {
                int t = __shfl_up_sync(0xffffffffu, wi, off);
                if (tid >= off) wi += t;
            }
            warp_sums[tid] = wi - ws;   // exclusive warp offset
        }
        __syncthreads();
        int excl = inc - v + warp_sums[tid >> 5];
        int carry = s_carry;
        if (i < n) {
            int start = carry + excl;
            cur[i] = start;
            ptr[i + 1] = start + v;
        }
        __syncthreads();
        if (tid == 1023) s_carry = carry + excl + v;
        __syncthreads();
    }
}

__global__ void scatter_kernel(const int* __restrict__ row_j, const int* __restrict__ col_j,
                               const float* __restrict__ val_j,
                               const int* __restrict__ row_s, const int* __restrict__ col_s,
                               const float* __restrict__ val_s) {
    int i = blockIdx.x * blockDim.x + threadIdx.x;
    if (i >= Ec) return;
    int p = atomicAdd(&g_cur_j[row_j[i]], 1);
    g_ccol_j[p] = col_j[i]; g_cval_j[p] = val_j[i];
    int q = atomicAdd(&g_cur_s[col_s[i]], 1);
    g_ccol_s[q] = row_s[i]; g_cval_s[q] = val_s[i];
}

// ---------------- fused row l2 normalize over up to 4 arrays ----------------
__global__ void l2norm4_kernel(const float4* s0, float4* d0, const float4* s1, float4* d1,
                               const float4* s2, float4* d2, const float4* s3, float4* d3,
                               int n) {
    const float4* src; float4* dst;
    switch (blockIdx.y) {
        case 0: src = s0; dst = d0; break;
        case 1: src = s1; dst = d1; break;
        case 2: src = s2; dst = d2; break;
        default: src = s3; dst = d3; break;
    }
    int w = (blockIdx.x * blockDim.x + threadIdx.x) >> 5;
    int lane = threadIdx.x & 31;
    if (w >= n) return;
    const float4* s = src + (size_t)w * D4c;
    float4 u0 = s[lane], u1 = s[lane + 32];
    float ss = u0.x*u0.x + u0.y*u0.y + u0.z*u0.z + u0.w*u0.w
             + u1.x*u1.x + u1.y*u1.y + u1.z*u1.z + u1.w*u1.w;
    #pragma unroll
    for (int o = 16; o; o >>= 1) ss += __shfl_xor_sync(0xffffffffu, ss, o);
    float inv = 1.f / fmaxf(sqrtf(ss), 1e-12f);
    float4* d = dst + (size_t)w * D4c;
    d[lane]      = make_float4(u0.x*inv, u0.y*inv, u0.z*inv, u0.w*inv);
    d[lane + 32] = make_float4(u1.x*inv, u1.y*inv, u1.z*inv, u1.w*inv);
}

// ---------------- SPMM row body (single dense operand, warp per row) ----------------
__device__ __forceinline__ void fma4(float4& acc, float v, const float4& u) {
    acc.x = fmaf(v, u.x, acc.x);
    acc.y = fmaf(v, u.y, acc.y);
    acc.z = fmaf(v, u.z, acc.z);
    acc.w = fmaf(v, u.w, acc.w);
}

__device__ __forceinline__ void spmm_row(
    const int* __restrict__ ptr, const int* __restrict__ cols, const float* __restrict__ vals,
    const float4* __restrict__ X, float4* __restrict__ O, int w, int lane)
{
    int s = ptr[w], e = ptr[w + 1];
    float4 z = make_float4(0.f, 0.f, 0.f, 0.f);
    float4 a0 = z, a1 = z;
    int p = s;
    for (; p + 4 <= e; p += 4) {
        int c0 = cols[p], c1 = cols[p+1], c2 = cols[p+2], c3 = cols[p+3];
        float v0 = vals[p], v1 = vals[p+1], v2 = vals[p+2], v3 = vals[p+3];
        const float4* x0 = X + (size_t)c0 * D4c;
        const float4* x1 = X + (size_t)c1 * D4c;
        const float4* x2 = X + (size_t)c2 * D4c;
        const float4* x3 = X + (size_t)c3 * D4c;
        float4 p00 = x0[lane], p01 = x0[lane + 32];
        float4 p10 = x1[lane], p11 = x1[lane + 32];
        float4 p20 = x2[lane], p21 = x2[lane + 32];
        float4 p30 = x3[lane], p31 = x3[lane + 32];
        fma4(a0, v0, p00); fma4(a1, v0, p01);
        fma4(a0, v1, p10); fma4(a1, v1, p11);
        fma4(a0, v2, p20); fma4(a1, v2, p21);
        fma4(a0, v3, p30); fma4(a1, v3, p31);
    }
    for (; p < e; p++) {
        int c0 = cols[p]; float v0 = vals[p];
        const float4* x0 = X + (size_t)c0 * D4c;
        float4 p00 = x0[lane], p01 = x0[lane + 32];
        fma4(a0, v0, p00); fma4(a1, v0, p01);
    }
    O[(size_t)w * D4c + lane] = a0;
    O[(size_t)w * D4c + 32 + lane] = a1;
}

// ---------------- GEMM tile body (R3 double-buffered 128x128x16 NT + fused epilogue) ------
// out = old + relu(A @ W^T); sum = first ? old + out : sum + out
__device__ __forceinline__ void gemm_tile(
    const float* __restrict__ A, const float* __restrict__ W,
    const float* __restrict__ oldv, float* __restrict__ outv, float* __restrict__ sumv,
    int M, int first, int rowTile, int colTile,
    float (&As)[2][16][128], float (&Bs)[2][16][128])
{
    int tid = threadIdx.x;
    int tx = tid & 15, ty = tid >> 4;
    float acc[8][8];
    #pragma unroll
    for (int i = 0; i < 8; i++)
        #pragma unroll
        for (int j = 0; j < 8; j++) acc[i][j] = 0.f;

    int lrow = tid & 127;
    int khalf = (tid >> 7) * 8;      // 0 or 8
    const float* Ag = A + (size_t)(rowTile + lrow) * DIMc + khalf;
    const float* Wg = W + (size_t)(colTile + lrow) * DIMc + khalf;
    bool arow_ok = (rowTile + lrow) < M;
    const float4 z4 = make_float4(0.f, 0.f, 0.f, 0.f);

    float4 ra0 = arow_ok ? *(const float4*)(Ag + 0) : z4;
    float4 ra1 = arow_ok ? *(const float4*)(Ag + 4) : z4;
    float4 rb0 = *(const float4*)(Wg + 0);
    float4 rb1 = *(const float4*)(Wg + 4);
    As[0][khalf+0][lrow] = ra0.x; As[0][khalf+1][lrow] = ra0.y;
    As[0][khalf+2][lrow] = ra0.z; As[0][khalf+3][lrow] = ra0.w;
    As[0][khalf+4][lrow] = ra1.x; As[0][khalf+5][lrow] = ra1.y;
    As[0][khalf+6][lrow] = ra1.z; As[0][khalf+7][lrow] = ra1.w;
    Bs[0][khalf+0][lrow] = rb0.x; Bs[0][khalf+1][lrow] = rb0.y;
    Bs[0][khalf+2][lrow] = rb0.z; Bs[0][khalf+3][lrow] = rb0.w;
    Bs[0][khalf+4][lrow] = rb1.x; Bs[0][khalf+5][lrow] = rb1.y;
    Bs[0][khalf+6][lrow] = rb1.z; Bs[0][khalf+7][lrow] = rb1.w;
    __syncthreads();

    int buf = 0;
    for (int k0 = 16; k0 <= DIMc; k0 += 16) {
        bool more = k0 < DIMc;
        if (more) {
            ra0 = arow_ok ? *(const float4*)(Ag + k0) : z4;
            ra1 = arow_ok ? *(const float4*)(Ag + k0 + 4) : z4;
            rb0 = *(const float4*)(Wg + k0);
            rb1 = *(const float4*)(Wg + k0 + 4);
        }
        #pragma unroll
        for (int kk = 0; kk < 16; kk++) {
            float a[8], b[8];
            #pragma unroll
            for (int i = 0; i < 4; i++) {
                a[i]   = As[buf][kk][ty*4 + i];
                a[i+4] = As[buf][kk][ty*4 + i + 64];
                b[i]   = Bs[buf][kk][tx*4 + i];
                b[i+4] = Bs[buf][kk][tx*4 + i + 64];
            }
            #pragma unroll
            for (int i = 0; i < 8; i++)
                #pragma unroll
                for (int j = 0; j < 8; j++)
                    acc[i][j] = fmaf(a[i], b[j], acc[i][j]);
        }
        if (more) {
            int nb = buf ^ 1;
            As[nb][khalf+0][lrow] = ra0.x; As[nb][khalf+1][lrow] = ra0.y;
            As[nb][khalf+2][lrow] = ra0.z; As[nb][khalf+3][lrow] = ra0.w;
            As[nb][khalf+4][lrow] = ra1.x; As[nb][khalf+5][lrow] = ra1.y;
            As[nb][khalf+6][lrow] = ra1.z; As[nb][khalf+7][lrow] = ra1.w;
            Bs[nb][khalf+0][lrow] = rb0.x; Bs[nb][khalf+1][lrow] = rb0.y;
            Bs[nb][khalf+2][lrow] = rb0.z; Bs[nb][khalf+3][lrow] = rb0.w;
            Bs[nb][khalf+4][lrow] = rb1.x; Bs[nb][khalf+5][lrow] = rb1.y;
            Bs[nb][khalf+6][lrow] = rb1.z; Bs[nb][khalf+7][lrow] = rb1.w;
            __syncthreads();
            buf = nb;
        }
    }
    #pragma unroll
    for (int i = 0; i < 8; i++) {
        int gr = rowTile + ty*4 + (i & 3) + ((i >> 2) * 64);
        if (gr < M) {
            #pragma unroll
            for (int j = 0; j < 8; j++) {
                int gc = colTile + tx*4 + (j & 3) + ((j >> 2) * 64);
                size_t idx = (size_t)gr * DIMc + gc;
                float v = fmaxf(acc[i][j], 0.f);
                float o = oldv[idx];
                float nv = o + v;
                outv[idx] = nv;
                sumv[idx] = first ? (o + nv) : (sumv[idx] + nv);
            }
        }
    }
}

// ---------------- standalone SPMM (2 CSR problems via blockIdx.y) ----------------
__global__ __launch_bounds__(256) void spmm2_kernel(
    const int* __restrict__ ptrA, const int* __restrict__ colsA, const float* __restrict__ valsA,
    const float4* __restrict__ XA, float4* __restrict__ OA,
    const int* __restrict__ ptrB, const int* __restrict__ colsB, const float* __restrict__ valsB,
    const float4* __restrict__ XB, float4* __restrict__ OB)
{
    int w = blockIdx.x * 8 + (threadIdx.x >> 5);
    int lane = threadIdx.x & 31;
    if (blockIdx.y == 0) spmm_row(ptrA, colsA, valsA, XA, OA, w, lane);
    else                 spmm_row(ptrB, colsB, valsB, XB, OB, w, lane);
}

// ---------------- heterogeneous combo: SPMM (mem-bound) + GEMM (fma-bound) ----------------
__global__ __launch_bounds__(256, 2) void combo_kernel(
    const int* __restrict__ ptrA, const int* __restrict__ colsA, const float* __restrict__ valsA,
    const float4* __restrict__ XA, float4* __restrict__ OA,
    const int* __restrict__ ptrB, const int* __restrict__ colsB, const float* __restrict__ valsB,
    const float4* __restrict__ XB, float4* __restrict__ OB,
    const float* __restrict__ A0, const float* __restrict__ W0,
    const float* __restrict__ old0, float* __restrict__ out0, float* __restrict__ sum0,
    const float* __restrict__ A1, const float* __restrict__ W1,
    const float* __restrict__ old1, float* __restrict__ out1, float* __restrict__ sum1,
    int first)
{
    __shared__ float As[2][16][128];
    __shared__ float Bs[2][16][128];
    int gid = blockIdx.x;
    int gb = (gid * NGEMM) / NTOT;          // gemm blocks before gid (Bresenham stripe)
    int ga = ((gid + 1) * NGEMM) / NTOT;
    if (ga > gb) {
        // GEMM block
        int prob = gb / 782;                 // 782 = 391 rowtiles * 2 coltiles
        int r = gb % 782;
        int colTile = (r & 1) * 128;
        int rowTile = (r >> 1) * 128;
        if (prob == 0) gemm_tile(A0, W0, old0, out0, sum0, NJc, first, rowTile, colTile, As, Bs);
        else           gemm_tile(A1, W1, old1, out1, sum1, NSc, first, rowTile, colTile, As, Bs);
    } else {
        // SPMM block
        int sIdx = gid - gb;
        int side = sIdx / 6250;
        int w = (sIdx % 6250) * 8 + (threadIdx.x >> 5);   // 6250*8 == 50000 exactly
        int lane = threadIdx.x & 31;
        if (side == 0) spmm_row(ptrA, colsA, valsA, XA, OA, w, lane);
        else           spmm_row(ptrB, colsB, valsB, XB, OB, w, lane);
    }
}

// ---------------- standalone GEMM pair (2 problems via blockIdx.z) ----------------
__global__ __launch_bounds__(256, 2) void gemm2_kernel(
    const float* __restrict__ A0, const float* __restrict__ W0,
    const float* __restrict__ old0, float* __restrict__ out0, float* __restrict__ sum0,
    const float* __restrict__ A1, const float* __restrict__ W1,
    const float* __restrict__ old1, float* __restrict__ out1, float* __restrict__ sum1,
    int first)
{
    __shared__ float As[2][16][128];
    __shared__ float Bs[2][16][128];
    int colTile = blockIdx.x * 128;
    int rowTile = blockIdx.y * 128;
    if (blockIdx.z == 0) gemm_tile(A0, W0, old0, out0, sum0, NJc, first, rowTile, colTile, As, Bs);
    else                 gemm_tile(A1, W1, old1, out1, sum1, NSc, first, rowTile, colTile, As, Bs);
}

// ---------------- double-buffered GEMM + exp + per-(row,group) sum (R3 version) ----------
__global__ __launch_bounds__(256, 2) void expsum_kernel(
    const float* __restrict__ A, const float* __restrict__ Bm,
    float* __restrict__ sumexp, int ngroups)
{
    __shared__ float As[2][16][128];
    __shared__ float Bs[2][16][128];
    __shared__ float red[128];
    int tid = threadIdx.x;
    int tx = tid & 15, ty = tid >> 4;
    int rowTile = blockIdx.y * 128;
    int colTile = blockIdx.x * 128;
    float acc[8][8];
    #pragma unroll
    for (int i = 0; i < 8; i++)
        #pragma unroll
        for (int j = 0; j < 8; j++) acc[i][j] = 0.f;

    int lrow = tid & 127;
    int khalf = (tid >> 7) * 8;
    const float* Ag = A + (size_t)(rowTile + lrow) * DIMc + khalf;
    const float* Bg = Bm + (size_t)(colTile + lrow) * DIMc + khalf;

    float4 ra0 = *(const float4*)(Ag + 0);
    float4 ra1 = *(const float4*)(Ag + 4);
    float4 rb0 = *(const float4*)(Bg + 0);
    float4 rb1 = *(const float4*)(Bg + 4);
    As[0][khalf+0][lrow] = ra0.x; As[0][khalf+1][lrow] = ra0.y;
    As[0][khalf+2][lrow] = ra0.z; As[0][khalf+3][lrow] = ra0.w;
    As[0][khalf+4][lrow] = ra1.x; As[0][khalf+5][lrow] = ra1.y;
    As[0][khalf+6][lrow] = ra1.z; As[0][khalf+7][lrow] = ra1.w;
    Bs[0][khalf+0][lrow] = rb0.x; Bs[0][khalf+1][lrow] = rb0.y;
    Bs[0][khalf+2][lrow] = rb0.z; Bs[0][khalf+3][lrow] = rb0.w;
    Bs[0][khalf+4][lrow] = rb1.x; Bs[0][khalf+5][lrow] = rb1.y;
    Bs[0][khalf+6][lrow] = rb1.z; Bs[0][khalf+7][lrow] = rb1.w;
    __syncthreads();

    int buf = 0;
    for (int k0 = 16; k0 <= DIMc; k0 += 16) {
        bool more = k0 < DIMc;
        if (more) {
            ra0 = *(const float4*)(Ag + k0);
            ra1 = *(const float4*)(Ag + k0 + 4);
            rb0 = *(const float4*)(Bg + k0);
            rb1 = *(const float4*)(Bg + k0 + 4);
        }
        #pragma unroll
        for (int kk = 0; kk < 16; kk++) {
            float a[8], b[8];
            #pragma unroll
            for (int i = 0; i < 4; i++) {
                a[i]   = As[buf][kk][ty*4 + i];
                a[i+4] = As[buf][kk][ty*4 + i + 64];
                b[i]   = Bs[buf][kk][tx*4 + i];
                b[i+4] = Bs[buf][kk][tx*4 + i + 64];
            }
            #pragma unroll
            for (int i = 0; i < 8; i++)
                #pragma unroll
                for (int j = 0; j < 8; j++)
                    acc[i][j] = fmaf(a[i], b[j], acc[i][j]);
        }
        if (more) {
            int nb = buf ^ 1;
            As[nb][khalf+0][lrow] = ra0.x; As[nb][khalf+1][lrow] = ra0.y;
            As[nb][khalf+2][lrow] = ra0.z; As[nb][khalf+3][lrow] = ra0.w;
            As[nb][khalf+4][lrow] = ra1.x; As[nb][khalf+5][lrow] = ra1.y;
            As[nb][khalf+6][lrow] = ra1.z; As[nb][khalf+7][lrow] = ra1.w;
            Bs[nb][khalf+0][lrow] = rb0.x; Bs[nb][khalf+1][lrow] = rb0.y;
            Bs[nb][khalf+2][lrow] = rb0.z; Bs[nb][khalf+3][lrow] = rb0.w;
            Bs[nb][khalf+4][lrow] = rb1.x; Bs[nb][khalf+5][lrow] = rb1.y;
            Bs[nb][khalf+6][lrow] = rb1.z; Bs[nb][khalf+7][lrow] = rb1.w;
            __syncthreads();
            buf = nb;
        }
    }
    // exp + per-row partial sums
    float rsum[8];
    #pragma unroll
    for (int i = 0; i < 8; i++) {
        rsum[i] = 0.f;
        #pragma unroll
        for (int j = 0; j < 8; j++) rsum[i] += expf(acc[i][j] * 5.0f);  // 1/TEMP = 5
    }
    if (tid < 128) red[tid] = 0.f;
    __syncthreads();
    #pragma unroll
    for (int i = 0; i < 8; i++) {
        int r = ty*4 + (i & 3) + ((i >> 2) * 64);
        atomicAdd(&red[r], rsum[i]);
    }
    __syncthreads();
    if (tid < 128) {
        int gr = rowTile + tid;
        int group = blockIdx.x >> 3;   // 128 cols/tile, 1024 cols/group
        atomicAdd(&sumexp[(size_t)gr * ngroups + group], red[tid]);
    }
}

// ---------------- gathers ----------------
__global__ void gather4_kernel(const int* __restrict__ j_ids, const int* __restrict__ s_ids) {
    float4* dst; const float4* src; const int* ids;
    switch (blockIdx.y) {
        case 0: dst = (float4*)g_gjsel; src = (const float4*)g_sGj; ids = j_ids; break;
        case 1: dst = (float4*)g_ejsel; src = (const float4*)g_sEj; ids = j_ids; break;
        case 2: dst = (float4*)g_gssel; src = (const float4*)g_sGs; ids = s_ids; break;
        default: dst = (float4*)g_essel; src = (const float4*)g_sEs; ids = s_ids; break;
    }
    int row = blockIdx.x;
    int id = ids[row];
    dst[(size_t)row * D4c + threadIdx.x] = src[(size_t)id * D4c + threadIdx.x];
}

__global__ void gather_kernel(float4* __restrict__ dst, const float4* __restrict__ src,
                              const int* __restrict__ ids) {
    int row = blockIdx.x;
    int id = ids[row];
    dst[(size_t)row * D4c + threadIdx.x] = src[(size_t)id * D4c + threadIdx.x];
}

// ---------------- pos score ----------------
__global__ void pos_kernel() {
    int w = (blockIdx.x * blockDim.x + threadIdx.x) >> 5;
    int lane = threadIdx.x & 31;
    if (w >= Bc) return;
    const float4* gj = (const float4*)g_gjsel + (size_t)w * D4c;
    const float4* ej = (const float4*)g_ejsel + (size_t)w * D4c;
    const float4* gs = (const float4*)g_gssel + (size_t)w * D4c;
    const float4* es = (const float4*)g_essel + (size_t)w * D4c;
    float4 a0 = gj[lane], a1 = gj[lane+32], b0 = ej[lane], b1 = ej[lane+32];
    float4 c0 = gs[lane], c1 = gs[lane+32], d0 = es[lane], d1 = es[lane+32];
    float s1 = a0.x*b0.x + a0.y*b0.y + a0.z*b0.z + a0.w*b0.w
             + a1.x*b1.x + a1.y*b1.y + a1.z*b1.z + a1.w*b1.w;
    float s2 = c0.x*d0.x + c0.y*d0.y + c0.z*d0.z + c0.w*d0.w
             + c1.x*d1.x + c1.y*d1.y + c1.z*d1.z + c1.w*d1.w;
    #pragma unroll
    for (int o = 16; o; o >>= 1) {
        s1 += __shfl_xor_sync(0xffffffffu, s1, o);
        s2 += __shfl_xor_sync(0xffffffffu, s2, o);
    }
    if (lane == 0) {
        float c1v = fminf(fmaxf(s1 * 5.0f, -1.f), 1.f);
        float c2v = fminf(fmaxf(s2 * 5.0f, -1.f), 1.f);
        atomicAdd(&g_scalars[0], c1v);
        atomicAdd(&g_scalars[1], c2v);
    }
}

// ---------------- weight L2 regularizer ----------------
__global__ void wsq_kernel(const float* __restrict__ a, const float* __restrict__ b,
                           const float* __restrict__ c, const float* __restrict__ d) {
    float s = 0.f;
    for (int i = blockIdx.x * blockDim.x + threadIdx.x; i < WSZc; i += gridDim.x * blockDim.x) {
        float x;
        x = a[i]; s += x * x;
        x = b[i]; s += x * x;
        x = c[i]; s += x * x;
        x = d[i]; s += x * x;
    }
    #pragma unroll
    for (int o = 16; o; o >>= 1) s += __shfl_xor_sync(0xffffffffu, s, o);
    __shared__ float sh[8];
    int lane = threadIdx.x & 31, wid = threadIdx.x >> 5;
    if (lane == 0) sh[wid] = s;
    __syncthreads();
    if (threadIdx.x == 0) {
        float t = 0.f;
        for (int i = 0; i < (int)(blockDim.x >> 5); i++) t += sh[i];
        atomicAdd(&g_scalars[2], t);
    }
}

// ---------------- finalize ----------------
__device__ double blk_reduce_1024(double v) {
    __shared__ double sh[32];
    __syncthreads();
    int lane = threadIdx.x & 31, wid = threadIdx.x >> 5;
    #pragma unroll
    for (int o = 16; o; o >>= 1) v += __shfl_down_sync(0xffffffffu, v, o);
    if (lane == 0) sh[wid] = v;
    __syncthreads();
    v = (threadIdx.x < 32) ? sh[threadIdx.x] : 0.0;
    if (wid == 0) {
        #pragma unroll
        for (int o = 16; o; o >>= 1) v += __shfl_down_sync(0xffffffffu, v, o);
    }
    return v;  // valid on thread 0
}

__global__ void finalize_kernel(float* __restrict__ out) {
    int tid = threadIdx.x;
    double a = (tid < Bc) ? log((double)g_sumexp_j[tid] + 1e-8) : 0.0;
    double negj = blk_reduce_1024(a);
    double b = 0.0;
    for (int i = tid; i < Bc * NNEGc; i += 1024)
        b += log((double)g_sumexp_s[i] + 1e-8);
    double negs = blk_reduce_1024(b);
    if (tid == 0) {
        double pos = (double)g_scalars[0] / Bc + (double)g_scalars[1] / Bc;
        double neg = negj / Bc + negs / (double)(Bc * NNEGc);
        double cl = (-pos + neg) * 0.2;
        double reg = 1e-4 * (double)g_scalars[2];
        out[0] = (float)(cl + reg);
        out[1] = (float)cl;
        out[2] = (float)reg;
    }
}

// ---------------- launch ----------------
#define SYM(p, s) do { void* _t = 0; cudaGetSymbolAddress(&_t, s); p = (decltype(p))_t; } while (0)

extern "C" void kernel_launch(void* const* d_in, const int* in_sizes, int n_in,
                              void* d_out, int out_size) {
    (void)in_sizes; (void)n_in; (void)out_size;
    const float* e_j_f   = (const float*)d_in[0];
    const float* e_s_f   = (const float*)d_in[1];
    const float* aug_e_j = (const float*)d_in[2];
    const float* aug_e_s = (const float*)d_in[3];
    const float* val_j   = (const float*)d_in[4];
    const float* val_s   = (const float*)d_in[5];
    const float* W_j     = (const float*)d_in[6];
    const float* W_s     = (const float*)d_in[7];
    const float* W_j_aug = (const float*)d_in[8];
    const float* W_s_aug = (const float*)d_in[9];
    const int* row_j = (const int*)d_in[10];
    const int* col_j = (const int*)d_in[11];
    const int* row_s = (const int*)d_in[12];
    const int* col_s = (const int*)d_in[13];
    const int* j_ids = (const int*)d_in[14];
    const int* s_ids = (const int*)d_in[15];
    const int* negs  = (const int*)d_in[16];
    float* out = (float*)d_out;

    float *Ej, *Es, *Gj, *Gs, *sEj, *sEs, *sGj, *sGs;
    float *Tje, *Tjg, *Tse, *Tsg;
    int *ptr_j, *ptr_s, *ccol_j, *ccol_s;
    float *cval_j, *cval_s;
    float *gjsel, *ejsel, *gssel, *essel, *negemb, *sumexp_j, *sumexp_s;
    SYM(Ej, g_Ej); SYM(Es, g_Es); SYM(Gj, g_Gj); SYM(Gs, g_Gs);
    SYM(sEj, g_sEj); SYM(sEs, g_sEs); SYM(sGj, g_sGj); SYM(sGs, g_sGs);
    SYM(Tje, g_Tje); SYM(Tjg, g_Tjg); SYM(Tse, g_Tse); SYM(Tsg, g_Tsg);
    SYM(ptr_j, g_ptr_j); SYM(ptr_s, g_ptr_s);
    SYM(ccol_j, g_ccol_j); SYM(ccol_s, g_ccol_s);
    SYM(cval_j, g_cval_j); SYM(cval_s, g_cval_s);
    SYM(gjsel, g_gjsel); SYM(ejsel, g_ejsel); SYM(gssel, g_gssel); SYM(essel, g_essel);
    SYM(negemb, g_negemb); SYM(sumexp_j, g_sumexp_j); SYM(sumexp_s, g_sumexp_s);

    const int EB = (Ec + 255) / 256;         // 6250
    const int RB = (NJc * 32 + 255) / 256;   // 6250

    zero_kernel<<<256, 256>>>();
    count_kernel<<<EB, 256>>>(row_j, col_s);
    scan2_kernel<<<2, 1024>>>();
    scatter_kernel<<<EB, 256>>>(row_j, col_j, val_j, row_s, col_s, val_s);

    {   // initial l2norm of aug embeddings -> Gj, Gs
        dim3 g(RB, 2);
        l2norm4_kernel<<<g, 256>>>((const float4*)aug_e_j, (float4*)Gj,
                                   (const float4*)aug_e_s, (float4*)Gs,
                                   (const float4*)aug_e_j, (float4*)Gj,
                                   (const float4*)aug_e_s, (float4*)Gs, NJc);
    }

    // ---- pipelined layers: spmmE(0); [spmmG(0)|gemmE(0)]; [spmmE(1)|gemmG(0)];
    //                        [spmmG(1)|gemmE(1)]; gemmG(1) ----
    {
        dim3 sg(6250, 2);
        spmm2_kernel<<<sg, 256>>>(ptr_j, ccol_j, cval_j, (const float4*)e_s_f, (float4*)Tje,
                                  ptr_s, ccol_s, cval_s, (const float4*)e_j_f, (float4*)Tse);

        combo_kernel<<<NTOT, 256>>>(                  // spmmG(0) || gemmE(0)
            ptr_j, ccol_j, cval_j, (const float4*)Gs, (float4*)Tjg,
            ptr_s, ccol_s, cval_s, (const float4*)Gj, (float4*)Tsg,
            Tje, W_j,             e_j_f, Ej, sEj,
            Tse, W_s,             e_s_f, Es, sEs, 1);

        combo_kernel<<<NTOT, 256>>>(                  // spmmE(1) || gemmG(0)
            ptr_j, ccol_j, cval_j, (const float4*)Es, (float4*)Tje,
            ptr_s, ccol_s, cval_s, (const float4*)Ej, (float4*)Tse,
            Tjg, W_j_aug,         Gj, Gj, sGj,
            Tsg, W_s_aug,         Gs, Gs, sGs, 1);

        combo_kernel<<<NTOT, 256>>>(                  // spmmG(1) || gemmE(1)
            ptr_j, ccol_j, cval_j, (const float4*)Gs, (float4*)Tjg,
            ptr_s, ccol_s, cval_s, (const float4*)Gj, (float4*)Tsg,
            Tje, W_j + DIMc*DIMc, Ej, Ej, sEj,
            Tse, W_s + DIMc*DIMc, Es, Es, sEs, 0);

        dim3 gg(2, 391, 2);
        gemm2_kernel<<<gg, 256>>>(                    // gemmG(1)
            Tjg, W_j_aug + DIMc*DIMc, Gj, Gj, sGj,
            Tsg, W_s_aug + DIMc*DIMc, Gs, Gs, sGs, 0);
    }

    {   // final normalize (scale 1/(L+1) cancels in l2norm) — in place, 4 arrays
        dim3 g(RB, 4);
        l2norm4_kernel<<<g, 256>>>((const float4*)sEj, (float4*)sEj,
                                   (const float4*)sEs, (float4*)sEs,
                                   (const float4*)sGj, (float4*)sGj,
                                   (const float4*)sGs, (float4*)sGs, NJc);
    }

    {
        dim3 g(Bc, 4);
        gather4_kernel<<<g, 64>>>(j_ids, s_ids);
    }
    gather_kernel<<<NEGRc, 64>>>((float4*)negemb, (const float4*)sEs, negs);

    dim3 lg(Bc / 128, Bc / 128);             // 8 x 8
    expsum_kernel<<<lg, 256>>>(gjsel, ejsel, sumexp_j, 1);
    dim3 ng(NEGRc / 128, Bc / 128);          // 256 x 8
    expsum_kernel<<<ng, 256>>>(gssel, negemb, sumexp_s, NNEGc);

    pos_kernel<<<Bc / 8, 256>>>();
    wsq_kernel<<<256, 256>>>(W_j, W_s, W_j_aug, W_s_aug);
    finalize_kernel<<<1, 1024>>>(out);
}

// round 8
// speedup vs baseline: 1.4686x; 1.3468x over previous
#include <cuda_runtime.h>
#include <math.h>

#define NJc 50000
#define NSc 50000
#define Ec  1600000
#define DIMc 256
#define D4c  64
#define Lc   2
#define Bc   1024
#define NNEGc 32
#define NEGRc (NNEGc*Bc)
#define WSZc (Lc*DIMc*DIMc)

// ---------------- scratch (device globals; no allocation allowed) ----------------
__device__ float g_Ej[NJc*DIMc];
__device__ float g_Es[NSc*DIMc];
__device__ float g_Gj[NJc*DIMc];
__device__ float g_Gs[NSc*DIMc];
__device__ float g_sEj[NJc*DIMc];
__device__ float g_sEs[NSc*DIMc];
__device__ float g_sGj[NJc*DIMc];
__device__ float g_sGs[NSc*DIMc];
__device__ float g_Tje[NJc*DIMc];
__device__ float g_Tjg[NJc*DIMc];
__device__ float g_Tse[NSc*DIMc];
__device__ float g_Tsg[NSc*DIMc];
__device__ float g_Tjec[Bc*DIMc];
__device__ float g_Tjgc[Bc*DIMc];
__device__ float g_Tsgc[Bc*DIMc];
__device__ int   g_cnt_j[NJc];
__device__ int   g_cnt_s[NSc];
__device__ int   g_ptr_j[NJc+1];
__device__ int   g_ptr_s[NSc+1];
__device__ int   g_cur_j[NJc];
__device__ int   g_cur_s[NSc];
__device__ int   g_ccol_j[Ec];
__device__ float g_cval_j[Ec];
__device__ int   g_ccol_s[Ec];
__device__ float g_cval_s[Ec];
__device__ float g_gjsel[Bc*DIMc];
__device__ float g_ejsel[Bc*DIMc];
__device__ float g_gssel[Bc*DIMc];
__device__ float g_essel[Bc*DIMc];
__device__ float g_negemb[NEGRc*DIMc];
__device__ float g_sumexp_j[Bc];
__device__ float g_sumexp_s[Bc*NNEGc];
__device__ float g_scalars[8];   // [0]=pos_j sum, [1]=pos_s sum, [2]=wsq

// ---------------- small utility kernels ----------------
__global__ void zero_kernel() {
    int i = blockIdx.x * blockDim.x + threadIdx.x;
    int st = gridDim.x * blockDim.x;
    for (int k = i; k < NJc; k += st) g_cnt_j[k] = 0;
    for (int k = i; k < NSc; k += st) g_cnt_s[k] = 0;
    for (int k = i; k < Bc; k += st) g_sumexp_j[k] = 0.f;
    for (int k = i; k < Bc*NNEGc; k += st) g_sumexp_s[k] = 0.f;
    if (i < 8) g_scalars[i] = 0.f;
}

__global__ void count_kernel(const int* __restrict__ row_j, const int* __restrict__ col_s) {
    int i = blockIdx.x * blockDim.x + threadIdx.x;
    if (i < Ec) {
        atomicAdd(&g_cnt_j[row_j[i]], 1);
        atomicAdd(&g_cnt_s[col_s[i]], 1);
    }
}

// dual single-block exclusive scan: blockIdx.x = 0 -> j arrays, 1 -> s arrays
__global__ void scan2_kernel() {
    const int* cnt = blockIdx.x ? g_cnt_s : g_cnt_j;
    int* ptr = blockIdx.x ? g_ptr_s : g_ptr_j;
    int* cur = blockIdx.x ? g_cur_s : g_cur_j;
    int n = blockIdx.x ? NSc : NJc;
    __shared__ int warp_sums[32];
    __shared__ int s_carry;
    int tid = threadIdx.x;
    if (tid == 0) { s_carry = 0; ptr[0] = 0; }
    __syncthreads();
    for (int base = 0; base < n; base += 1024) {
        int i = base + tid;
        int v = (i < n) ? cnt[i] : 0;
        int inc = v;
        #pragma unroll
        for (int off = 1; off < 32; off <<= 1) {
            int t = __shfl_up_sync(0xffffffffu, inc, off);
            if ((tid & 31) >= off) inc += t;
        }
        if ((tid & 31) == 31) warp_sums[tid >> 5] = inc;
        __syncthreads();
        if (tid < 32) {
            int ws = warp_sums[tid];
            int wi = ws;
            #pragma unroll
            for (int off = 1; off < 32; off <<= 1) {
                int t = __shfl_up_sync(0xffffffffu, wi, off);
                if (tid >= off) wi += t;
            }
            warp_sums[tid] = wi - ws;   // exclusive warp offset
        }
        __syncthreads();
        int excl = inc - v + warp_sums[tid >> 5];
        int carry = s_carry;
        if (i < n) {
            int start = carry + excl;
            cur[i] = start;
            ptr[i + 1] = start + v;
        }
        __syncthreads();
        if (tid == 1023) s_carry = carry + excl + v;
        __syncthreads();
    }
}

__global__ void scatter_kernel(const int* __restrict__ row_j, const int* __restrict__ col_j,
                               const float* __restrict__ val_j,
                               const int* __restrict__ row_s, const int* __restrict__ col_s,
                               const float* __restrict__ val_s) {
    int i = blockIdx.x * blockDim.x + threadIdx.x;
    if (i >= Ec) return;
    int p = atomicAdd(&g_cur_j[row_j[i]], 1);
    g_ccol_j[p] = col_j[i]; g_cval_j[p] = val_j[i];
    int q = atomicAdd(&g_cur_s[col_s[i]], 1);
    g_ccol_s[q] = row_s[i]; g_cval_s[q] = val_s[i];
}

// ---------------- fused row l2 normalize over up to 4 arrays ----------------
__global__ void l2norm4_kernel(const float4* s0, float4* d0, const float4* s1, float4* d1,
                               const float4* s2, float4* d2, const float4* s3, float4* d3,
                               int n) {
    const float4* src; float4* dst;
    switch (blockIdx.y) {
        case 0: src = s0; dst = d0; break;
        case 1: src = s1; dst = d1; break;
        case 2: src = s2; dst = d2; break;
        default: src = s3; dst = d3; break;
    }
    int w = (blockIdx.x * blockDim.x + threadIdx.x) >> 5;
    int lane = threadIdx.x & 31;
    if (w >= n) return;
    const float4* s = src + (size_t)w * D4c;
    float4 u0 = s[lane], u1 = s[lane + 32];
    float ss = u0.x*u0.x + u0.y*u0.y + u0.z*u0.z + u0.w*u0.w
             + u1.x*u1.x + u1.y*u1.y + u1.z*u1.z + u1.w*u1.w;
    #pragma unroll
    for (int o = 16; o; o >>= 1) ss += __shfl_xor_sync(0xffffffffu, ss, o);
    float inv = 1.f / fmaxf(sqrtf(ss), 1e-12f);
    float4* d = dst + (size_t)w * D4c;
    d[lane]      = make_float4(u0.x*inv, u0.y*inv, u0.z*inv, u0.w*inv);
    d[lane + 32] = make_float4(u1.x*inv, u1.y*inv, u1.z*inv, u1.w*inv);
}

// ---------------- SPMM row bodies ----------------
__device__ __forceinline__ void fma4(float4& acc, float v, const float4& u) {
    acc.x = fmaf(v, u.x, acc.x);
    acc.y = fmaf(v, u.y, acc.y);
    acc.z = fmaf(v, u.z, acc.z);
    acc.w = fmaf(v, u.w, acc.w);
}

// dual: O1[dst] = A[src] @ X1, O2[dst] = A[src] @ X2
__device__ __forceinline__ void spmm_row2(
    const int* __restrict__ ptr, const int* __restrict__ cols, const float* __restrict__ vals,
    const float4* __restrict__ X1, const float4* __restrict__ X2,
    float4* __restrict__ O1, float4* __restrict__ O2, int src, int dst, int lane)
{
    int s = ptr[src], e = ptr[src + 1];
    float4 z = make_float4(0.f, 0.f, 0.f, 0.f);
    float4 a0 = z, a1 = z, b0 = z, b1 = z;
    int p = s;
    for (; p + 2 <= e; p += 2) {
        int c0 = cols[p], c1 = cols[p + 1];
        float v0 = vals[p], v1 = vals[p + 1];
        const float4* x10 = X1 + (size_t)c0 * D4c;
        const float4* x20 = X2 + (size_t)c0 * D4c;
        const float4* x11 = X1 + (size_t)c1 * D4c;
        const float4* x21 = X2 + (size_t)c1 * D4c;
        float4 p0 = x10[lane], p1 = x10[lane + 32];
        float4 q0 = x20[lane], q1 = x20[lane + 32];
        float4 r0 = x11[lane], r1 = x11[lane + 32];
        float4 t0 = x21[lane], t1 = x21[lane + 32];
        fma4(a0, v0, p0); fma4(a1, v0, p1); fma4(b0, v0, q0); fma4(b1, v0, q1);
        fma4(a0, v1, r0); fma4(a1, v1, r1); fma4(b0, v1, t0); fma4(b1, v1, t1);
    }
    if (p < e) {
        int c0 = cols[p]; float v0 = vals[p];
        const float4* x10 = X1 + (size_t)c0 * D4c;
        const float4* x20 = X2 + (size_t)c0 * D4c;
        float4 p0 = x10[lane], p1 = x10[lane + 32];
        float4 q0 = x20[lane], q1 = x20[lane + 32];
        fma4(a0, v0, p0); fma4(a1, v0, p1); fma4(b0, v0, q0); fma4(b1, v0, q1);
    }
    O1[(size_t)dst * D4c + lane] = a0; O1[(size_t)dst * D4c + 32 + lane] = a1;
    O2[(size_t)dst * D4c + lane] = b0; O2[(size_t)dst * D4c + 32 + lane] = b1;
}

// single: O[dst] = A[src] @ X
__device__ __forceinline__ void spmm_row1(
    const int* __restrict__ ptr, const int* __restrict__ cols, const float* __restrict__ vals,
    const float4* __restrict__ X, float4* __restrict__ O, int src, int dst, int lane)
{
    int s = ptr[src], e = ptr[src + 1];
    float4 z = make_float4(0.f, 0.f, 0.f, 0.f);
    float4 a0 = z, a1 = z;
    int p = s;
    for (; p + 4 <= e; p += 4) {
        int c0 = cols[p], c1 = cols[p+1], c2 = cols[p+2], c3 = cols[p+3];
        float v0 = vals[p], v1 = vals[p+1], v2 = vals[p+2], v3 = vals[p+3];
        const float4* x0 = X + (size_t)c0 * D4c;
        const float4* x1 = X + (size_t)c1 * D4c;
        const float4* x2 = X + (size_t)c2 * D4c;
        const float4* x3 = X + (size_t)c3 * D4c;
        float4 p00 = x0[lane], p01 = x0[lane + 32];
        float4 p10 = x1[lane], p11 = x1[lane + 32];
        float4 p20 = x2[lane], p21 = x2[lane + 32];
        float4 p30 = x3[lane], p31 = x3[lane + 32];
        fma4(a0, v0, p00); fma4(a1, v0, p01);
        fma4(a0, v1, p10); fma4(a1, v1, p11);
        fma4(a0, v2, p20); fma4(a1, v2, p21);
        fma4(a0, v3, p30); fma4(a1, v3, p31);
    }
    for (; p < e; p++) {
        int c0 = cols[p]; float v0 = vals[p];
        const float4* x0 = X + (size_t)c0 * D4c;
        float4 p00 = x0[lane], p01 = x0[lane + 32];
        fma4(a0, v0, p00); fma4(a1, v0, p01);
    }
    O[(size_t)dst * D4c + lane] = a0;
    O[(size_t)dst * D4c + 32 + lane] = a1;
}

// ---------------- L1 SPMM: dual x 2 CSR problems via blockIdx.y ----------------
__global__ __launch_bounds__(256) void spmm_dual2_kernel(
    const int* __restrict__ ptrA, const int* __restrict__ colsA, const float* __restrict__ valsA,
    const float4* __restrict__ XA1, const float4* __restrict__ XA2,
    float4* __restrict__ OA1, float4* __restrict__ OA2,
    const int* __restrict__ ptrB, const int* __restrict__ colsB, const float* __restrict__ valsB,
    const float4* __restrict__ XB1, const float4* __restrict__ XB2,
    float4* __restrict__ OB1, float4* __restrict__ OB2)
{
    int w = blockIdx.x * 8 + (threadIdx.x >> 5);
    int lane = threadIdx.x & 31;
    if (w >= NJc) return;
    if (blockIdx.y == 0) spmm_row2(ptrA, colsA, valsA, XA1, XA2, OA1, OA2, w, w, lane);
    else                 spmm_row2(ptrB, colsB, valsB, XB1, XB2, OB1, OB2, w, w, lane);
}

// ---------------- L2 SPMM: full Tse + selected compact rows, one launch ----------------
__global__ __launch_bounds__(256) void spmmL2_kernel(
    const float4* __restrict__ Ej, const float4* __restrict__ Gj,
    const float4* __restrict__ Es, const float4* __restrict__ Gs,
    float4* __restrict__ Tse, float4* __restrict__ Tjec, float4* __restrict__ Tjgc,
    float4* __restrict__ Tsgc,
    const int* __restrict__ j_ids, const int* __restrict__ s_ids)
{
    int gid = blockIdx.x;
    int warp = threadIdx.x >> 5;
    int lane = threadIdx.x & 31;
    if (gid < 6250) {
        int w = gid * 8 + warp;            // 50000 rows exactly
        spmm_row1(g_ptr_s, g_ccol_s, g_cval_s, Ej, Tse, w, w, lane);
    } else if (gid < 6250 + 128) {
        int i = (gid - 6250) * 8 + warp;   // 0..1023
        int row = j_ids[i];
        spmm_row2(g_ptr_j, g_ccol_j, g_cval_j, Es, Gs, Tjec, Tjgc, row, i, lane);
    } else {
        int i = (gid - 6378) * 8 + warp;
        int row = s_ids[i];
        spmm_row1(g_ptr_s, g_ccol_s, g_cval_s, Gj, Tsgc, row, i, lane);
    }
}

// ---------------- double-buffered SGEMM 128x128x16 (NT) + fused update epilogue ----------
// out = old + relu(C); sum = first ? old + out : sum + out
__global__ __launch_bounds__(256, 2) void gemm_update_kernel(
    const float* __restrict__ A, const float* __restrict__ W,
    const float* __restrict__ oldv, float* __restrict__ outv, float* __restrict__ sumv,
    int M, int first)
{
    __shared__ float As[2][16][128];
    __shared__ float Bs[2][16][128];
    int tid = threadIdx.x;
    int tx = tid & 15, ty = tid >> 4;
    int rowTile = blockIdx.y * 128;
    int colTile = blockIdx.x * 128;
    float acc[8][8];
    #pragma unroll
    for (int i = 0; i < 8; i++)
        #pragma unroll
        for (int j = 0; j < 8; j++) acc[i][j] = 0.f;

    int lrow = tid & 127;
    int khalf = (tid >> 7) * 8;
    const float* Ag = A + (size_t)(rowTile + lrow) * DIMc + khalf;
    const float* Wg = W + (size_t)(colTile + lrow) * DIMc + khalf;
    bool arow_ok = (rowTile + lrow) < M;
    const float4 z4 = make_float4(0.f, 0.f, 0.f, 0.f);

    float4 ra0 = arow_ok ? *(const float4*)(Ag + 0) : z4;
    float4 ra1 = arow_ok ? *(const float4*)(Ag + 4) : z4;
    float4 rb0 = *(const float4*)(Wg + 0);
    float4 rb1 = *(const float4*)(Wg + 4);
    As[0][khalf+0][lrow] = ra0.x; As[0][khalf+1][lrow] = ra0.y;
    As[0][khalf+2][lrow] = ra0.z; As[0][khalf+3][lrow] = ra0.w;
    As[0][khalf+4][lrow] = ra1.x; As[0][khalf+5][lrow] = ra1.y;
    As[0][khalf+6][lrow] = ra1.z; As[0][khalf+7][lrow] = ra1.w;
    Bs[0][khalf+0][lrow] = rb0.x; Bs[0][khalf+1][lrow] = rb0.y;
    Bs[0][khalf+2][lrow] = rb0.z; Bs[0][khalf+3][lrow] = rb0.w;
    Bs[0][khalf+4][lrow] = rb1.x; Bs[0][khalf+5][lrow] = rb1.y;
    Bs[0][khalf+6][lrow] = rb1.z; Bs[0][khalf+7][lrow] = rb1.w;
    __syncthreads();

    int buf = 0;
    for (int k0 = 16; k0 <= DIMc; k0 += 16) {
        bool more = k0 < DIMc;
        if (more) {
            ra0 = arow_ok ? *(const float4*)(Ag + k0) : z4;
            ra1 = arow_ok ? *(const float4*)(Ag + k0 + 4) : z4;
            rb0 = *(const float4*)(Wg + k0);
            rb1 = *(const float4*)(Wg + k0 + 4);
        }
        #pragma unroll
        for (int kk = 0; kk < 16; kk++) {
            float a[8], b[8];
            #pragma unroll
            for (int i = 0; i < 4; i++) {
                a[i]   = As[buf][kk][ty*4 + i];
                a[i+4] = As[buf][kk][ty*4 + i + 64];
                b[i]   = Bs[buf][kk][tx*4 + i];
                b[i+4] = Bs[buf][kk][tx*4 + i + 64];
            }
            #pragma unroll
            for (int i = 0; i < 8; i++)
                #pragma unroll
                for (int j = 0; j < 8; j++)
                    acc[i][j] = fmaf(a[i], b[j], acc[i][j]);
        }
        if (more) {
            int nb = buf ^ 1;
            As[nb][khalf+0][lrow] = ra0.x; As[nb][khalf+1][lrow] = ra0.y;
            As[nb][khalf+2][lrow] = ra0.z; As[nb][khalf+3][lrow] = ra0.w;
            As[nb][khalf+4][lrow] = ra1.x; As[nb][khalf+5][lrow] = ra1.y;
            As[nb][khalf+6][lrow] = ra1.z; As[nb][khalf+7][lrow] = ra1.w;
            Bs[nb][khalf+0][lrow] = rb0.x; Bs[nb][khalf+1][lrow] = rb0.y;
            Bs[nb][khalf+2][lrow] = rb0.z; Bs[nb][khalf+3][lrow] = rb0.w;
            Bs[nb][khalf+4][lrow] = rb1.x; Bs[nb][khalf+5][lrow] = rb1.y;
            Bs[nb][khalf+6][lrow] = rb1.z; Bs[nb][khalf+7][lrow] = rb1.w;
            __syncthreads();
            buf = nb;
        }
    }
    #pragma unroll
    for (int i = 0; i < 8; i++) {
        int gr = rowTile + ty*4 + (i & 3) + ((i >> 2) * 64);
        if (gr < M) {
            #pragma unroll
            for (int j = 0; j < 8; j++) {
                int gc = colTile + tx*4 + (j & 3) + ((j >> 2) * 64);
                size_t idx = (size_t)gr * DIMc + gc;
                float v = fmaxf(acc[i][j], 0.f);
                float o = oldv[idx];
                float nv = o + v;
                outv[idx] = nv;
                sumv[idx] = first ? (o + nv) : (sumv[idx] + nv);
            }
        }
    }
}

// ---------------- compacted selected GEMM (3 problems via blockIdx.z) ----------------
// dst[i,:] = sumP[ids[i],:] + oldB[ids[i],:] + relu(Ac[i,:] @ W^T)   (i in 0..1023)
__global__ __launch_bounds__(256, 2) void gemm_sel_kernel(
    const float* __restrict__ Wj2, const float* __restrict__ Wja2, const float* __restrict__ Wsa2,
    const int* __restrict__ j_ids, const int* __restrict__ s_ids)
{
    __shared__ float As[2][16][128];
    __shared__ float Bs[2][16][128];
    const float* A; const float* W; const float* oldB; const float* sumP;
    float* dst; const int* ids;
    switch (blockIdx.z) {
        case 0: A = g_Tjec; W = Wj2;  oldB = g_Ej; sumP = g_sEj; dst = g_ejsel; ids = j_ids; break;
        case 1: A = g_Tjgc; W = Wja2; oldB = g_Gj; sumP = g_sGj; dst = g_gjsel; ids = j_ids; break;
        default: A = g_Tsgc; W = Wsa2; oldB = g_Gs; sumP = g_sGs; dst = g_gssel; ids = s_ids; break;
    }
    int tid = threadIdx.x;
    int tx = tid & 15, ty = tid >> 4;
    int rowTile = blockIdx.y * 128;
    int colTile = blockIdx.x * 128;
    float acc[8][8];
    #pragma unroll
    for (int i = 0; i < 8; i++)
        #pragma unroll
        for (int j = 0; j < 8; j++) acc[i][j] = 0.f;

    int lrow = tid & 127;
    int khalf = (tid >> 7) * 8;
    const float* Ag = A + (size_t)(rowTile + lrow) * DIMc + khalf;
    const float* Wg = W + (size_t)(colTile + lrow) * DIMc + khalf;

    float4 ra0 = *(const float4*)(Ag + 0);
    float4 ra1 = *(const float4*)(Ag + 4);
    float4 rb0 = *(const float4*)(Wg + 0);
    float4 rb1 = *(const float4*)(Wg + 4);
    As[0][khalf+0][lrow] = ra0.x; As[0][khalf+1][lrow] = ra0.y;
    As[0][khalf+2][lrow] = ra0.z; As[0][khalf+3][lrow] = ra0.w;
    As[0][khalf+4][lrow] = ra1.x; As[0][khalf+5][lrow] = ra1.y;
    As[0][khalf+6][lrow] = ra1.z; As[0][khalf+7][lrow] = ra1.w;
    Bs[0][khalf+0][lrow] = rb0.x; Bs[0][khalf+1][lrow] = rb0.y;
    Bs[0][khalf+2][lrow] = rb0.z; Bs[0][khalf+3][lrow] = rb0.w;
    Bs[0][khalf+4][lrow] = rb1.x; Bs[0][khalf+5][lrow] = rb1.y;
    Bs[0][khalf+6][lrow] = rb1.z; Bs[0][khalf+7][lrow] = rb1.w;
    __syncthreads();

    int buf = 0;
    for (int k0 = 16; k0 <= DIMc; k0 += 16) {
        bool more = k0 < DIMc;
        if (more) {
            ra0 = *(const float4*)(Ag + k0);
            ra1 = *(const float4*)(Ag + k0 + 4);
            rb0 = *(const float4*)(Wg + k0);
            rb1 = *(const float4*)(Wg + k0 + 4);
        }
        #pragma unroll
        for (int kk = 0; kk < 16; kk++) {
            float a[8], b[8];
            #pragma unroll
            for (int i = 0; i < 4; i++) {
                a[i]   = As[buf][kk][ty*4 + i];
                a[i+4] = As[buf][kk][ty*4 + i + 64];
                b[i]   = Bs[buf][kk][tx*4 + i];
                b[i+4] = Bs[buf][kk][tx*4 + i + 64];
            }
            #pragma unroll
            for (int i = 0; i < 8; i++)
                #pragma unroll
                for (int j = 0; j < 8; j++)
                    acc[i][j] = fmaf(a[i], b[j], acc[i][j]);
        }
        if (more) {
            int nb = buf ^ 1;
            As[nb][khalf+0][lrow] = ra0.x; As[nb][khalf+1][lrow] = ra0.y;
            As[nb][khalf+2][lrow] = ra0.z; As[nb][khalf+3][lrow] = ra0.w;
            As[nb][khalf+4][lrow] = ra1.x; As[nb][khalf+5][lrow] = ra1.y;
            As[nb][khalf+6][lrow] = ra1.z; As[nb][khalf+7][lrow] = ra1.w;
            Bs[nb][khalf+0][lrow] = rb0.x; Bs[nb][khalf+1][lrow] = rb0.y;
            Bs[nb][khalf+2][lrow] = rb0.z; Bs[nb][khalf+3][lrow] = rb0.w;
            Bs[nb][khalf+4][lrow] = rb1.x; Bs[nb][khalf+5][lrow] = rb1.y;
            Bs[nb][khalf+6][lrow] = rb1.z; Bs[nb][khalf+7][lrow] = rb1.w;
            __syncthreads();
            buf = nb;
        }
    }
    #pragma unroll
    for (int i = 0; i < 8; i++) {
        int gr = rowTile + ty*4 + (i & 3) + ((i >> 2) * 64);
        int id = ids[gr];
        #pragma unroll
        for (int j = 0; j < 8; j++) {
            int gc = colTile + tx*4 + (j & 3) + ((j >> 2) * 64);
            size_t src = (size_t)id * DIMc + gc;
            float v = fmaxf(acc[i][j], 0.f);
            dst[(size_t)gr * DIMc + gc] = sumP[src] + oldB[src] + v;
        }
    }
}

// ---------------- double-buffered GEMM + exp + per-(row,group) sum ----------------
__global__ __launch_bounds__(256, 2) void expsum_kernel(
    const float* __restrict__ A, const float* __restrict__ Bm,
    float* __restrict__ sumexp, int ngroups)
{
    __shared__ float As[2][16][128];
    __shared__ float Bs[2][16][128];
    __shared__ float red[128];
    int tid = threadIdx.x;
    int tx = tid & 15, ty = tid >> 4;
    int rowTile = blockIdx.y * 128;
    int colTile = blockIdx.x * 128;
    float acc[8][8];
    #pragma unroll
    for (int i = 0; i < 8; i++)
        #pragma unroll
        for (int j = 0; j < 8; j++) acc[i][j] = 0.f;

    int lrow = tid & 127;
    int khalf = (tid >> 7) * 8;
    const float* Ag = A + (size_t)(rowTile + lrow) * DIMc + khalf;
    const float* Bg = Bm + (size_t)(colTile + lrow) * DIMc + khalf;

    float4 ra0 = *(const float4*)(Ag + 0);
    float4 ra1 = *(const float4*)(Ag + 4);
    float4 rb0 = *(const float4*)(Bg + 0);
    float4 rb1 = *(const float4*)(Bg + 4);
    As[0][khalf+0][lrow] = ra0.x; As[0][khalf+1][lrow] = ra0.y;
    As[0][khalf+2][lrow] = ra0.z; As[0][khalf+3][lrow] = ra0.w;
    As[0][khalf+4][lrow] = ra1.x; As[0][khalf+5][lrow] = ra1.y;
    As[0][khalf+6][lrow] = ra1.z; As[0][khalf+7][lrow] = ra1.w;
    Bs[0][khalf+0][lrow] = rb0.x; Bs[0][khalf+1][lrow] = rb0.y;
    Bs[0][khalf+2][lrow] = rb0.z; Bs[0][khalf+3][lrow] = rb0.w;
    Bs[0][khalf+4][lrow] = rb1.x; Bs[0][khalf+5][lrow] = rb1.y;
    Bs[0][khalf+6][lrow] = rb1.z; Bs[0][khalf+7][lrow] = rb1.w;
    __syncthreads();

    int buf = 0;
    for (int k0 = 16; k0 <= DIMc; k0 += 16) {
        bool more = k0 < DIMc;
        if (more) {
            ra0 = *(const float4*)(Ag + k0);
            ra1 = *(const float4*)(Ag + k0 + 4);
            rb0 = *(const float4*)(Bg + k0);
            rb1 = *(const float4*)(Bg + k0 + 4);
        }
        #pragma unroll
        for (int kk = 0; kk < 16; kk++) {
            float a[8], b[8];
            #pragma unroll
            for (int i = 0; i < 4; i++) {
                a[i]   = As[buf][kk][ty*4 + i];
                a[i+4] = As[buf][kk][ty*4 + i + 64];
                b[i]   = Bs[buf][kk][tx*4 + i];
                b[i+4] = Bs[buf][kk][tx*4 + i + 64];
            }
            #pragma unroll
            for (int i = 0; i < 8; i++)
                #pragma unroll
                for (int j = 0; j < 8; j++)
                    acc[i][j] = fmaf(a[i], b[j], acc[i][j]);
        }
        if (more) {
            int nb = buf ^ 1;
            As[nb][khalf+0][lrow] = ra0.x; As[nb][khalf+1][lrow] = ra0.y;
            As[nb][khalf+2][lrow] = ra0.z; As[nb][khalf+3][lrow] = ra0.w;
            As[nb][khalf+4][lrow] = ra1.x; As[nb][khalf+5][lrow] = ra1.y;
            As[nb][khalf+6][lrow] = ra1.z; As[nb][khalf+7][lrow] = ra1.w;
            Bs[nb][khalf+0][lrow] = rb0.x; Bs[nb][khalf+1][lrow] = rb0.y;
            Bs[nb][khalf+2][lrow] = rb0.z; Bs[nb][khalf+3][lrow] = rb0.w;
            Bs[nb][khalf+4][lrow] = rb1.x; Bs[nb][khalf+5][lrow] = rb1.y;
            Bs[nb][khalf+6][lrow] = rb1.z; Bs[nb][khalf+7][lrow] = rb1.w;
            __syncthreads();
            buf = nb;
        }
    }
    // exp + per-row partial sums
    float rsum[8];
    #pragma unroll
    for (int i = 0; i < 8; i++) {
        rsum[i] = 0.f;
        #pragma unroll
        for (int j = 0; j < 8; j++) rsum[i] += expf(acc[i][j] * 5.0f);  // 1/TEMP = 5
    }
    if (tid < 128) red[tid] = 0.f;
    __syncthreads();
    #pragma unroll
    for (int i = 0; i < 8; i++) {
        int r = ty*4 + (i & 3) + ((i >> 2) * 64);
        atomicAdd(&red[r], rsum[i]);
    }
    __syncthreads();
    if (tid < 128) {
        int gr = rowTile + tid;
        int group = blockIdx.x >> 3;   // 128 cols/tile, 1024 cols/group
        atomicAdd(&sumexp[(size_t)gr * ngroups + group], red[tid]);
    }
}

// ---------------- gather ----------------
__global__ void gather_kernel(float4* __restrict__ dst, const float4* __restrict__ src,
                              const int* __restrict__ ids) {
    int row = blockIdx.x;
    int id = ids[row];
    dst[(size_t)row * D4c + threadIdx.x] = src[(size_t)id * D4c + threadIdx.x];
}

// ---------------- pos score ----------------
__global__ void pos_kernel() {
    int w = (blockIdx.x * blockDim.x + threadIdx.x) >> 5;
    int lane = threadIdx.x & 31;
    if (w >= Bc) return;
    const float4* gj = (const float4*)g_gjsel + (size_t)w * D4c;
    const float4* ej = (const float4*)g_ejsel + (size_t)w * D4c;
    const float4* gs = (const float4*)g_gssel + (size_t)w * D4c;
    const float4* es = (const float4*)g_essel + (size_t)w * D4c;
    float4 a0 = gj[lane], a1 = gj[lane+32], b0 = ej[lane], b1 = ej[lane+32];
    float4 c0 = gs[lane], c1 = gs[lane+32], d0 = es[lane], d1 = es[lane+32];
    float s1 = a0.x*b0.x + a0.y*b0.y + a0.z*b0.z + a0.w*b0.w
             + a1.x*b1.x + a1.y*b1.y + a1.z*b1.z + a1.w*b1.w;
    float s2 = c0.x*d0.x + c0.y*d0.y + c0.z*d0.z + c0.w*d0.w
             + c1.x*d1.x + c1.y*d1.y + c1.z*d1.z + c1.w*d1.w;
    #pragma unroll
    for (int o = 16; o; o >>= 1) {
        s1 += __shfl_xor_sync(0xffffffffu, s1, o);
        s2 += __shfl_xor_sync(0xffffffffu, s2, o);
    }
    if (lane == 0) {
        float c1v = fminf(fmaxf(s1 * 5.0f, -1.f), 1.f);
        float c2v = fminf(fmaxf(s2 * 5.0f, -1.f), 1.f);
        atomicAdd(&g_scalars[0], c1v);
        atomicAdd(&g_scalars[1], c2v);
    }
}

// ---------------- weight L2 regularizer ----------------
__global__ void wsq_kernel(const float* __restrict__ a, const float* __restrict__ b,
                           const float* __restrict__ c, const float* __restrict__ d) {
    float s = 0.f;
    for (int i = blockIdx.x * blockDim.x + threadIdx.x; i < WSZc; i += gridDim.x * blockDim.x) {
        float x;
        x = a[i]; s += x * x;
        x = b[i]; s += x * x;
        x = c[i]; s += x * x;
        x = d[i]; s += x * x;
    }
    #pragma unroll
    for (int o = 16; o; o >>= 1) s += __shfl_xor_sync(0xffffffffu, s, o);
    __shared__ float sh[8];
    int lane = threadIdx.x & 31, wid = threadIdx.x >> 5;
    if (lane == 0) sh[wid] = s;
    __syncthreads();
    if (threadIdx.x == 0) {
        float t = 0.f;
        for (int i = 0; i < (int)(blockDim.x >> 5); i++) t += sh[i];
        atomicAdd(&g_scalars[2], t);
    }
}

// ---------------- finalize ----------------
__device__ double blk_reduce_1024(double v) {
    __shared__ double sh[32];
    __syncthreads();
    int lane = threadIdx.x & 31, wid = threadIdx.x >> 5;
    #pragma unroll
    for (int o = 16; o; o >>= 1) v += __shfl_down_sync(0xffffffffu, v, o);
    if (lane == 0) sh[wid] = v;
    __syncthreads();
    v = (threadIdx.x < 32) ? sh[threadIdx.x] : 0.0;
    if (wid == 0) {
        #pragma unroll
        for (int o = 16; o; o >>= 1) v += __shfl_down_sync(0xffffffffu, v, o);
    }
    return v;  // valid on thread 0
}

__global__ void finalize_kernel(float* __restrict__ out) {
    int tid = threadIdx.x;
    double a = (tid < Bc) ? log((double)g_sumexp_j[tid] + 1e-8) : 0.0;
    double negj = blk_reduce_1024(a);
    double b = 0.0;
    for (int i = tid; i < Bc * NNEGc; i += 1024)
        b += log((double)g_sumexp_s[i] + 1e-8);
    double negs = blk_reduce_1024(b);
    if (tid == 0) {
        double pos = (double)g_scalars[0] / Bc + (double)g_scalars[1] / Bc;
        double neg = negj / Bc + negs / (double)(Bc * NNEGc);
        double cl = (-pos + neg) * 0.2;
        double reg = 1e-4 * (double)g_scalars[2];
        out[0] = (float)(cl + reg);
        out[1] = (float)cl;
        out[2] = (float)reg;
    }
}

// ---------------- launch ----------------
#define SYM(p, s) do { void* _t = 0; cudaGetSymbolAddress(&_t, s); p = (decltype(p))_t; } while (0)

extern "C" void kernel_launch(void* const* d_in, const int* in_sizes, int n_in,
                              void* d_out, int out_size) {
    (void)in_sizes; (void)n_in; (void)out_size;
    const float* e_j_f   = (const float*)d_in[0];
    const float* e_s_f   = (const float*)d_in[1];
    const float* aug_e_j = (const float*)d_in[2];
    const float* aug_e_s = (const float*)d_in[3];
    const float* val_j   = (const float*)d_in[4];
    const float* val_s   = (const float*)d_in[5];
    const float* W_j     = (const float*)d_in[6];
    const float* W_s     = (const float*)d_in[7];
    const float* W_j_aug = (const float*)d_in[8];
    const float* W_s_aug = (const float*)d_in[9];
    const int* row_j = (const int*)d_in[10];
    const int* col_j = (const int*)d_in[11];
    const int* row_s = (const int*)d_in[12];
    const int* col_s = (const int*)d_in[13];
    const int* j_ids = (const int*)d_in[14];
    const int* s_ids = (const int*)d_in[15];
    const int* negs  = (const int*)d_in[16];
    float* out = (float*)d_out;

    float *Ej, *Es, *Gj, *Gs, *sEj, *sEs, *sGj, *sGs;
    float *Tje, *Tjg, *Tse, *Tsg, *Tjec, *Tjgc, *Tsgc;
    int *ptr_j, *ptr_s, *ccol_j, *ccol_s;
    float *cval_j, *cval_s;
    float *gjsel, *ejsel, *gssel, *essel, *negemb, *sumexp_j, *sumexp_s;
    SYM(Ej, g_Ej); SYM(Es, g_Es); SYM(Gj, g_Gj); SYM(Gs, g_Gs);
    SYM(sEj, g_sEj); SYM(sEs, g_sEs); SYM(sGj, g_sGj); SYM(sGs, g_sGs);
    SYM(Tje, g_Tje); SYM(Tjg, g_Tjg); SYM(Tse, g_Tse); SYM(Tsg, g_Tsg);
    SYM(Tjec, g_Tjec); SYM(Tjgc, g_Tjgc); SYM(Tsgc, g_Tsgc);
    SYM(ptr_j, g_ptr_j); SYM(ptr_s, g_ptr_s);
    SYM(ccol_j, g_ccol_j); SYM(ccol_s, g_ccol_s);
    SYM(cval_j, g_cval_j); SYM(cval_s, g_cval_s);
    SYM(gjsel, g_gjsel); SYM(ejsel, g_ejsel); SYM(gssel, g_gssel); SYM(essel, g_essel);
    SYM(negemb, g_negemb); SYM(sumexp_j, g_sumexp_j); SYM(sumexp_s, g_sumexp_s);

    const int EB = (Ec + 255) / 256;         // 6250
    const int RB = (NJc * 32 + 255) / 256;   // 6250

    zero_kernel<<<256, 256>>>();
    count_kernel<<<EB, 256>>>(row_j, col_s);
    scan2_kernel<<<2, 1024>>>();
    scatter_kernel<<<EB, 256>>>(row_j, col_j, val_j, row_s, col_s, val_s);

    {   // initial l2norm of aug embeddings -> Gj, Gs
        dim3 g(RB, 2);
        l2norm4_kernel<<<g, 256>>>((const float4*)aug_e_j, (float4*)Gj,
                                   (const float4*)aug_e_s, (float4*)Gs,
                                   (const float4*)aug_e_j, (float4*)Gj,
                                   (const float4*)aug_e_s, (float4*)Gs, NJc);
    }

    // ---- layer 1 (full) ----
    dim3 spmm_grid(6250, 2);
    dim3 gemm_grid(2, 391);
    spmm_dual2_kernel<<<spmm_grid, 256>>>(
        ptr_j, ccol_j, cval_j, (const float4*)e_s_f, (const float4*)Gs, (float4*)Tje, (float4*)Tjg,
        ptr_s, ccol_s, cval_s, (const float4*)e_j_f, (const float4*)Gj, (float4*)Tse, (float4*)Tsg);
    gemm_update_kernel<<<gemm_grid, 256>>>(Tje, W_j,     e_j_f, Ej, sEj, NJc, 1);
    gemm_update_kernel<<<gemm_grid, 256>>>(Tse, W_s,     e_s_f, Es, sEs, NSc, 1);
    gemm_update_kernel<<<gemm_grid, 256>>>(Tjg, W_j_aug, Gj,    Gj, sGj, NJc, 1);
    gemm_update_kernel<<<gemm_grid, 256>>>(Tsg, W_s_aug, Gs,    Gs, sGs, NSc, 1);

    // ---- layer 2 (full Es path + compacted selected rows) ----
    spmmL2_kernel<<<6250 + 128 + 128, 256>>>(
        (const float4*)Ej, (const float4*)Gj, (const float4*)Es, (const float4*)Gs,
        (float4*)Tse, (float4*)Tjec, (float4*)Tjgc, (float4*)Tsgc, j_ids, s_ids);
    gemm_update_kernel<<<gemm_grid, 256>>>(Tse, W_s + DIMc*DIMc, Es, Es, sEs, NSc, 0);
    {
        dim3 sg(2, 8, 3);
        gemm_sel_kernel<<<sg, 256>>>(W_j + DIMc*DIMc, W_j_aug + DIMc*DIMc,
                                     W_s_aug + DIMc*DIMc, j_ids, s_ids);
    }

    // ---- final normalize: full sEs + 3 compacted 1024-row arrays ----
    l2norm4_kernel<<<dim3(RB, 1), 256>>>((const float4*)sEs, (float4*)sEs,
                                         (const float4*)sEs, (float4*)sEs,
                                         (const float4*)sEs, (float4*)sEs,
                                         (const float4*)sEs, (float4*)sEs, NSc);
    l2norm4_kernel<<<dim3(128, 3), 256>>>((const float4*)ejsel, (float4*)ejsel,
                                          (const float4*)gjsel, (float4*)gjsel,
                                          (const float4*)gssel, (float4*)gssel,
                                          (const float4*)gssel, (float4*)gssel, Bc);

    gather_kernel<<<Bc, 64>>>((float4*)essel, (const float4*)sEs, s_ids);
    gather_kernel<<<NEGRc, 64>>>((float4*)negemb, (const float4*)sEs, negs);

    dim3 lg(Bc / 128, Bc / 128);             // 8 x 8
    expsum_kernel<<<lg, 256>>>(gjsel, ejsel, sumexp_j, 1);
    dim3 ng(NEGRc / 128, Bc / 128);          // 256 x 8
    expsum_kernel<<<ng, 256>>>(gssel, negemb, sumexp_s, NNEGc);

    pos_kernel<<<Bc / 8, 256>>>();
    wsq_kernel<<<256, 256>>>(W_j, W_s, W_j_aug, W_s_aug);
    finalize_kernel<<<1, 1024>>>(out);
}

// round 9
// speedup vs baseline: 1.5422x; 1.0501x over previous
#include <cuda_runtime.h>
#include <math.h>

#define NJc 50000
#define NSc 50000
#define Ec  1600000
#define DIMc 256
#define D4c  64
#define Lc   2
#define Bc   1024
#define NNEGc 32
#define NEGRc (NNEGc*Bc)
#define WSZc (Lc*DIMc*DIMc)

// ---------------- scratch (device globals; no allocation allowed) ----------------
__device__ float g_Ej[NJc*DIMc];
__device__ float g_Es[NSc*DIMc];
__device__ float g_Gj[NJc*DIMc];      // layer-0 G_j (preserved)
__device__ float g_Gs[NSc*DIMc];      // layer-0 G_s (preserved)
__device__ float g_Gj1[NJc*DIMc];     // layer-1 G_j
__device__ float g_Gs1[NSc*DIMc];     // layer-1 G_s
__device__ float g_sEs[NSc*DIMc];
__device__ float g_Tje[NJc*DIMc];
__device__ float g_Tjg[NJc*DIMc];
__device__ float g_Tse[NSc*DIMc];
__device__ float g_Tsg[NSc*DIMc];
__device__ float g_Tjec[Bc*DIMc];
__device__ float g_Tjgc[Bc*DIMc];
__device__ float g_Tsgc[Bc*DIMc];
__device__ int   g_cnt_j[NJc];
__device__ int   g_cnt_s[NSc];
__device__ int   g_ptr_j[NJc+1];
__device__ int   g_ptr_s[NSc+1];
__device__ int   g_cur_j[NJc];
__device__ int   g_cur_s[NSc];
__device__ int   g_ccol_j[Ec];
__device__ float g_cval_j[Ec];
__device__ int   g_ccol_s[Ec];
__device__ float g_cval_s[Ec];
__device__ float g_gjsel[Bc*DIMc];
__device__ float g_ejsel[Bc*DIMc];
__device__ float g_gssel[Bc*DIMc];
__device__ float g_essel[Bc*DIMc];
__device__ float g_negemb[NEGRc*DIMc];
__device__ float g_sumexp_j[Bc];
__device__ float g_sumexp_s[Bc*NNEGc];
__device__ float g_scalars[8];   // [0]=pos_j sum, [1]=pos_s sum, [2]=wsq

// ---------------- small utility kernels ----------------
__global__ void zero_kernel() {
    int i = blockIdx.x * blockDim.x + threadIdx.x;
    int st = gridDim.x * blockDim.x;
    for (int k = i; k < NJc; k += st) g_cnt_j[k] = 0;
    for (int k = i; k < NSc; k += st) g_cnt_s[k] = 0;
    for (int k = i; k < Bc; k += st) g_sumexp_j[k] = 0.f;
    for (int k = i; k < Bc*NNEGc; k += st) g_sumexp_s[k] = 0.f;
    if (i < 8) g_scalars[i] = 0.f;
}

__global__ void count_kernel(const int* __restrict__ row_j, const int* __restrict__ col_s) {
    int i = blockIdx.x * blockDim.x + threadIdx.x;
    if (i < Ec) {
        atomicAdd(&g_cnt_j[row_j[i]], 1);
        atomicAdd(&g_cnt_s[col_s[i]], 1);
    }
}

__global__ void scan2_kernel() {
    const int* cnt = blockIdx.x ? g_cnt_s : g_cnt_j;
    int* ptr = blockIdx.x ? g_ptr_s : g_ptr_j;
    int* cur = blockIdx.x ? g_cur_s : g_cur_j;
    int n = blockIdx.x ? NSc : NJc;
    __shared__ int warp_sums[32];
    __shared__ int s_carry;
    int tid = threadIdx.x;
    if (tid == 0) { s_carry = 0; ptr[0] = 0; }
    __syncthreads();
    for (int base = 0; base < n; base += 1024) {
        int i = base + tid;
        int v = (i < n) ? cnt[i] : 0;
        int inc = v;
        #pragma unroll
        for (int off = 1; off < 32; off <<= 1) {
            int t = __shfl_up_sync(0xffffffffu, inc, off);
            if ((tid & 31) >= off) inc += t;
        }
        if ((tid & 31) == 31) warp_sums[tid >> 5] = inc;
        __syncthreads();
        if (tid < 32) {
            int ws = warp_sums[tid];
            int wi = ws;
            #pragma unroll
            for (int off = 1; off < 32; off <<= 1) {
                int t = __shfl_up_sync(0xffffffffu, wi, off);
                if (tid >= off) wi += t;
            }
            warp_sums[tid] = wi - ws;
        }
        __syncthreads();
        int excl = inc - v + warp_sums[tid >> 5];
        int carry = s_carry;
        if (i < n) {
            int start = carry + excl;
            cur[i] = start;
            ptr[i + 1] = start + v;
        }
        __syncthreads();
        if (tid == 1023) s_carry = carry + excl + v;
        __syncthreads();
    }
}

__global__ void scatter_kernel(const int* __restrict__ row_j, const int* __restrict__ col_j,
                               const float* __restrict__ val_j,
                               const int* __restrict__ row_s, const int* __restrict__ col_s,
                               const float* __restrict__ val_s) {
    int i = blockIdx.x * blockDim.x + threadIdx.x;
    if (i >= Ec) return;
    int p = atomicAdd(&g_cur_j[row_j[i]], 1);
    g_ccol_j[p] = col_j[i]; g_cval_j[p] = val_j[i];
    int q = atomicAdd(&g_cur_s[col_s[i]], 1);
    g_ccol_s[q] = row_s[i]; g_cval_s[q] = val_s[i];
}

// ---------------- fused row l2 normalize over up to 4 arrays ----------------
__global__ void l2norm4_kernel(const float4* s0, float4* d0, const float4* s1, float4* d1,
                               const float4* s2, float4* d2, const float4* s3, float4* d3,
                               int n) {
    const float4* src; float4* dst;
    switch (blockIdx.y) {
        case 0: src = s0; dst = d0; break;
        case 1: src = s1; dst = d1; break;
        case 2: src = s2; dst = d2; break;
        default: src = s3; dst = d3; break;
    }
    int w = (blockIdx.x * blockDim.x + threadIdx.x) >> 5;
    int lane = threadIdx.x & 31;
    if (w >= n) return;
    const float4* s = src + (size_t)w * D4c;
    float4 u0 = s[lane], u1 = s[lane + 32];
    float ss = u0.x*u0.x + u0.y*u0.y + u0.z*u0.z + u0.w*u0.w
             + u1.x*u1.x + u1.y*u1.y + u1.z*u1.z + u1.w*u1.w;
    #pragma unroll
    for (int o = 16; o; o >>= 1) ss += __shfl_xor_sync(0xffffffffu, ss, o);
    float inv = 1.f / fmaxf(sqrtf(ss), 1e-12f);
    float4* d = dst + (size_t)w * D4c;
    d[lane]      = make_float4(u0.x*inv, u0.y*inv, u0.z*inv, u0.w*inv);
    d[lane + 32] = make_float4(u1.x*inv, u1.y*inv, u1.z*inv, u1.w*inv);
}

// ---------------- SPMM row bodies ----------------
__device__ __forceinline__ void fma4(float4& acc, float v, const float4& u) {
    acc.x = fmaf(v, u.x, acc.x);
    acc.y = fmaf(v, u.y, acc.y);
    acc.z = fmaf(v, u.z, acc.z);
    acc.w = fmaf(v, u.w, acc.w);
}

__device__ __forceinline__ void spmm_row2(
    const int* __restrict__ ptr, const int* __restrict__ cols, const float* __restrict__ vals,
    const float4* __restrict__ X1, const float4* __restrict__ X2,
    float4* __restrict__ O1, float4* __restrict__ O2, int src, int dst, int lane)
{
    int s = ptr[src], e = ptr[src + 1];
    float4 z = make_float4(0.f, 0.f, 0.f, 0.f);
    float4 a0 = z, a1 = z, b0 = z, b1 = z;
    int p = s;
    for (; p + 2 <= e; p += 2) {
        int c0 = cols[p], c1 = cols[p + 1];
        float v0 = vals[p], v1 = vals[p + 1];
        const float4* x10 = X1 + (size_t)c0 * D4c;
        const float4* x20 = X2 + (size_t)c0 * D4c;
        const float4* x11 = X1 + (size_t)c1 * D4c;
        const float4* x21 = X2 + (size_t)c1 * D4c;
        float4 p0 = x10[lane], p1 = x10[lane + 32];
        float4 q0 = x20[lane], q1 = x20[lane + 32];
        float4 r0 = x11[lane], r1 = x11[lane + 32];
        float4 t0 = x21[lane], t1 = x21[lane + 32];
        fma4(a0, v0, p0); fma4(a1, v0, p1); fma4(b0, v0, q0); fma4(b1, v0, q1);
        fma4(a0, v1, r0); fma4(a1, v1, r1); fma4(b0, v1, t0); fma4(b1, v1, t1);
    }
    if (p < e) {
        int c0 = cols[p]; float v0 = vals[p];
        const float4* x10 = X1 + (size_t)c0 * D4c;
        const float4* x20 = X2 + (size_t)c0 * D4c;
        float4 p0 = x10[lane], p1 = x10[lane + 32];
        float4 q0 = x20[lane], q1 = x20[lane + 32];
        fma4(a0, v0, p0); fma4(a1, v0, p1); fma4(b0, v0, q0); fma4(b1, v0, q1);
    }
    O1[(size_t)dst * D4c + lane] = a0; O1[(size_t)dst * D4c + 32 + lane] = a1;
    O2[(size_t)dst * D4c + lane] = b0; O2[(size_t)dst * D4c + 32 + lane] = b1;
}

__device__ __forceinline__ void spmm_row1(
    const int* __restrict__ ptr, const int* __restrict__ cols, const float* __restrict__ vals,
    const float4* __restrict__ X, float4* __restrict__ O, int src, int dst, int lane)
{
    int s = ptr[src], e = ptr[src + 1];
    float4 z = make_float4(0.f, 0.f, 0.f, 0.f);
    float4 a0 = z, a1 = z;
    int p = s;
    for (; p + 4 <= e; p += 4) {
        int c0 = cols[p], c1 = cols[p+1], c2 = cols[p+2], c3 = cols[p+3];
        float v0 = vals[p], v1 = vals[p+1], v2 = vals[p+2], v3 = vals[p+3];
        const float4* x0 = X + (size_t)c0 * D4c;
        const float4* x1 = X + (size_t)c1 * D4c;
        const float4* x2 = X + (size_t)c2 * D4c;
        const float4* x3 = X + (size_t)c3 * D4c;
        float4 p00 = x0[lane], p01 = x0[lane + 32];
        float4 p10 = x1[lane], p11 = x1[lane + 32];
        float4 p20 = x2[lane], p21 = x2[lane + 32];
        float4 p30 = x3[lane], p31 = x3[lane + 32];
        fma4(a0, v0, p00); fma4(a1, v0, p01);
        fma4(a0, v1, p10); fma4(a1, v1, p11);
        fma4(a0, v2, p20); fma4(a1, v2, p21);
        fma4(a0, v3, p30); fma4(a1, v3, p31);
    }
    for (; p < e; p++) {
        int c0 = cols[p]; float v0 = vals[p];
        const float4* x0 = X + (size_t)c0 * D4c;
        float4 p00 = x0[lane], p01 = x0[lane + 32];
        fma4(a0, v0, p00); fma4(a1, v0, p01);
    }
    O[(size_t)dst * D4c + lane] = a0;
    O[(size_t)dst * D4c + 32 + lane] = a1;
}

// ---------------- L1 SPMM: dual x 2 CSR problems via blockIdx.y ----------------
__global__ __launch_bounds__(256) void spmm_dual2_kernel(
    const int* __restrict__ ptrA, const int* __restrict__ colsA, const float* __restrict__ valsA,
    const float4* __restrict__ XA1, const float4* __restrict__ XA2,
    float4* __restrict__ OA1, float4* __restrict__ OA2,
    const int* __restrict__ ptrB, const int* __restrict__ colsB, const float* __restrict__ valsB,
    const float4* __restrict__ XB1, const float4* __restrict__ XB2,
    float4* __restrict__ OB1, float4* __restrict__ OB2)
{
    int w = blockIdx.x * 8 + (threadIdx.x >> 5);
    int lane = threadIdx.x & 31;
    if (w >= NJc) return;
    if (blockIdx.y == 0) spmm_row2(ptrA, colsA, valsA, XA1, XA2, OA1, OA2, w, w, lane);
    else                 spmm_row2(ptrB, colsB, valsB, XB1, XB2, OB1, OB2, w, w, lane);
}

// ---------------- L2 SPMM part 1: full Tse2 = A_s^T @ Ej1 -> g_Tje buffer ----------------
__global__ __launch_bounds__(256) void spmmL2_tse_kernel(
    const float4* __restrict__ Ej, float4* __restrict__ Odst)
{
    int w = blockIdx.x * 8 + (threadIdx.x >> 5);
    int lane = threadIdx.x & 31;
    if (w >= NSc) return;
    spmm_row1(g_ptr_s, g_ccol_s, g_cval_s, Ej, Odst, w, w, lane);
}

// ---------------- L2 SPMM part 2: compacted selected rows ----------------
__global__ __launch_bounds__(256) void spmmL2_sel_kernel(
    const float4* __restrict__ Es, const float4* __restrict__ Gs1, const float4* __restrict__ Gj1,
    const int* __restrict__ j_ids, const int* __restrict__ s_ids)
{
    int gid = blockIdx.x;
    int warp = threadIdx.x >> 5;
    int lane = threadIdx.x & 31;
    if (gid < 128) {
        int i = gid * 8 + warp;
        int row = j_ids[i];
        spmm_row2(g_ptr_j, g_ccol_j, g_cval_j, Es, Gs1,
                  (float4*)g_Tjec, (float4*)g_Tjgc, row, i, lane);
    } else {
        int i = (gid - 128) * 8 + warp;
        int row = s_ids[i];
        spmm_row1(g_ptr_s, g_ccol_s, g_cval_s, Gj1, (float4*)g_Tsgc, row, i, lane);
    }
}

// ---------------- double-buffered SGEMM 128x128x16 (NT) + flexible epilogue ----------
// nv = old + relu(C); wout: write outv; smode: 0 none, 1 sum=old+nv, 2 sum+=nv
__global__ __launch_bounds__(256, 2) void gemm_update_kernel(
    const float* __restrict__ A, const float* __restrict__ W,
    const float* __restrict__ oldv, float* __restrict__ outv, float* __restrict__ sumv,
    int M, int wout, int smode)
{
    __shared__ float As[2][16][128];
    __shared__ float Bs[2][16][128];
    int tid = threadIdx.x;
    int tx = tid & 15, ty = tid >> 4;
    int rowTile = blockIdx.y * 128;
    int colTile = blockIdx.x * 128;
    float acc[8][8];
    #pragma unroll
    for (int i = 0; i < 8; i++)
        #pragma unroll
        for (int j = 0; j < 8; j++) acc[i][j] = 0.f;

    int lrow = tid & 127;
    int khalf = (tid >> 7) * 8;
    const float* Ag = A + (size_t)(rowTile + lrow) * DIMc + khalf;
    const float* Wg = W + (size_t)(colTile + lrow) * DIMc + khalf;
    bool arow_ok = (rowTile + lrow) < M;
    const float4 z4 = make_float4(0.f, 0.f, 0.f, 0.f);

    float4 ra0 = arow_ok ? *(const float4*)(Ag + 0) : z4;
    float4 ra1 = arow_ok ? *(const float4*)(Ag + 4) : z4;
    float4 rb0 = *(const float4*)(Wg + 0);
    float4 rb1 = *(const float4*)(Wg + 4);
    As[0][khalf+0][lrow] = ra0.x; As[0][khalf+1][lrow] = ra0.y;
    As[0][khalf+2][lrow] = ra0.z; As[0][khalf+3][lrow] = ra0.w;
    As[0][khalf+4][lrow] = ra1.x; As[0][khalf+5][lrow] = ra1.y;
    As[0][khalf+6][lrow] = ra1.z; As[0][khalf+7][lrow] = ra1.w;
    Bs[0][khalf+0][lrow] = rb0.x; Bs[0][khalf+1][lrow] = rb0.y;
    Bs[0][khalf+2][lrow] = rb0.z; Bs[0][khalf+3][lrow] = rb0.w;
    Bs[0][khalf+4][lrow] = rb1.x; Bs[0][khalf+5][lrow] = rb1.y;
    Bs[0][khalf+6][lrow] = rb1.z; Bs[0][khalf+7][lrow] = rb1.w;
    __syncthreads();

    int buf = 0;
    for (int k0 = 16; k0 <= DIMc; k0 += 16) {
        bool more = k0 < DIMc;
        if (more) {
            ra0 = arow_ok ? *(const float4*)(Ag + k0) : z4;
            ra1 = arow_ok ? *(const float4*)(Ag + k0 + 4) : z4;
            rb0 = *(const float4*)(Wg + k0);
            rb1 = *(const float4*)(Wg + k0 + 4);
        }
        #pragma unroll
        for (int kk = 0; kk < 16; kk++) {
            float a[8], b[8];
            #pragma unroll
            for (int i = 0; i < 4; i++) {
                a[i]   = As[buf][kk][ty*4 + i];
                a[i+4] = As[buf][kk][ty*4 + i + 64];
                b[i]   = Bs[buf][kk][tx*4 + i];
                b[i+4] = Bs[buf][kk][tx*4 + i + 64];
            }
            #pragma unroll
            for (int i = 0; i < 8; i++)
                #pragma unroll
                for (int j = 0; j < 8; j++)
                    acc[i][j] = fmaf(a[i], b[j], acc[i][j]);
        }
        if (more) {
            int nb = buf ^ 1;
            As[nb][khalf+0][lrow] = ra0.x; As[nb][khalf+1][lrow] = ra0.y;
            As[nb][khalf+2][lrow] = ra0.z; As[nb][khalf+3][lrow] = ra0.w;
            As[nb][khalf+4][lrow] = ra1.x; As[nb][khalf+5][lrow] = ra1.y;
            As[nb][khalf+6][lrow] = ra1.z; As[nb][khalf+7][lrow] = ra1.w;
            Bs[nb][khalf+0][lrow] = rb0.x; Bs[nb][khalf+1][lrow] = rb0.y;
            Bs[nb][khalf+2][lrow] = rb0.z; Bs[nb][khalf+3][lrow] = rb0.w;
            Bs[nb][khalf+4][lrow] = rb1.x; Bs[nb][khalf+5][lrow] = rb1.y;
            Bs[nb][khalf+6][lrow] = rb1.z; Bs[nb][khalf+7][lrow] = rb1.w;
            __syncthreads();
            buf = nb;
        }
    }
    #pragma unroll
    for (int i = 0; i < 8; i++) {
        int gr = rowTile + ty*4 + (i & 3) + ((i >> 2) * 64);
        if (gr < M) {
            #pragma unroll
            for (int j = 0; j < 8; j++) {
                int gc = colTile + tx*4 + (j & 3) + ((j >> 2) * 64);
                size_t idx = (size_t)gr * DIMc + gc;
                float v = fmaxf(acc[i][j], 0.f);
                float o = oldv[idx];
                float nv = o + v;
                if (wout) outv[idx] = nv;
                if (smode == 1) sumv[idx] = o + nv;
                else if (smode == 2) sumv[idx] = sumv[idx] + nv;
            }
        }
    }
}

// ---------------- compacted selected GEMM (3 problems via blockIdx.z) ----------------
// dst[i,:] = base0[ids[i],:] + 2*base1[ids[i],:] + relu(Ac[i,:] @ W^T)
__global__ __launch_bounds__(256, 2) void gemm_sel_kernel(
    const float* __restrict__ e_j_f,
    const float* __restrict__ Wj2, const float* __restrict__ Wja2, const float* __restrict__ Wsa2,
    const int* __restrict__ j_ids, const int* __restrict__ s_ids)
{
    __shared__ float As[2][16][128];
    __shared__ float Bs[2][16][128];
    const float* A; const float* W; const float* base0; const float* base1;
    float* dst; const int* ids;
    switch (blockIdx.z) {
        case 0: A = g_Tjec; W = Wj2;  base0 = e_j_f; base1 = g_Ej;  dst = g_ejsel; ids = j_ids; break;
        case 1: A = g_Tjgc; W = Wja2; base0 = g_Gj;  base1 = g_Gj1; dst = g_gjsel; ids = j_ids; break;
        default: A = g_Tsgc; W = Wsa2; base0 = g_Gs; base1 = g_Gs1; dst = g_gssel; ids = s_ids; break;
    }
    int tid = threadIdx.x;
    int tx = tid & 15, ty = tid >> 4;
    int rowTile = blockIdx.y * 128;
    int colTile = blockIdx.x * 128;
    float acc[8][8];
    #pragma unroll
    for (int i = 0; i < 8; i++)
        #pragma unroll
        for (int j = 0; j < 8; j++) acc[i][j] = 0.f;

    int lrow = tid & 127;
    int khalf = (tid >> 7) * 8;
    const float* Ag = A + (size_t)(rowTile + lrow) * DIMc + khalf;
    const float* Wg = W + (size_t)(colTile + lrow) * DIMc + khalf;

    float4 ra0 = *(const float4*)(Ag + 0);
    float4 ra1 = *(const float4*)(Ag + 4);
    float4 rb0 = *(const float4*)(Wg + 0);
    float4 rb1 = *(const float4*)(Wg + 4);
    As[0][khalf+0][lrow] = ra0.x; As[0][khalf+1][lrow] = ra0.y;
    As[0][khalf+2][lrow] = ra0.z; As[0][khalf+3][lrow] = ra0.w;
    As[0][khalf+4][lrow] = ra1.x; As[0][khalf+5][lrow] = ra1.y;
    As[0][khalf+6][lrow] = ra1.z; As[0][khalf+7][lrow] = ra1.w;
    Bs[0][khalf+0][lrow] = rb0.x; Bs[0][khalf+1][lrow] = rb0.y;
    Bs[0][khalf+2][lrow] = rb0.z; Bs[0][khalf+3][lrow] = rb0.w;
    Bs[0][khalf+4][lrow] = rb1.x; Bs[0][khalf+5][lrow] = rb1.y;
    Bs[0][khalf+6][lrow] = rb1.z; Bs[0][khalf+7][lrow] = rb1.w;
    __syncthreads();

    int buf = 0;
    for (int k0 = 16; k0 <= DIMc; k0 += 16) {
        bool more = k0 < DIMc;
        if (more) {
            ra0 = *(const float4*)(Ag + k0);
            ra1 = *(const float4*)(Ag + k0 + 4);
            rb0 = *(const float4*)(Wg + k0);
            rb1 = *(const float4*)(Wg + k0 + 4);
        }
        #pragma unroll
        for (int kk = 0; kk < 16; kk++) {
            float a[8], b[8];
            #pragma unroll
            for (int i = 0; i < 4; i++) {
                a[i]   = As[buf][kk][ty*4 + i];
                a[i+4] = As[buf][kk][ty*4 + i + 64];
                b[i]   = Bs[buf][kk][tx*4 + i];
                b[i+4] = Bs[buf][kk][tx*4 + i + 64];
            }
            #pragma unroll
            for (int i = 0; i < 8; i++)
                #pragma unroll
                for (int j = 0; j < 8; j++)
                    acc[i][j] = fmaf(a[i], b[j], acc[i][j]);
        }
        if (more) {
            int nb = buf ^ 1;
            As[nb][khalf+0][lrow] = ra0.x; As[nb][khalf+1][lrow] = ra0.y;
            As[nb][khalf+2][lrow] = ra0.z; As[nb][khalf+3][lrow] = ra0.w;
            As[nb][khalf+4][lrow] = ra1.x; As[nb][khalf+5][lrow] = ra1.y;
            As[nb][khalf+6][lrow] = ra1.z; As[nb][khalf+7][lrow] = ra1.w;
            Bs[nb][khalf+0][lrow] = rb0.x; Bs[nb][khalf+1][lrow] = rb0.y;
            Bs[nb][khalf+2][lrow] = rb0.z; Bs[nb][khalf+3][lrow] = rb0.w;
            Bs[nb][khalf+4][lrow] = rb1.x; Bs[nb][khalf+5][lrow] = rb1.y;
            Bs[nb][khalf+6][lrow] = rb1.z; Bs[nb][khalf+7][lrow] = rb1.w;
            __syncthreads();
            buf = nb;
        }
    }
    #pragma unroll
    for (int i = 0; i < 8; i++) {
        int gr = rowTile + ty*4 + (i & 3) + ((i >> 2) * 64);
        int id = ids[gr];
        #pragma unroll
        for (int j = 0; j < 8; j++) {
            int gc = colTile + tx*4 + (j & 3) + ((j >> 2) * 64);
            size_t src = (size_t)id * DIMc + gc;
            float v = fmaxf(acc[i][j], 0.f);
            dst[(size_t)gr * DIMc + gc] = base0[src] + 2.f * base1[src] + v;
        }
    }
}

// ---------------- double-buffered GEMM + exp + per-(row,group) sum ----------------
__global__ __launch_bounds__(256, 2) void expsum_kernel(
    const float* __restrict__ A, const float* __restrict__ Bm,
    float* __restrict__ sumexp, int ngroups)
{
    __shared__ float As[2][16][128];
    __shared__ float Bs[2][16][128];
    __shared__ float red[128];
    int tid = threadIdx.x;
    int tx = tid & 15, ty = tid >> 4;
    int rowTile = blockIdx.y * 128;
    int colTile = blockIdx.x * 128;
    float acc[8][8];
    #pragma unroll
    for (int i = 0; i < 8; i++)
        #pragma unroll
        for (int j = 0; j < 8; j++) acc[i][j] = 0.f;

    int lrow = tid & 127;
    int khalf = (tid >> 7) * 8;
    const float* Ag = A + (size_t)(rowTile + lrow) * DIMc + khalf;
    const float* Bg = Bm + (size_t)(colTile + lrow) * DIMc + khalf;

    float4 ra0 = *(const float4*)(Ag + 0);
    float4 ra1 = *(const float4*)(Ag + 4);
    float4 rb0 = *(const float4*)(Bg + 0);
    float4 rb1 = *(const float4*)(Bg + 4);
    As[0][khalf+0][lrow] = ra0.x; As[0][khalf+1][lrow] = ra0.y;
    As[0][khalf+2][lrow] = ra0.z; As[0][khalf+3][lrow] = ra0.w;
    As[0][khalf+4][lrow] = ra1.x; As[0][khalf+5][lrow] = ra1.y;
    As[0][khalf+6][lrow] = ra1.z; As[0][khalf+7][lrow] = ra1.w;
    Bs[0][khalf+0][lrow] = rb0.x; Bs[0][khalf+1][lrow] = rb0.y;
    Bs[0][khalf+2][lrow] = rb0.z; Bs[0][khalf+3][lrow] = rb0.w;
    Bs[0][khalf+4][lrow] = rb1.x; Bs[0][khalf+5][lrow] = rb1.y;
    Bs[0][khalf+6][lrow] = rb1.z; Bs[0][khalf+7][lrow] = rb1.w;
    __syncthreads();

    int buf = 0;
    for (int k0 = 16; k0 <= DIMc; k0 += 16) {
        bool more = k0 < DIMc;
        if (more) {
            ra0 = *(const float4*)(Ag + k0);
            ra1 = *(const float4*)(Ag + k0 + 4);
            rb0 = *(const float4*)(Bg + k0);
            rb1 = *(const float4*)(Bg + k0 + 4);
        }
        #pragma unroll
        for (int kk = 0; kk < 16; kk++) {
            float a[8], b[8];
            #pragma unroll
            for (int i = 0; i < 4; i++) {
                a[i]   = As[buf][kk][ty*4 + i];
                a[i+4] = As[buf][kk][ty*4 + i + 64];
                b[i]   = Bs[buf][kk][tx*4 + i];
                b[i+4] = Bs[buf][kk][tx*4 + i + 64];
            }
            #pragma unroll
            for (int i = 0; i < 8; i++)
                #pragma unroll
                for (int j = 0; j < 8; j++)
                    acc[i][j] = fmaf(a[i], b[j], acc[i][j]);
        }
        if (more) {
            int nb = buf ^ 1;
            As[nb][khalf+0][lrow] = ra0.x; As[nb][khalf+1][lrow] = ra0.y;
            As[nb][khalf+2][lrow] = ra0.z; As[nb][khalf+3][lrow] = ra0.w;
            As[nb][khalf+4][lrow] = ra1.x; As[nb][khalf+5][lrow] = ra1.y;
            As[nb][khalf+6][lrow] = ra1.z; As[nb][khalf+7][lrow] = ra1.w;
            Bs[nb][khalf+0][lrow] = rb0.x; Bs[nb][khalf+1][lrow] = rb0.y;
            Bs[nb][khalf+2][lrow] = rb0.z; Bs[nb][khalf+3][lrow] = rb0.w;
            Bs[nb][khalf+4][lrow] = rb1.x; Bs[nb][khalf+5][lrow] = rb1.y;
            Bs[nb][khalf+6][lrow] = rb1.z; Bs[nb][khalf+7][lrow] = rb1.w;
            __syncthreads();
            buf = nb;
        }
    }
    float rsum[8];
    #pragma unroll
    for (int i = 0; i < 8; i++) {
        rsum[i] = 0.f;
        #pragma unroll
        for (int j = 0; j < 8; j++) rsum[i] += expf(acc[i][j] * 5.0f);  // 1/TEMP = 5
    }
    if (tid < 128) red[tid] = 0.f;
    __syncthreads();
    #pragma unroll
    for (int i = 0; i < 8; i++) {
        int r = ty*4 + (i & 3) + ((i >> 2) * 64);
        atomicAdd(&red[r], rsum[i]);
    }
    __syncthreads();
    if (tid < 128) {
        int gr = rowTile + tid;
        int group = blockIdx.x >> 3;
        atomicAdd(&sumexp[(size_t)gr * ngroups + group], red[tid]);
    }
}

// ---------------- combined gather: negemb (NEGR rows) + essel (B rows) ----------------
__global__ void gatherNE_kernel(const int* __restrict__ negs, const int* __restrict__ s_ids) {
    int row = blockIdx.x;
    const float4* src = (const float4*)g_sEs;
    if (row < NEGRc) {
        int id = negs[row];
        ((float4*)g_negemb)[(size_t)row * D4c + threadIdx.x] = src[(size_t)id * D4c + threadIdx.x];
    } else {
        int r = row - NEGRc;
        int id = s_ids[r];
        ((float4*)g_essel)[(size_t)r * D4c + threadIdx.x] = src[(size_t)id * D4c + threadIdx.x];
    }
}

// ---------------- pos score ----------------
__global__ void pos_kernel() {
    int w = (blockIdx.x * blockDim.x + threadIdx.x) >> 5;
    int lane = threadIdx.x & 31;
    if (w >= Bc) return;
    const float4* gj = (const float4*)g_gjsel + (size_t)w * D4c;
    const float4* ej = (const float4*)g_ejsel + (size_t)w * D4c;
    const float4* gs = (const float4*)g_gssel + (size_t)w * D4c;
    const float4* es = (const float4*)g_essel + (size_t)w * D4c;
    float4 a0 = gj[lane], a1 = gj[lane+32], b0 = ej[lane], b1 = ej[lane+32];
    float4 c0 = gs[lane], c1 = gs[lane+32], d0 = es[lane], d1 = es[lane+32];
    float s1 = a0.x*b0.x + a0.y*b0.y + a0.z*b0.z + a0.w*b0.w
             + a1.x*b1.x + a1.y*b1.y + a1.z*b1.z + a1.w*b1.w;
    float s2 = c0.x*d0.x + c0.y*d0.y + c0.z*d0.z + c0.w*d0.w
             + c1.x*d1.x + c1.y*d1.y + c1.z*d1.z + c1.w*d1.w;
    #pragma unroll
    for (int o = 16; o; o >>= 1) {
        s1 += __shfl_xor_sync(0xffffffffu, s1, o);
        s2 += __shfl_xor_sync(0xffffffffu, s2, o);
    }
    if (lane == 0) {
        float c1v = fminf(fmaxf(s1 * 5.0f, -1.f), 1.f);
        float c2v = fminf(fmaxf(s2 * 5.0f, -1.f), 1.f);
        atomicAdd(&g_scalars[0], c1v);
        atomicAdd(&g_scalars[1], c2v);
    }
}

// ---------------- weight L2 regularizer ----------------
__global__ void wsq_kernel(const float* __restrict__ a, const float* __restrict__ b,
                           const float* __restrict__ c, const float* __restrict__ d) {
    float s = 0.f;
    for (int i = blockIdx.x * blockDim.x + threadIdx.x; i < WSZc; i += gridDim.x * blockDim.x) {
        float x;
        x = a[i]; s += x * x;
        x = b[i]; s += x * x;
        x = c[i]; s += x * x;
        x = d[i]; s += x * x;
    }
    #pragma unroll
    for (int o = 16; o; o >>= 1) s += __shfl_xor_sync(0xffffffffu, s, o);
    __shared__ float sh[8];
    int lane = threadIdx.x & 31, wid = threadIdx.x >> 5;
    if (lane == 0) sh[wid] = s;
    __syncthreads();
    if (threadIdx.x == 0) {
        float t = 0.f;
        for (int i = 0; i < (int)(blockDim.x >> 5); i++) t += sh[i];
        atomicAdd(&g_scalars[2], t);
    }
}

// ---------------- finalize ----------------
__device__ double blk_reduce_1024(double v) {
    __shared__ double sh[32];
    __syncthreads();
    int lane = threadIdx.x & 31, wid = threadIdx.x >> 5;
    #pragma unroll
    for (int o = 16; o; o >>= 1) v += __shfl_down_sync(0xffffffffu, v, o);
    if (lane == 0) sh[wid] = v;
    __syncthreads();
    v = (threadIdx.x < 32) ? sh[threadIdx.x] : 0.0;
    if (wid == 0) {
        #pragma unroll
        for (int o = 16; o; o >>= 1) v += __shfl_down_sync(0xffffffffu, v, o);
    }
    return v;
}

__global__ void finalize_kernel(float* __restrict__ out) {
    int tid = threadIdx.x;
    double a = (tid < Bc) ? log((double)g_sumexp_j[tid] + 1e-8) : 0.0;
    double negj = blk_reduce_1024(a);
    double b = 0.0;
    for (int i = tid; i < Bc * NNEGc; i += 1024)
        b += log((double)g_sumexp_s[i] + 1e-8);
    double negs = blk_reduce_1024(b);
    if (tid == 0) {
        double pos = (double)g_scalars[0] / Bc + (double)g_scalars[1] / Bc;
        double neg = negj / Bc + negs / (double)(Bc * NNEGc);
        double cl = (-pos + neg) * 0.2;
        double reg = 1e-4 * (double)g_scalars[2];
        out[0] = (float)(cl + reg);
        out[1] = (float)cl;
        out[2] = (float)reg;
    }
}

// ---------------- launch ----------------
#define SYM(p, s) do { void* _t = 0; cudaGetSymbolAddress(&_t, s); p = (decltype(p))_t; } while (0)

extern "C" void kernel_launch(void* const* d_in, const int* in_sizes, int n_in,
                              void* d_out, int out_size) {
    (void)in_sizes; (void)n_in; (void)out_size;
    const float* e_j_f   = (const float*)d_in[0];
    const float* e_s_f   = (const float*)d_in[1];
    const float* aug_e_j = (const float*)d_in[2];
    const float* aug_e_s = (const float*)d_in[3];
    const float* val_j   = (const float*)d_in[4];
    const float* val_s   = (const float*)d_in[5];
    const float* W_j     = (const float*)d_in[6];
    const float* W_s     = (const float*)d_in[7];
    const float* W_j_aug = (const float*)d_in[8];
    const float* W_s_aug = (const float*)d_in[9];
    const int* row_j = (const int*)d_in[10];
    const int* col_j = (const int*)d_in[11];
    const int* row_s = (const int*)d_in[12];
    const int* col_s = (const int*)d_in[13];
    const int* j_ids = (const int*)d_in[14];
    const int* s_ids = (const int*)d_in[15];
    const int* negs  = (const int*)d_in[16];
    float* out = (float*)d_out;

    float *Ej, *Es, *Gj, *Gs, *Gj1, *Gs1, *sEs;
    float *Tje, *Tjg, *Tse, *Tsg;
    int *ptr_j, *ptr_s, *ccol_j, *ccol_s;
    float *cval_j, *cval_s;
    float *gjsel, *ejsel, *gssel, *negemb, *sumexp_j, *sumexp_s;
    SYM(Ej, g_Ej); SYM(Es, g_Es); SYM(Gj, g_Gj); SYM(Gs, g_Gs);
    SYM(Gj1, g_Gj1); SYM(Gs1, g_Gs1); SYM(sEs, g_sEs);
    SYM(Tje, g_Tje); SYM(Tjg, g_Tjg); SYM(Tse, g_Tse); SYM(Tsg, g_Tsg);
    SYM(ptr_j, g_ptr_j); SYM(ptr_s, g_ptr_s);
    SYM(ccol_j, g_ccol_j); SYM(ccol_s, g_ccol_s);
    SYM(cval_j, g_cval_j); SYM(cval_s, g_cval_s);
    SYM(gjsel, g_gjsel); SYM(ejsel, g_ejsel); SYM(gssel, g_gssel);
    SYM(negemb, g_negemb); SYM(sumexp_j, g_sumexp_j); SYM(sumexp_s, g_sumexp_s);

    static int inited = 0;
    static cudaStream_t s1;
    static cudaEvent_t evStart, evL2n, evEj, evTse, evG, evSel;
    if (!inited) {
        cudaStreamCreateWithFlags(&s1, cudaStreamNonBlocking);
        cudaEventCreateWithFlags(&evStart, cudaEventDisableTiming);
        cudaEventCreateWithFlags(&evL2n,   cudaEventDisableTiming);
        cudaEventCreateWithFlags(&evEj,    cudaEventDisableTiming);
        cudaEventCreateWithFlags(&evTse,   cudaEventDisableTiming);
        cudaEventCreateWithFlags(&evG,     cudaEventDisableTiming);
        cudaEventCreateWithFlags(&evSel,   cudaEventDisableTiming);
        inited = 1;
    }

    const int EB = (Ec + 255) / 256;         // 6250
    const int RB = 6250;                     // warp-per-row blocks

    zero_kernel<<<256, 256>>>();
    cudaEventRecord(evStart, 0);
    cudaStreamWaitEvent(s1, evStart, 0);

    // side stream: initial l2norm + wsq (independent of CSR build)
    {
        dim3 g(RB, 2);
        l2norm4_kernel<<<g, 256, 0, s1>>>((const float4*)aug_e_j, (float4*)Gj,
                                          (const float4*)aug_e_s, (float4*)Gs,
                                          (const float4*)aug_e_j, (float4*)Gj,
                                          (const float4*)aug_e_s, (float4*)Gs, NJc);
        wsq_kernel<<<256, 256, 0, s1>>>(W_j, W_s, W_j_aug, W_s_aug);
        cudaEventRecord(evL2n, s1);
    }
    // default stream: CSR build
    count_kernel<<<EB, 256>>>(row_j, col_s);
    scan2_kernel<<<2, 1024>>>();
    scatter_kernel<<<EB, 256>>>(row_j, col_j, val_j, row_s, col_s, val_s);
    cudaStreamWaitEvent(0, evL2n, 0);

    // ---- layer 1 ----
    dim3 spmm_grid(RB, 2);
    dim3 gemm_grid(2, 391);
    spmm_dual2_kernel<<<spmm_grid, 256>>>(
        ptr_j, ccol_j, cval_j, (const float4*)e_s_f, (const float4*)Gs, (float4*)Tje, (float4*)Tjg,
        ptr_s, ccol_s, cval_s, (const float4*)e_j_f, (const float4*)Gj, (float4*)Tse, (float4*)Tsg);

    gemm_update_kernel<<<gemm_grid, 256>>>(Tje, W_j, e_j_f, Ej, (float*)0, NJc, 1, 0);
    cudaEventRecord(evEj, 0);
    // side stream: full L2 SPMM Tse2 = A_s^T @ Ej -> g_Tje (Tje free after GEMM_Ej)
    cudaStreamWaitEvent(s1, evEj, 0);
    spmmL2_tse_kernel<<<RB, 256, 0, s1>>>((const float4*)Ej, (float4*)Tje);
    cudaEventRecord(evTse, s1);
    // default: remaining L1 GEMMs
    gemm_update_kernel<<<gemm_grid, 256>>>(Tse, W_s,     e_s_f, Es,  sEs,      NSc, 1, 1);
    gemm_update_kernel<<<gemm_grid, 256>>>(Tjg, W_j_aug, Gj,    Gj1, (float*)0, NJc, 1, 0);
    gemm_update_kernel<<<gemm_grid, 256>>>(Tsg, W_s_aug, Gs,    Gs1, (float*)0, NSc, 1, 0);
    cudaEventRecord(evG, 0);

    // side stream: compacted selected chain (needs Es, Gs1, Gj1)
    cudaStreamWaitEvent(s1, evG, 0);
    spmmL2_sel_kernel<<<256, 256, 0, s1>>>((const float4*)Es, (const float4*)Gs1,
                                           (const float4*)Gj1, j_ids, s_ids);
    {
        dim3 sg(2, 8, 3);
        gemm_sel_kernel<<<sg, 256, 0, s1>>>(e_j_f, W_j + DIMc*DIMc, W_j_aug + DIMc*DIMc,
                                            W_s_aug + DIMc*DIMc, j_ids, s_ids);
    }
    l2norm4_kernel<<<dim3(128, 3), 256, 0, s1>>>(
        (const float4*)ejsel, (float4*)ejsel,
        (const float4*)gjsel, (float4*)gjsel,
        (const float4*)gssel, (float4*)gssel,
        (const float4*)gssel, (float4*)gssel, Bc);
    cudaEventRecord(evSel, s1);

    // default: full Es L2 chain (sum-only GEMM; out not written)
    cudaStreamWaitEvent(0, evTse, 0);
    gemm_update_kernel<<<gemm_grid, 256>>>(Tje, W_s + DIMc*DIMc, Es, (float*)0, sEs, NSc, 0, 2);
    l2norm4_kernel<<<dim3(RB, 1), 256>>>((const float4*)sEs, (float4*)sEs,
                                         (const float4*)sEs, (float4*)sEs,
                                         (const float4*)sEs, (float4*)sEs,
                                         (const float4*)sEs, (float4*)sEs, NSc);
    gatherNE_kernel<<<NEGRc + Bc, 64>>>(negs, s_ids);

    // join sel chain, then losses
    cudaStreamWaitEvent(0, evSel, 0);
    dim3 lg(Bc / 128, Bc / 128);             // 8 x 8
    expsum_kernel<<<lg, 256>>>(gjsel, ejsel, sumexp_j, 1);
    dim3 ng(NEGRc / 128, Bc / 128);          // 256 x 8
    expsum_kernel<<<ng, 256>>>(gssel, negemb, sumexp_s, NNEGc);

    pos_kernel<<<Bc / 8, 256>>>();
    finalize_kernel<<<1, 1024>>>(out);
}

// round 11
// speedup vs baseline: 1.5558x; 1.0088x over previous
#include <cuda_runtime.h>
#include <math.h>

#define NJc 50000
#define NSc 50000
#define Ec  1600000
#define DIMc 256
#define D4c  64
#define Lc   2
#define Bc   1024
#define NNEGc 32
#define NEGRc (NNEGc*Bc)
#define WSZc (Lc*DIMc*DIMc)

// ---------------- scratch (device globals; no allocation allowed) ----------------
__device__ float g_Ej[NJc*DIMc];
__device__ float g_Es[NSc*DIMc];
__device__ float g_Gj[NJc*DIMc];      // layer-0 G_j (preserved)
__device__ float g_Gs[NSc*DIMc];      // layer-0 G_s (preserved)
__device__ float g_Gj1[NJc*DIMc];     // layer-1 G_j
__device__ float g_Gs1[NSc*DIMc];     // layer-1 G_s
__device__ float g_sEs[NSc*DIMc];
__device__ float g_Tje[NJc*DIMc];
__device__ float g_Tjg[NJc*DIMc];
__device__ float g_Tse[NSc*DIMc];
__device__ float g_Tsg[NSc*DIMc];
__device__ float g_Tjec[Bc*DIMc];
__device__ float g_Tjgc[Bc*DIMc];
__device__ float g_Tsgc[Bc*DIMc];
__device__ int   g_cnt_j[NJc];
__device__ int   g_cnt_s[NSc];
__device__ int   g_ptr_j[NJc+1];
__device__ int   g_ptr_s[NSc+1];
__device__ int   g_cur_j[NJc];
__device__ int   g_cur_s[NSc];
__device__ int   g_ccol_j[Ec];
__device__ float g_cval_j[Ec];
__device__ int   g_ccol_s[Ec];
__device__ float g_cval_s[Ec];
__device__ float g_gjsel[Bc*DIMc];
__device__ float g_ejsel[Bc*DIMc];
__device__ float g_gssel[Bc*DIMc];
__device__ float g_essel[Bc*DIMc];
__device__ float g_negemb[NEGRc*DIMc];
__device__ float g_sumexp_j[Bc];
__device__ float g_sumexp_s[Bc*NNEGc];
__device__ float g_scalars[8];   // [0]=pos_j sum, [1]=pos_s sum, [2]=wsq

// ---------------- small utility kernels ----------------
__global__ void zero_kernel() {
    int i = blockIdx.x * blockDim.x + threadIdx.x;
    int st = gridDim.x * blockDim.x;
    for (int k = i; k < NJc; k += st) g_cnt_j[k] = 0;
    for (int k = i; k < NSc; k += st) g_cnt_s[k] = 0;
    for (int k = i; k < Bc; k += st) g_sumexp_j[k] = 0.f;
    for (int k = i; k < Bc*NNEGc; k += st) g_sumexp_s[k] = 0.f;
    if (i < 8) g_scalars[i] = 0.f;
}

__global__ void count_kernel(const int* __restrict__ row_j, const int* __restrict__ col_s) {
    int i = blockIdx.x * blockDim.x + threadIdx.x;
    if (i < Ec) {
        atomicAdd(&g_cnt_j[row_j[i]], 1);
        atomicAdd(&g_cnt_s[col_s[i]], 1);
    }
}

__global__ void scan2_kernel() {
    const int* cnt = blockIdx.x ? g_cnt_s : g_cnt_j;
    int* ptr = blockIdx.x ? g_ptr_s : g_ptr_j;
    int* cur = blockIdx.x ? g_cur_s : g_cur_j;
    int n = blockIdx.x ? NSc : NJc;
    __shared__ int warp_sums[32];
    __shared__ int s_carry;
    int tid = threadIdx.x;
    if (tid == 0) { s_carry = 0; ptr[0] = 0; }
    __syncthreads();
    for (int base = 0; base < n; base += 1024) {
        int i = base + tid;
        int v = (i < n) ? cnt[i] : 0;
        int inc = v;
        #pragma unroll
        for (int off = 1; off < 32; off <<= 1) {
            int t = __shfl_up_sync(0xffffffffu, inc, off);
            if ((tid & 31) >= off) inc += t;
        }
        if ((tid & 31) == 31) warp_sums[tid >> 5] = inc;
        __syncthreads();
        if (tid < 32) {
            int ws = warp_sums[tid];
            int wi = ws;
            #pragma unroll
            for (int off = 1; off < 32; off <<= 1) {
                int t = __shfl_up_sync(0xffffffffu, wi, off);
                if (tid >= off) wi += t;
            }
            warp_sums[tid] = wi - ws;
        }
        __syncthreads();
        int excl = inc - v + warp_sums[tid >> 5];
        int carry = s_carry;
        if (i < n) {
            int start = carry + excl;
            cur[i] = start;
            ptr[i + 1] = start + v;
        }
        __syncthreads();
        if (tid == 1023) s_carry = carry + excl + v;
        __syncthreads();
    }
}

__global__ void scatter_kernel(const int* __restrict__ row_j, const int* __restrict__ col_j,
                               const float* __restrict__ val_j,
                               const int* __restrict__ row_s, const int* __restrict__ col_s,
                               const float* __restrict__ val_s) {
    int i = blockIdx.x * blockDim.x + threadIdx.x;
    if (i >= Ec) return;
    int p = atomicAdd(&g_cur_j[row_j[i]], 1);
    g_ccol_j[p] = col_j[i]; g_cval_j[p] = val_j[i];
    int q = atomicAdd(&g_cur_s[col_s[i]], 1);
    g_ccol_s[q] = row_s[i]; g_cval_s[q] = val_s[i];
}

// ---------------- fused row l2 normalize over up to 4 arrays ----------------
__global__ void l2norm4_kernel(const float4* s0, float4* d0, const float4* s1, float4* d1,
                               const float4* s2, float4* d2, const float4* s3, float4* d3,
                               int n) {
    const float4* src; float4* dst;
    switch (blockIdx.y) {
        case 0: src = s0; dst = d0; break;
        case 1: src = s1; dst = d1; break;
        case 2: src = s2; dst = d2; break;
        default: src = s3; dst = d3; break;
    }
    int w = (blockIdx.x * blockDim.x + threadIdx.x) >> 5;
    int lane = threadIdx.x & 31;
    if (w >= n) return;
    const float4* s = src + (size_t)w * D4c;
    float4 u0 = s[lane], u1 = s[lane + 32];
    float ss = u0.x*u0.x + u0.y*u0.y + u0.z*u0.z + u0.w*u0.w
             + u1.x*u1.x + u1.y*u1.y + u1.z*u1.z + u1.w*u1.w;
    #pragma unroll
    for (int o = 16; o; o >>= 1) ss += __shfl_xor_sync(0xffffffffu, ss, o);
    float inv = 1.f / fmaxf(sqrtf(ss), 1e-12f);
    float4* d = dst + (size_t)w * D4c;
    d[lane]      = make_float4(u0.x*inv, u0.y*inv, u0.z*inv, u0.w*inv);
    d[lane + 32] = make_float4(u1.x*inv, u1.y*inv, u1.z*inv, u1.w*inv);
}

// ---------------- SPMM row bodies ----------------
__device__ __forceinline__ void fma4(float4& acc, float v, const float4& u) {
    acc.x = fmaf(v, u.x, acc.x);
    acc.y = fmaf(v, u.y, acc.y);
    acc.z = fmaf(v, u.z, acc.z);
    acc.w = fmaf(v, u.w, acc.w);
}

__device__ __forceinline__ void spmm_row2(
    const int* __restrict__ ptr, const int* __restrict__ cols, const float* __restrict__ vals,
    const float4* __restrict__ X1, const float4* __restrict__ X2,
    float4* __restrict__ O1, float4* __restrict__ O2, int src, int dst, int lane)
{
    int s = ptr[src], e = ptr[src + 1];
    float4 z = make_float4(0.f, 0.f, 0.f, 0.f);
    float4 a0 = z, a1 = z, b0 = z, b1 = z;
    int p = s;
    for (; p + 2 <= e; p += 2) {
        int c0 = cols[p], c1 = cols[p + 1];
        float v0 = vals[p], v1 = vals[p + 1];
        const float4* x10 = X1 + (size_t)c0 * D4c;
        const float4* x20 = X2 + (size_t)c0 * D4c;
        const float4* x11 = X1 + (size_t)c1 * D4c;
        const float4* x21 = X2 + (size_t)c1 * D4c;
        float4 p0 = x10[lane], p1 = x10[lane + 32];
        float4 q0 = x20[lane], q1 = x20[lane + 32];
        float4 r0 = x11[lane], r1 = x11[lane + 32];
        float4 t0 = x21[lane], t1 = x21[lane + 32];
        fma4(a0, v0, p0); fma4(a1, v0, p1); fma4(b0, v0, q0); fma4(b1, v0, q1);
        fma4(a0, v1, r0); fma4(a1, v1, r1); fma4(b0, v1, t0); fma4(b1, v1, t1);
    }
    if (p < e) {
        int c0 = cols[p]; float v0 = vals[p];
        const float4* x10 = X1 + (size_t)c0 * D4c;
        const float4* x20 = X2 + (size_t)c0 * D4c;
        float4 p0 = x10[lane], p1 = x10[lane + 32];
        float4 q0 = x20[lane], q1 = x20[lane + 32];
        fma4(a0, v0, p0); fma4(a1, v0, p1); fma4(b0, v0, q0); fma4(b1, v0, q1);
    }
    O1[(size_t)dst * D4c + lane] = a0; O1[(size_t)dst * D4c + 32 + lane] = a1;
    O2[(size_t)dst * D4c + lane] = b0; O2[(size_t)dst * D4c + 32 + lane] = b1;
}

__device__ __forceinline__ void spmm_row1(
    const int* __restrict__ ptr, const int* __restrict__ cols, const float* __restrict__ vals,
    const float4* __restrict__ X, float4* __restrict__ O, int src, int dst, int lane)
{
    int s = ptr[src], e = ptr[src + 1];
    float4 z = make_float4(0.f, 0.f, 0.f, 0.f);
    float4 a0 = z, a1 = z;
    int p = s;
    for (; p + 4 <= e; p += 4) {
        int c0 = cols[p], c1 = cols[p+1], c2 = cols[p+2], c3 = cols[p+3];
        float v0 = vals[p], v1 = vals[p+1], v2 = vals[p+2], v3 = vals[p+3];
        const float4* x0 = X + (size_t)c0 * D4c;
        const float4* x1 = X + (size_t)c1 * D4c;
        const float4* x2 = X + (size_t)c2 * D4c;
        const float4* x3 = X + (size_t)c3 * D4c;
        float4 p00 = x0[lane], p01 = x0[lane + 32];
        float4 p10 = x1[lane], p11 = x1[lane + 32];
        float4 p20 = x2[lane], p21 = x2[lane + 32];
        float4 p30 = x3[lane], p31 = x3[lane + 32];
        fma4(a0, v0, p00); fma4(a1, v0, p01);
        fma4(a0, v1, p10); fma4(a1, v1, p11);
        fma4(a0, v2, p20); fma4(a1, v2, p21);
        fma4(a0, v3, p30); fma4(a1, v3, p31);
    }
    for (; p < e; p++) {
        int c0 = cols[p]; float v0 = vals[p];
        const float4* x0 = X + (size_t)c0 * D4c;
        float4 p00 = x0[lane], p01 = x0[lane + 32];
        fma4(a0, v0, p00); fma4(a1, v0, p01);
    }
    O[(size_t)dst * D4c + lane] = a0;
    O[(size_t)dst * D4c + 32 + lane] = a1;
}

// ---------------- L1 SPMM: one CSR side, dual dense operand ----------------
__global__ __launch_bounds__(256) void spmmL1_kernel(
    const int* __restrict__ ptr, const int* __restrict__ cols, const float* __restrict__ vals,
    const float4* __restrict__ X1, const float4* __restrict__ X2,
    float4* __restrict__ O1, float4* __restrict__ O2)
{
    int w = blockIdx.x * 8 + (threadIdx.x >> 5);
    int lane = threadIdx.x & 31;
    if (w >= NJc) return;
    spmm_row2(ptr, cols, vals, X1, X2, O1, O2, w, w, lane);
}

// ---------------- L2 SPMM part 1: full Tse2 = A_s^T @ Ej1 -> g_Tje buffer ----------------
__global__ __launch_bounds__(256) void spmmL2_tse_kernel(
    const float4* __restrict__ Ej, float4* __restrict__ Odst)
{
    int w = blockIdx.x * 8 + (threadIdx.x >> 5);
    int lane = threadIdx.x & 31;
    if (w >= NSc) return;
    spmm_row1(g_ptr_s, g_ccol_s, g_cval_s, Ej, Odst, w, w, lane);
}

// ---------------- L2 SPMM part 2: compacted selected rows ----------------
__global__ __launch_bounds__(256) void spmmL2_sel_kernel(
    const float4* __restrict__ Es, const float4* __restrict__ Gs1, const float4* __restrict__ Gj1,
    const int* __restrict__ j_ids, const int* __restrict__ s_ids)
{
    int gid = blockIdx.x;
    int warp = threadIdx.x >> 5;
    int lane = threadIdx.x & 31;
    if (gid < 128) {
        int i = gid * 8 + warp;
        int row = j_ids[i];
        spmm_row2(g_ptr_j, g_ccol_j, g_cval_j, Es, Gs1,
                  (float4*)g_Tjec, (float4*)g_Tjgc, row, i, lane);
    } else {
        int i = (gid - 128) * 8 + warp;
        int row = s_ids[i];
        spmm_row1(g_ptr_s, g_ccol_s, g_cval_s, Gj1, (float4*)g_Tsgc, row, i, lane);
    }
}

// ---------------- double-buffered SGEMM 128x128x16 (NT) + flexible epilogue ----------
// nv = old + relu(C); wout: write outv; smode: 0 none, 1 sum=old+nv, 2 sum+=nv
__global__ __launch_bounds__(256, 2) void gemm_update_kernel(
    const float* __restrict__ A, const float* __restrict__ W,
    const float* __restrict__ oldv, float* __restrict__ outv, float* __restrict__ sumv,
    int M, int wout, int smode)
{
    __shared__ float As[2][16][128];
    __shared__ float Bs[2][16][128];
    int tid = threadIdx.x;
    int tx = tid & 15, ty = tid >> 4;
    int rowTile = blockIdx.y * 128;
    int colTile = blockIdx.x * 128;
    float acc[8][8];
    #pragma unroll
    for (int i = 0; i < 8; i++)
        #pragma unroll
        for (int j = 0; j < 8; j++) acc[i][j] = 0.f;

    int lrow = tid & 127;
    int khalf = (tid >> 7) * 8;
    const float* Ag = A + (size_t)(rowTile + lrow) * DIMc + khalf;
    const float* Wg = W + (size_t)(colTile + lrow) * DIMc + khalf;
    bool arow_ok = (rowTile + lrow) < M;
    const float4 z4 = make_float4(0.f, 0.f, 0.f, 0.f);

    float4 ra0 = arow_ok ? *(const float4*)(Ag + 0) : z4;
    float4 ra1 = arow_ok ? *(const float4*)(Ag + 4) : z4;
    float4 rb0 = *(const float4*)(Wg + 0);
    float4 rb1 = *(const float4*)(Wg + 4);
    As[0][khalf+0][lrow] = ra0.x; As[0][khalf+1][lrow] = ra0.y;
    As[0][khalf+2][lrow] = ra0.z; As[0][khalf+3][lrow] = ra0.w;
    As[0][khalf+4][lrow] = ra1.x; As[0][khalf+5][lrow] = ra1.y;
    As[0][khalf+6][lrow] = ra1.z; As[0][khalf+7][lrow] = ra1.w;
    Bs[0][khalf+0][lrow] = rb0.x; Bs[0][khalf+1][lrow] = rb0.y;
    Bs[0][khalf+2][lrow] = rb0.z; Bs[0][khalf+3][lrow] = rb0.w;
    Bs[0][khalf+4][lrow] = rb1.x; Bs[0][khalf+5][lrow] = rb1.y;
    Bs[0][khalf+6][lrow] = rb1.z; Bs[0][khalf+7][lrow] = rb1.w;
    __syncthreads();

    int buf = 0;
    for (int k0 = 16; k0 <= DIMc; k0 += 16) {
        bool more = k0 < DIMc;
        if (more) {
            ra0 = arow_ok ? *(const float4*)(Ag + k0) : z4;
            ra1 = arow_ok ? *(const float4*)(Ag + k0 + 4) : z4;
            rb0 = *(const float4*)(Wg + k0);
            rb1 = *(const float4*)(Wg + k0 + 4);
        }
        #pragma unroll
        for (int kk = 0; kk < 16; kk++) {
            float a[8], b[8];
            #pragma unroll
            for (int i = 0; i < 4; i++) {
                a[i]   = As[buf][kk][ty*4 + i];
                a[i+4] = As[buf][kk][ty*4 + i + 64];
                b[i]   = Bs[buf][kk][tx*4 + i];
                b[i+4] = Bs[buf][kk][tx*4 + i + 64];
            }
            #pragma unroll
            for (int i = 0; i < 8; i++)
                #pragma unroll
                for (int j = 0; j < 8; j++)
                    acc[i][j] = fmaf(a[i], b[j], acc[i][j]);
        }
        if (more) {
            int nb = buf ^ 1;
            As[nb][khalf+0][lrow] = ra0.x; As[nb][khalf+1][lrow] = ra0.y;
            As[nb][khalf+2][lrow] = ra0.z; As[nb][khalf+3][lrow] = ra0.w;
            As[nb][khalf+4][lrow] = ra1.x; As[nb][khalf+5][lrow] = ra1.y;
            As[nb][khalf+6][lrow] = ra1.z; As[nb][khalf+7][lrow] = ra1.w;
            Bs[nb][khalf+0][lrow] = rb0.x; Bs[nb][khalf+1][lrow] = rb0.y;
            Bs[nb][khalf+2][lrow] = rb0.z; Bs[nb][khalf+3][lrow] = rb0.w;
            Bs[nb][khalf+4][lrow] = rb1.x; Bs[nb][khalf+5][lrow] = rb1.y;
            Bs[nb][khalf+6][lrow] = rb1.z; Bs[nb][khalf+7][lrow] = rb1.w;
            __syncthreads();
            buf = nb;
        }
    }
    #pragma unroll
    for (int i = 0; i < 8; i++) {
        int gr = rowTile + ty*4 + (i & 3) + ((i >> 2) * 64);
        if (gr < M) {
            #pragma unroll
            for (int j = 0; j < 8; j++) {
                int gc = colTile + tx*4 + (j & 3) + ((j >> 2) * 64);
                size_t idx = (size_t)gr * DIMc + gc;
                float v = fmaxf(acc[i][j], 0.f);
                float o = oldv[idx];
                float nv = o + v;
                if (wout) outv[idx] = nv;
                if (smode == 1) sumv[idx] = o + nv;
                else if (smode == 2) sumv[idx] = sumv[idx] + nv;
            }
        }
    }
}

// ---------------- compacted selected GEMM (3 problems via blockIdx.z) ----------------
// dst[i,:] = base0[ids[i],:] + 2*base1[ids[i],:] + relu(Ac[i,:] @ W^T)
__global__ __launch_bounds__(256, 2) void gemm_sel_kernel(
    const float* __restrict__ e_j_f,
    const float* __restrict__ Wj2, const float* __restrict__ Wja2, const float* __restrict__ Wsa2,
    const int* __restrict__ j_ids, const int* __restrict__ s_ids)
{
    __shared__ float As[2][16][128];
    __shared__ float Bs[2][16][128];
    const float* A; const float* W; const float* base0; const float* base1;
    float* dst; const int* ids;
    switch (blockIdx.z) {
        case 0: A = g_Tjec; W = Wj2;  base0 = e_j_f; base1 = g_Ej;  dst = g_ejsel; ids = j_ids; break;
        case 1: A = g_Tjgc; W = Wja2; base0 = g_Gj;  base1 = g_Gj1; dst = g_gjsel; ids = j_ids; break;
        default: A = g_Tsgc; W = Wsa2; base0 = g_Gs; base1 = g_Gs1; dst = g_gssel; ids = s_ids; break;
    }
    int tid = threadIdx.x;
    int tx = tid & 15, ty = tid >> 4;
    int rowTile = blockIdx.y * 128;
    int colTile = blockIdx.x * 128;
    float acc[8][8];
    #pragma unroll
    for (int i = 0; i < 8; i++)
        #pragma unroll
        for (int j = 0; j < 8; j++) acc[i][j] = 0.f;

    int lrow = tid & 127;
    int khalf = (tid >> 7) * 8;
    const float* Ag = A + (size_t)(rowTile + lrow) * DIMc + khalf;
    const float* Wg = W + (size_t)(colTile + lrow) * DIMc + khalf;

    float4 ra0 = *(const float4*)(Ag + 0);
    float4 ra1 = *(const float4*)(Ag + 4);
    float4 rb0 = *(const float4*)(Wg + 0);
    float4 rb1 = *(const float4*)(Wg + 4);
    As[0][khalf+0][lrow] = ra0.x; As[0][khalf+1][lrow] = ra0.y;
    As[0][khalf+2][lrow] = ra0.z; As[0][khalf+3][lrow] = ra0.w;
    As[0][khalf+4][lrow] = ra1.x; As[0][khalf+5][lrow] = ra1.y;
    As[0][khalf+6][lrow] = ra1.z; As[0][khalf+7][lrow] = ra1.w;
    Bs[0][khalf+0][lrow] = rb0.x; Bs[0][khalf+1][lrow] = rb0.y;
    Bs[0][khalf+2][lrow] = rb0.z; Bs[0][khalf+3][lrow] = rb0.w;
    Bs[0][khalf+4][lrow] = rb1.x; Bs[0][khalf+5][lrow] = rb1.y;
    Bs[0][khalf+6][lrow] = rb1.z; Bs[0][khalf+7][lrow] = rb1.w;
    __syncthreads();

    int buf = 0;
    for (int k0 = 16; k0 <= DIMc; k0 += 16) {
        bool more = k0 < DIMc;
        if (more) {
            ra0 = *(const float4*)(Ag + k0);
            ra1 = *(const float4*)(Ag + k0 + 4);
            rb0 = *(const float4*)(Wg + k0);
            rb1 = *(const float4*)(Wg + k0 + 4);
        }
        #pragma unroll
        for (int kk = 0; kk < 16; kk++) {
            float a[8], b[8];
            #pragma unroll
            for (int i = 0; i < 4; i++) {
                a[i]   = As[buf][kk][ty*4 + i];
                a[i+4] = As[buf][kk][ty*4 + i + 64];
                b[i]   = Bs[buf][kk][tx*4 + i];
                b[i+4] = Bs[buf][kk][tx*4 + i + 64];
            }
            #pragma unroll
            for (int i = 0; i < 8; i++)
                #pragma unroll
                for (int j = 0; j < 8; j++)
                    acc[i][j] = fmaf(a[i], b[j], acc[i][j]);
        }
        if (more) {
            int nb = buf ^ 1;
            As[nb][khalf+0][lrow] = ra0.x; As[nb][khalf+1][lrow] = ra0.y;
            As[nb][khalf+2][lrow] = ra0.z; As[nb][khalf+3][lrow] = ra0.w;
            As[nb][khalf+4][lrow] = ra1.x; As[nb][khalf+5][lrow] = ra1.y;
            As[nb][khalf+6][lrow] = ra1.z; As[nb][khalf+7][lrow] = ra1.w;
            Bs[nb][khalf+0][lrow] = rb0.x; Bs[nb][khalf+1][lrow] = rb0.y;
            Bs[nb][khalf+2][lrow] = rb0.z; Bs[nb][khalf+3][lrow] = rb0.w;
            Bs[nb][khalf+4][lrow] = rb1.x; Bs[nb][khalf+5][lrow] = rb1.y;
            Bs[nb][khalf+6][lrow] = rb1.z; Bs[nb][khalf+7][lrow] = rb1.w;
            __syncthreads();
            buf = nb;
        }
    }
    #pragma unroll
    for (int i = 0; i < 8; i++) {
        int gr = rowTile + ty*4 + (i & 3) + ((i >> 2) * 64);
        int id = ids[gr];
        #pragma unroll
        for (int j = 0; j < 8; j++) {
            int gc = colTile + tx*4 + (j & 3) + ((j >> 2) * 64);
            size_t src = (size_t)id * DIMc + gc;
            float v = fmaxf(acc[i][j], 0.f);
            dst[(size_t)gr * DIMc + gc] = base0[src] + 2.f * base1[src] + v;
        }
    }
}

// ---------------- double-buffered GEMM + exp + per-(row,group) sum ----------------
__global__ __launch_bounds__(256, 2) void expsum_kernel(
    const float* __restrict__ A, const float* __restrict__ Bm,
    float* __restrict__ sumexp, int ngroups)
{
    __shared__ float As[2][16][128];
    __shared__ float Bs[2][16][128];
    __shared__ float red[128];
    int tid = threadIdx.x;
    int tx = tid & 15, ty = tid >> 4;
    int rowTile = blockIdx.y * 128;
    int colTile = blockIdx.x * 128;
    float acc[8][8];
    #pragma unroll
    for (int i = 0; i < 8; i++)
        #pragma unroll
        for (int j = 0; j < 8; j++) acc[i][j] = 0.f;

    int lrow = tid & 127;
    int khalf = (tid >> 7) * 8;
    const float* Ag = A + (size_t)(rowTile + lrow) * DIMc + khalf;
    const float* Bg = Bm + (size_t)(colTile + lrow) * DIMc + khalf;

    float4 ra0 = *(const float4*)(Ag + 0);
    float4 ra1 = *(const float4*)(Ag + 4);
    float4 rb0 = *(const float4*)(Bg + 0);
    float4 rb1 = *(const float4*)(Bg + 4);
    As[0][khalf+0][lrow] = ra0.x; As[0][khalf+1][lrow] = ra0.y;
    As[0][khalf+2][lrow] = ra0.z; As[0][khalf+3][lrow] = ra0.w;
    As[0][khalf+4][lrow] = ra1.x; As[0][khalf+5][lrow] = ra1.y;
    As[0][khalf+6][lrow] = ra1.z; As[0][khalf+7][lrow] = ra1.w;
    Bs[0][khalf+0][lrow] = rb0.x; Bs[0][khalf+1][lrow] = rb0.y;
    Bs[0][khalf+2][lrow] = rb0.z; Bs[0][khalf+3][lrow] = rb0.w;
    Bs[0][khalf+4][lrow] = rb1.x; Bs[0][khalf+5][lrow] = rb1.y;
    Bs[0][khalf+6][lrow] = rb1.z; Bs[0][khalf+7][lrow] = rb1.w;
    __syncthreads();

    int buf = 0;
    for (int k0 = 16; k0 <= DIMc; k0 += 16) {
        bool more = k0 < DIMc;
        if (more) {
            ra0 = *(const float4*)(Ag + k0);
            ra1 = *(const float4*)(Ag + k0 + 4);
            rb0 = *(const float4*)(Bg + k0);
            rb1 = *(const float4*)(Bg + k0 + 4);
        }
        #pragma unroll
        for (int kk = 0; kk < 16; kk++) {
            float a[8], b[8];
            #pragma unroll
            for (int i = 0; i < 4; i++) {
                a[i]   = As[buf][kk][ty*4 + i];
                a[i+4] = As[buf][kk][ty*4 + i + 64];
                b[i]   = Bs[buf][kk][tx*4 + i];
                b[i+4] = Bs[buf][kk][tx*4 + i + 64];
            }
            #pragma unroll
            for (int i = 0; i < 8; i++)
                #pragma unroll
                for (int j = 0; j < 8; j++)
                    acc[i][j] = fmaf(a[i], b[j], acc[i][j]);
        }
        if (more) {
            int nb = buf ^ 1;
            As[nb][khalf+0][lrow] = ra0.x; As[nb][khalf+1][lrow] = ra0.y;
            As[nb][khalf+2][lrow] = ra0.z; As[nb][khalf+3][lrow] = ra0.w;
            As[nb][khalf+4][lrow] = ra1.x; As[nb][khalf+5][lrow] = ra1.y;
            As[nb][khalf+6][lrow] = ra1.z; As[nb][khalf+7][lrow] = ra1.w;
            Bs[nb][khalf+0][lrow] = rb0.x; Bs[nb][khalf+1][lrow] = rb0.y;
            Bs[nb][khalf+2][lrow] = rb0.z; Bs[nb][khalf+3][lrow] = rb0.w;
            Bs[nb][khalf+4][lrow] = rb1.x; Bs[nb][khalf+5][lrow] = rb1.y;
            Bs[nb][khalf+6][lrow] = rb1.z; Bs[nb][khalf+7][lrow] = rb1.w;
            __syncthreads();
            buf = nb;
        }
    }
    float rsum[8];
    #pragma unroll
    for (int i = 0; i < 8; i++) {
        rsum[i] = 0.f;
        #pragma unroll
        for (int j = 0; j < 8; j++) rsum[i] += expf(acc[i][j] * 5.0f);  // 1/TEMP = 5
    }
    if (tid < 128) red[tid] = 0.f;
    __syncthreads();
    #pragma unroll
    for (int i = 0; i < 8; i++) {
        int r = ty*4 + (i & 3) + ((i >> 2) * 64);
        atomicAdd(&red[r], rsum[i]);
    }
    __syncthreads();
    if (tid < 128) {
        int gr = rowTile + tid;
        int group = blockIdx.x >> 3;
        atomicAdd(&sumexp[(size_t)gr * ngroups + group], red[tid]);
    }
}

// ---------------- combined gather: negemb (NEGR rows) + essel (B rows) ----------------
__global__ void gatherNE_kernel(const int* __restrict__ negs, const int* __restrict__ s_ids) {
    int row = blockIdx.x;
    const float4* src = (const float4*)g_sEs;
    if (row < NEGRc) {
        int id = negs[row];
        ((float4*)g_negemb)[(size_t)row * D4c + threadIdx.x] = src[(size_t)id * D4c + threadIdx.x];
    } else {
        int r = row - NEGRc;
        int id = s_ids[r];
        ((float4*)g_essel)[(size_t)r * D4c + threadIdx.x] = src[(size_t)id * D4c + threadIdx.x];
    }
}

// ---------------- pos score ----------------
__global__ void pos_kernel() {
    int w = (blockIdx.x * blockDim.x + threadIdx.x) >> 5;
    int lane = threadIdx.x & 31;
    if (w >= Bc) return;
    const float4* gj = (const float4*)g_gjsel + (size_t)w * D4c;
    const float4* ej = (const float4*)g_ejsel + (size_t)w * D4c;
    const float4* gs = (const float4*)g_gssel + (size_t)w * D4c;
    const float4* es = (const float4*)g_essel + (size_t)w * D4c;
    float4 a0 = gj[lane], a1 = gj[lane+32], b0 = ej[lane], b1 = ej[lane+32];
    float4 c0 = gs[lane], c1 = gs[lane+32], d0 = es[lane], d1 = es[lane+32];
    float s1 = a0.x*b0.x + a0.y*b0.y + a0.z*b0.z + a0.w*b0.w
             + a1.x*b1.x + a1.y*b1.y + a1.z*b1.z + a1.w*b1.w;
    float s2 = c0.x*d0.x + c0.y*d0.y + c0.z*d0.z + c0.w*d0.w
             + c1.x*d1.x + c1.y*d1.y + c1.z*d1.z + c1.w*d1.w;
    #pragma unroll
    for (int o = 16; o; o >>= 1) {
        s1 += __shfl_xor_sync(0xffffffffu, s1, o);
        s2 += __shfl_xor_sync(0xffffffffu, s2, o);
    }
    if (lane == 0) {
        float c1v = fminf(fmaxf(s1 * 5.0f, -1.f), 1.f);
        float c2v = fminf(fmaxf(s2 * 5.0f, -1.f), 1.f);
        atomicAdd(&g_scalars[0], c1v);
        atomicAdd(&g_scalars[1], c2v);
    }
}

// ---------------- weight L2 regularizer ----------------
__global__ void wsq_kernel(const float* __restrict__ a, const float* __restrict__ b,
                           const float* __restrict__ c, const float* __restrict__ d) {
    float s = 0.f;
    for (int i = blockIdx.x * blockDim.x + threadIdx.x; i < WSZc; i += gridDim.x * blockDim.x) {
        float x;
        x = a[i]; s += x * x;
        x = b[i]; s += x * x;
        x = c[i]; s += x * x;
        x = d[i]; s += x * x;
    }
    #pragma unroll
    for (int o = 16; o; o >>= 1) s += __shfl_xor_sync(0xffffffffu, s, o);
    __shared__ float sh[8];
    int lane = threadIdx.x & 31, wid = threadIdx.x >> 5;
    if (lane == 0) sh[wid] = s;
    __syncthreads();
    if (threadIdx.x == 0) {
        float t = 0.f;
        for (int i = 0; i < (int)(blockDim.x >> 5); i++) t += sh[i];
        atomicAdd(&g_scalars[2], t);
    }
}

// ---------------- finalize ----------------
__device__ double blk_reduce_1024(double v) {
    __shared__ double sh[32];
    __syncthreads();
    int lane = threadIdx.x & 31, wid = threadIdx.x >> 5;
    #pragma unroll
    for (int o = 16; o; o >>= 1) v += __shfl_down_sync(0xffffffffu, v, o);
    if (lane == 0) sh[wid] = v;
    __syncthreads();
    v = (threadIdx.x < 32) ? sh[threadIdx.x] : 0.0;
    if (wid == 0) {
        #pragma unroll
        for (int o = 16; o; o >>= 1) v += __shfl_down_sync(0xffffffffu, v, o);
    }
    return v;
}

__global__ void finalize_kernel(float* __restrict__ out) {
    int tid = threadIdx.x;
    double a = (tid < Bc) ? log((double)g_sumexp_j[tid] + 1e-8) : 0.0;
    double negj = blk_reduce_1024(a);
    double b = 0.0;
    for (int i = tid; i < Bc * NNEGc; i += 1024)
        b += log((double)g_sumexp_s[i] + 1e-8);
    double negs = blk_reduce_1024(b);
    if (tid == 0) {
        double pos = (double)g_scalars[0] / Bc + (double)g_scalars[1] / Bc;
        double neg = negj / Bc + negs / (double)(Bc * NNEGc);
        double cl = (-pos + neg) * 0.2;
        double reg = 1e-4 * (double)g_scalars[2];
        out[0] = (float)(cl + reg);
        out[1] = (float)cl;
        out[2] = (float)reg;
    }
}

// ---------------- launch ----------------
#define SYM(p, s) do { void* _t = 0; cudaGetSymbolAddress(&_t, s); p = (decltype(p))_t; } while (0)

extern "C" void kernel_launch(void* const* d_in, const int* in_sizes, int n_in,
                              void* d_out, int out_size) {
    (void)in_sizes; (void)n_in; (void)out_size;
    const float* e_j_f   = (const float*)d_in[0];
    const float* e_s_f   = (const float*)d_in[1];
    const float* aug_e_j = (const float*)d_in[2];
    const float* aug_e_s = (const float*)d_in[3];
    const float* val_j   = (const float*)d_in[4];
    const float* val_s   = (const float*)d_in[5];
    const float* W_j     = (const float*)d_in[6];
    const float* W_s     = (const float*)d_in[7];
    const float* W_j_aug = (const float*)d_in[8];
    const float* W_s_aug = (const float*)d_in[9];
    const int* row_j = (const int*)d_in[10];
    const int* col_j = (const int*)d_in[11];
    const int* row_s = (const int*)d_in[12];
    const int* col_s = (const int*)d_in[13];
    const int* j_ids = (const int*)d_in[14];
    const int* s_ids = (const int*)d_in[15];
    const int* negs  = (const int*)d_in[16];
    float* out = (float*)d_out;

    float *Ej, *Es, *Gj, *Gs, *Gj1, *Gs1, *sEs;
    float *Tje, *Tjg, *Tse, *Tsg;
    int *ptr_j, *ptr_s, *ccol_j, *ccol_s;
    float *cval_j, *cval_s;
    float *gjsel, *ejsel, *gssel, *negemb, *sumexp_j, *sumexp_s;
    SYM(Ej, g_Ej); SYM(Es, g_Es); SYM(Gj, g_Gj); SYM(Gs, g_Gs);
    SYM(Gj1, g_Gj1); SYM(Gs1, g_Gs1); SYM(sEs, g_sEs);
    SYM(Tje, g_Tje); SYM(Tjg, g_Tjg); SYM(Tse, g_Tse); SYM(Tsg, g_Tsg);
    SYM(ptr_j, g_ptr_j); SYM(ptr_s, g_ptr_s);
    SYM(ccol_j, g_ccol_j); SYM(ccol_s, g_ccol_s);
    SYM(cval_j, g_cval_j); SYM(cval_s, g_cval_s);
    SYM(gjsel, g_gjsel); SYM(ejsel, g_ejsel); SYM(gssel, g_gssel);
    SYM(negemb, g_negemb); SYM(sumexp_j, g_sumexp_j); SYM(sumexp_s, g_sumexp_s);

    static int inited = 0;
    static cudaStream_t s1;
    static cudaEvent_t evStart, evL2n, evSpmmJ, evSpmmS, evEj, evTse, evG, evSel, evGat, evLoss;
    if (!inited) {
        cudaStreamCreateWithFlags(&s1, cudaStreamNonBlocking);
        cudaEventCreateWithFlags(&evStart, cudaEventDisableTiming);
        cudaEventCreateWithFlags(&evL2n,   cudaEventDisableTiming);
        cudaEventCreateWithFlags(&evSpmmJ, cudaEventDisableTiming);
        cudaEventCreateWithFlags(&evSpmmS, cudaEventDisableTiming);
        cudaEventCreateWithFlags(&evEj,    cudaEventDisableTiming);
        cudaEventCreateWithFlags(&evTse,   cudaEventDisableTiming);
        cudaEventCreateWithFlags(&evG,     cudaEventDisableTiming);
        cudaEventCreateWithFlags(&evSel,   cudaEventDisableTiming);
        cudaEventCreateWithFlags(&evGat,   cudaEventDisableTiming);
        cudaEventCreateWithFlags(&evLoss,  cudaEventDisableTiming);
        inited = 1;
    }

    const int EB = (Ec + 255) / 256;         // 6250
    const int RB = 6250;                     // warp-per-row blocks

    zero_kernel<<<256, 256>>>();
    cudaEventRecord(evStart, 0);
    cudaStreamWaitEvent(s1, evStart, 0);

    // side stream: initial l2norm + wsq (independent of CSR build)
    {
        dim3 g(RB, 2);
        l2norm4_kernel<<<g, 256, 0, s1>>>((const float4*)aug_e_j, (float4*)Gj,
                                          (const float4*)aug_e_s, (float4*)Gs,
                                          (const float4*)aug_e_j, (float4*)Gj,
                                          (const float4*)aug_e_s, (float4*)Gs, NJc);
        wsq_kernel<<<256, 256, 0, s1>>>(W_j, W_s, W_j_aug, W_s_aug);
        cudaEventRecord(evL2n, s1);
    }
    // default stream: CSR build
    count_kernel<<<EB, 256>>>(row_j, col_s);
    scan2_kernel<<<2, 1024>>>();
    scatter_kernel<<<EB, 256>>>(row_j, col_j, val_j, row_s, col_s, val_s);
    cudaStreamWaitEvent(0, evL2n, 0);

    dim3 gemm_grid(2, 391);

    // ---- layer 1, j side first ----
    spmmL1_kernel<<<RB, 256>>>(ptr_j, ccol_j, cval_j,
                               (const float4*)e_s_f, (const float4*)Gs,
                               (float4*)Tje, (float4*)Tjg);
    cudaEventRecord(evSpmmJ, 0);
    // side stream: s-side L1 SPMM, overlapped with j-side GEMMs
    cudaStreamWaitEvent(s1, evSpmmJ, 0);
    spmmL1_kernel<<<RB, 256, 0, s1>>>(ptr_s, ccol_s, cval_s,
                                      (const float4*)e_j_f, (const float4*)Gj,
                                      (float4*)Tse, (float4*)Tsg);
    cudaEventRecord(evSpmmS, s1);

    gemm_update_kernel<<<gemm_grid, 256>>>(Tje, W_j, e_j_f, Ej, (float*)0, NJc, 1, 0);
    cudaEventRecord(evEj, 0);
    // side stream: full L2 SPMM Tse2 = A_s^T @ Ej -> g_Tje (Tje free after GEMM_Ej)
    cudaStreamWaitEvent(s1, evEj, 0);
    spmmL2_tse_kernel<<<RB, 256, 0, s1>>>((const float4*)Ej, (float4*)Tje);
    cudaEventRecord(evTse, s1);

    gemm_update_kernel<<<gemm_grid, 256>>>(Tjg, W_j_aug, Gj, Gj1, (float*)0, NJc, 1, 0);
    cudaStreamWaitEvent(0, evSpmmS, 0);
    gemm_update_kernel<<<gemm_grid, 256>>>(Tse, W_s,     e_s_f, Es,  sEs,       NSc, 1, 1);
    gemm_update_kernel<<<gemm_grid, 256>>>(Tsg, W_s_aug, Gs,    Gs1, (float*)0, NSc, 1, 0);
    cudaEventRecord(evG, 0);

    // side stream: compacted selected chain (needs Es, Gs1, Gj1)
    cudaStreamWaitEvent(s1, evG, 0);
    spmmL2_sel_kernel<<<256, 256, 0, s1>>>((const float4*)Es, (const float4*)Gs1,
                                           (const float4*)Gj1, j_ids, s_ids);
    {
        dim3 sg(2, 8, 3);
        gemm_sel_kernel<<<sg, 256, 0, s1>>>(e_j_f, W_j + DIMc*DIMc, W_j_aug + DIMc*DIMc,
                                            W_s_aug + DIMc*DIMc, j_ids, s_ids);
    }
    l2norm4_kernel<<<dim3(128, 3), 256, 0, s1>>>(
        (const float4*)ejsel, (float4*)ejsel,
        (const float4*)gjsel, (float4*)gjsel,
        (const float4*)gssel, (float4*)gssel,
        (const float4*)gssel, (float4*)gssel, Bc);
    cudaEventRecord(evSel, s1);

    // default: full Es L2 chain (sum-only GEMM; out not written)
    cudaStreamWaitEvent(0, evTse, 0);
    gemm_update_kernel<<<gemm_grid, 256>>>(Tje, W_s + DIMc*DIMc, Es, (float*)0, sEs, NSc, 0, 2);
    l2norm4_kernel<<<dim3(RB, 1), 256>>>((const float4*)sEs, (float4*)sEs,
                                         (const float4*)sEs, (float4*)sEs,
                                         (const float4*)sEs, (float4*)sEs,
                                         (const float4*)sEs, (float4*)sEs, NSc);
    gatherNE_kernel<<<NEGRc + Bc, 64>>>(negs, s_ids);
    cudaEventRecord(evGat, 0);

    // small losses on side stream, big expsum_s on default
    cudaStreamWaitEvent(s1, evGat, 0);   // s1 already ordered after evSel (in-order stream)
    {
        dim3 lg(Bc / 128, Bc / 128);     // 8 x 8
        expsum_kernel<<<lg, 256, 0, s1>>>(gjsel, ejsel, sumexp_j, 1);
        pos_kernel<<<Bc / 8, 256, 0, s1>>>();
        cudaEventRecord(evLoss, s1);
    }
    cudaStreamWaitEvent(0, evSel, 0);
    {
        dim3 ng(NEGRc / 128, Bc / 128);  // 256 x 8
        expsum_kernel<<<ng, 256>>>(gssel, negemb, sumexp_s, NNEGc);
    }
    cudaStreamWaitEvent(0, evLoss, 0);
    finalize_kernel<<<1, 1024>>>(out);
}

// round 12
// speedup vs baseline: 1.8782x; 1.2072x over previous
#include <cuda_runtime.h>
#include <math.h>

#define NJc 50000
#define NSc 50000
#define Ec  1600000
#define DIMc 256
#define D4c  64
#define Lc   2
#define Bc   1024
#define NNEGc 32
#define NEGRc (NNEGc*Bc)
#define WSZc (Lc*DIMc*DIMc)

// ---------------- scratch (device globals; no allocation allowed) ----------------
__device__ float g_Ej[NJc*DIMc];
__device__ float g_Es[NSc*DIMc];
__device__ float g_Gj[NJc*DIMc];      // layer-0 G_j (preserved)
__device__ float g_Gs[NSc*DIMc];      // layer-0 G_s (preserved)
__device__ float g_Gj1[NJc*DIMc];     // layer-1 G_j, COMPACT rows (jlist order)
__device__ float g_Gs1[NSc*DIMc];     // layer-1 G_s, COMPACT rows (slist order)
__device__ float g_sEs[NSc*DIMc];
__device__ float g_Tje[NJc*DIMc];
__device__ float g_Tjg[NJc*DIMc];     // compact G SPMM out (j side)
__device__ float g_Tse[NSc*DIMc];
__device__ float g_Tsg[NSc*DIMc];     // compact G SPMM out (s side)
__device__ float g_Tjec[Bc*DIMc];
__device__ float g_Tjgc[Bc*DIMc];
__device__ float g_Tsgc[Bc*DIMc];
__device__ int   g_cnt_j[NJc];
__device__ int   g_cnt_s[NSc];
__device__ int   g_ptr_j[NJc+1];
__device__ int   g_ptr_s[NSc+1];
__device__ int   g_cur_j[NJc];
__device__ int   g_cur_s[NSc];
__device__ int   g_ccol_j[Ec];
__device__ float g_cval_j[Ec];
__device__ int   g_ccol_s[Ec];
__device__ float g_cval_s[Ec];
// neighbor-set machinery
__device__ int   g_jmark[NJc];
__device__ int   g_smark[NSc];
__device__ int   g_jlist[NJc];
__device__ int   g_slist[NSc];
__device__ int   g_jmap[NJc];
__device__ int   g_smap[NSc];
__device__ int   g_jcnt_sel;
__device__ int   g_scnt_sel;
__device__ float g_gjsel[Bc*DIMc];
__device__ float g_ejsel[Bc*DIMc];
__device__ float g_gssel[Bc*DIMc];
__device__ float g_essel[Bc*DIMc];
__device__ float g_negemb[NEGRc*DIMc];
__device__ float g_sumexp_j[Bc];
__device__ float g_sumexp_s[Bc*NNEGc];
__device__ float g_scalars[8];   // [0]=pos_j sum, [1]=pos_s sum, [2]=wsq

// ---------------- small utility kernels ----------------
__global__ void zero_kernel() {
    int i = blockIdx.x * blockDim.x + threadIdx.x;
    int st = gridDim.x * blockDim.x;
    for (int k = i; k < NJc; k += st) { g_cnt_j[k] = 0; g_jmark[k] = 0; }
    for (int k = i; k < NSc; k += st) { g_cnt_s[k] = 0; g_smark[k] = 0; }
    for (int k = i; k < Bc; k += st) g_sumexp_j[k] = 0.f;
    for (int k = i; k < Bc*NNEGc; k += st) g_sumexp_s[k] = 0.f;
    if (i < 8) g_scalars[i] = 0.f;
    if (i == 8) { g_jcnt_sel = 0; g_scnt_sel = 0; }
}

__global__ void count_kernel(const int* __restrict__ row_j, const int* __restrict__ col_s) {
    int i = blockIdx.x * blockDim.x + threadIdx.x;
    if (i < Ec) {
        atomicAdd(&g_cnt_j[row_j[i]], 1);
        atomicAdd(&g_cnt_s[col_s[i]], 1);
    }
}

__global__ void scan2_kernel() {
    const int* cnt = blockIdx.x ? g_cnt_s : g_cnt_j;
    int* ptr = blockIdx.x ? g_ptr_s : g_ptr_j;
    int* cur = blockIdx.x ? g_cur_s : g_cur_j;
    int n = blockIdx.x ? NSc : NJc;
    __shared__ int warp_sums[32];
    __shared__ int s_carry;
    int tid = threadIdx.x;
    if (tid == 0) { s_carry = 0; ptr[0] = 0; }
    __syncthreads();
    for (int base = 0; base < n; base += 1024) {
        int i = base + tid;
        int v = (i < n) ? cnt[i] : 0;
        int inc = v;
        #pragma unroll
        for (int off = 1; off < 32; off <<= 1) {
            int t = __shfl_up_sync(0xffffffffu, inc, off);
            if ((tid & 31) >= off) inc += t;
        }
        if ((tid & 31) == 31) warp_sums[tid >> 5] = inc;
        __syncthreads();
        if (tid < 32) {
            int ws = warp_sums[tid];
            int wi = ws;
            #pragma unroll
            for (int off = 1; off < 32; off <<= 1) {
                int t = __shfl_up_sync(0xffffffffu, wi, off);
                if (tid >= off) wi += t;
            }
            warp_sums[tid] = wi - ws;
        }
        __syncthreads();
        int excl = inc - v + warp_sums[tid >> 5];
        int carry = s_carry;
        if (i < n) {
            int start = carry + excl;
            cur[i] = start;
            ptr[i + 1] = start + v;
        }
        __syncthreads();
        if (tid == 1023) s_carry = carry + excl + v;
        __syncthreads();
    }
}

__global__ void scatter_kernel(const int* __restrict__ row_j, const int* __restrict__ col_j,
                               const float* __restrict__ val_j,
                               const int* __restrict__ row_s, const int* __restrict__ col_s,
                               const float* __restrict__ val_s) {
    int i = blockIdx.x * blockDim.x + threadIdx.x;
    if (i >= Ec) return;
    int p = atomicAdd(&g_cur_j[row_j[i]], 1);
    g_ccol_j[p] = col_j[i]; g_cval_j[p] = val_j[i];
    int q = atomicAdd(&g_cur_s[col_s[i]], 1);
    g_ccol_s[q] = row_s[i]; g_cval_s[q] = val_s[i];
}

// mark neighbor sets: Sset = N(j_ids) via CSR_j cols + s_ids; Jset = N(s_ids) via CSR_s + j_ids
__global__ void mark_kernel(const int* __restrict__ j_ids, const int* __restrict__ s_ids) {
    int w = blockIdx.x * (blockDim.x >> 5) + (threadIdx.x >> 5);
    int lane = threadIdx.x & 31;
    if (w >= Bc) return;
    int r = j_ids[w];
    if (lane == 0) g_jmark[r] = 1;
    for (int p = g_ptr_j[r] + lane; p < g_ptr_j[r+1]; p += 32) g_smark[g_ccol_j[p]] = 1;
    int rs = s_ids[w];
    if (lane == 0) g_smark[rs] = 1;
    for (int p = g_ptr_s[rs] + lane; p < g_ptr_s[rs+1]; p += 32) g_jmark[g_ccol_s[p]] = 1;
}

__global__ void compact_kernel() {
    int i = blockIdx.x * blockDim.x + threadIdx.x;
    if (i < NJc && g_jmark[i]) {
        int p = atomicAdd(&g_jcnt_sel, 1);
        g_jlist[p] = i; g_jmap[i] = p;
    }
    if (i < NSc && g_smark[i]) {
        int p = atomicAdd(&g_scnt_sel, 1);
        g_slist[p] = i; g_smap[i] = p;
    }
}

// ---------------- fused row l2 normalize over up to 4 arrays ----------------
__global__ void l2norm4_kernel(const float4* s0, float4* d0, const float4* s1, float4* d1,
                               const float4* s2, float4* d2, const float4* s3, float4* d3,
                               int n) {
    const float4* src; float4* dst;
    switch (blockIdx.y) {
        case 0: src = s0; dst = d0; break;
        case 1: src = s1; dst = d1; break;
        case 2: src = s2; dst = d2; break;
        default: src = s3; dst = d3; break;
    }
    int w = (blockIdx.x * blockDim.x + threadIdx.x) >> 5;
    int lane = threadIdx.x & 31;
    if (w >= n) return;
    const float4* s = src + (size_t)w * D4c;
    float4 u0 = s[lane], u1 = s[lane + 32];
    float ss = u0.x*u0.x + u0.y*u0.y + u0.z*u0.z + u0.w*u0.w
             + u1.x*u1.x + u1.y*u1.y + u1.z*u1.z + u1.w*u1.w;
    #pragma unroll
    for (int o = 16; o; o >>= 1) ss += __shfl_xor_sync(0xffffffffu, ss, o);
    float inv = 1.f / fmaxf(sqrtf(ss), 1e-12f);
    float4* d = dst + (size_t)w * D4c;
    d[lane]      = make_float4(u0.x*inv, u0.y*inv, u0.z*inv, u0.w*inv);
    d[lane + 32] = make_float4(u1.x*inv, u1.y*inv, u1.z*inv, u1.w*inv);
}

// ---------------- SPMM row bodies ----------------
__device__ __forceinline__ void fma4(float4& acc, float v, const float4& u) {
    acc.x = fmaf(v, u.x, acc.x);
    acc.y = fmaf(v, u.y, acc.y);
    acc.z = fmaf(v, u.z, acc.z);
    acc.w = fmaf(v, u.w, acc.w);
}

__device__ __forceinline__ void spmm_row1(
    const int* __restrict__ ptr, const int* __restrict__ cols, const float* __restrict__ vals,
    const float4* __restrict__ X, float4* __restrict__ O, int src, int dst, int lane)
{
    int s = ptr[src], e = ptr[src + 1];
    float4 z = make_float4(0.f, 0.f, 0.f, 0.f);
    float4 a0 = z, a1 = z;
    int p = s;
    for (; p + 4 <= e; p += 4) {
        int c0 = cols[p], c1 = cols[p+1], c2 = cols[p+2], c3 = cols[p+3];
        float v0 = vals[p], v1 = vals[p+1], v2 = vals[p+2], v3 = vals[p+3];
        const float4* x0 = X + (size_t)c0 * D4c;
        const float4* x1 = X + (size_t)c1 * D4c;
        const float4* x2 = X + (size_t)c2 * D4c;
        const float4* x3 = X + (size_t)c3 * D4c;
        float4 p00 = x0[lane], p01 = x0[lane + 32];
        float4 p10 = x1[lane], p11 = x1[lane + 32];
        float4 p20 = x2[lane], p21 = x2[lane + 32];
        float4 p30 = x3[lane], p31 = x3[lane + 32];
        fma4(a0, v0, p00); fma4(a1, v0, p01);
        fma4(a0, v1, p10); fma4(a1, v1, p11);
        fma4(a0, v2, p20); fma4(a1, v2, p21);
        fma4(a0, v3, p30); fma4(a1, v3, p31);
    }
    for (; p < e; p++) {
        int c0 = cols[p]; float v0 = vals[p];
        const float4* x0 = X + (size_t)c0 * D4c;
        float4 p00 = x0[lane], p01 = x0[lane + 32];
        fma4(a0, v0, p00); fma4(a1, v0, p01);
    }
    O[(size_t)dst * D4c + lane] = a0;
    O[(size_t)dst * D4c + 32 + lane] = a1;
}

// single with column map on X (X stored compact, index via map[c])
__device__ __forceinline__ void spmm_row1m(
    const int* __restrict__ ptr, const int* __restrict__ cols, const float* __restrict__ vals,
    const float4* __restrict__ X, const int* __restrict__ map,
    float4* __restrict__ O, int src, int dst, int lane)
{
    int s = ptr[src], e = ptr[src + 1];
    float4 z = make_float4(0.f, 0.f, 0.f, 0.f);
    float4 a0 = z, a1 = z;
    for (int p = s; p < e; p++) {
        int c0 = map[cols[p]]; float v0 = vals[p];
        const float4* x0 = X + (size_t)c0 * D4c;
        float4 p00 = x0[lane], p01 = x0[lane + 32];
        fma4(a0, v0, p00); fma4(a1, v0, p01);
    }
    O[(size_t)dst * D4c + lane] = a0;
    O[(size_t)dst * D4c + 32 + lane] = a1;
}

// dual where X2 is compact with map
__device__ __forceinline__ void spmm_row2m(
    const int* __restrict__ ptr, const int* __restrict__ cols, const float* __restrict__ vals,
    const float4* __restrict__ X1, const float4* __restrict__ X2, const int* __restrict__ map2,
    float4* __restrict__ O1, float4* __restrict__ O2, int src, int dst, int lane)
{
    int s = ptr[src], e = ptr[src + 1];
    float4 z = make_float4(0.f, 0.f, 0.f, 0.f);
    float4 a0 = z, a1 = z, b0 = z, b1 = z;
    for (int p = s; p < e; p++) {
        int c0 = cols[p]; float v0 = vals[p];
        int c0m = map2[c0];
        const float4* x10 = X1 + (size_t)c0 * D4c;
        const float4* x20 = X2 + (size_t)c0m * D4c;
        float4 p0 = x10[lane], p1 = x10[lane + 32];
        float4 q0 = x20[lane], q1 = x20[lane + 32];
        fma4(a0, v0, p0); fma4(a1, v0, p1); fma4(b0, v0, q0); fma4(b1, v0, q1);
    }
    O1[(size_t)dst * D4c + lane] = a0; O1[(size_t)dst * D4c + 32 + lane] = a1;
    O2[(size_t)dst * D4c + lane] = b0; O2[(size_t)dst * D4c + 32 + lane] = b1;
}

// ---------------- E-path L1 SPMM, both sides in one launch ----------------
__global__ __launch_bounds__(256) void spmmE2_kernel(
    const float4* __restrict__ e_s_f, const float4* __restrict__ e_j_f)
{
    int w = blockIdx.x * 8 + (threadIdx.x >> 5);
    int lane = threadIdx.x & 31;
    if (w >= NJc) return;
    if (blockIdx.y == 0) spmm_row1(g_ptr_j, g_ccol_j, g_cval_j, e_s_f, (float4*)g_Tje, w, w, lane);
    else                 spmm_row1(g_ptr_s, g_ccol_s, g_cval_s, e_j_f, (float4*)g_Tse, w, w, lane);
}

// ---------------- G-path L1 SPMM on COMPACT rows, both sides ----------------
__global__ __launch_bounds__(256) void spmmG2_kernel(
    const float4* __restrict__ Gs0, const float4* __restrict__ Gj0)
{
    int w = blockIdx.x * 8 + (threadIdx.x >> 5);
    int lane = threadIdx.x & 31;
    if (blockIdx.y == 0) {
        if (w >= g_jcnt_sel) return;
        spmm_row1(g_ptr_j, g_ccol_j, g_cval_j, Gs0, (float4*)g_Tjg, g_jlist[w], w, lane);
    } else {
        if (w >= g_scnt_sel) return;
        spmm_row1(g_ptr_s, g_ccol_s, g_cval_s, Gj0, (float4*)g_Tsg, g_slist[w], w, lane);
    }
}

// ---------------- L2 full Tse2 = A_s^T @ Ej1 -> g_Tje buffer ----------------
__global__ __launch_bounds__(256) void spmmL2_tse_kernel(
    const float4* __restrict__ Ej, float4* __restrict__ Odst)
{
    int w = blockIdx.x * 8 + (threadIdx.x >> 5);
    int lane = threadIdx.x & 31;
    if (w >= NSc) return;
    spmm_row1(g_ptr_s, g_ccol_s, g_cval_s, Ej, Odst, w, w, lane);
}

// ---------------- L2 compacted selected rows (reads compact G1 via maps) ----------------
__global__ __launch_bounds__(256) void spmmL2_sel_kernel(
    const float4* __restrict__ Es, const float4* __restrict__ Gs1c, const float4* __restrict__ Gj1c,
    const int* __restrict__ j_ids, const int* __restrict__ s_ids)
{
    int gid = blockIdx.x;
    int warp = threadIdx.x >> 5;
    int lane = threadIdx.x & 31;
    if (gid < 128) {
        int i = gid * 8 + warp;
        int row = j_ids[i];
        spmm_row2m(g_ptr_j, g_ccol_j, g_cval_j, Es, Gs1c, g_smap,
                   (float4*)g_Tjec, (float4*)g_Tjgc, row, i, lane);
    } else {
        int i = (gid - 128) * 8 + warp;
        int row = s_ids[i];
        spmm_row1m(g_ptr_s, g_ccol_s, g_cval_s, Gj1c, g_jmap, (float4*)g_Tsgc, row, i, lane);
    }
}

// ---------------- GEMM core (double-buffered 128x128x16 NT) ----------------
__device__ __forceinline__ void gemm_core(
    const float* __restrict__ A, const float* __restrict__ W,
    int rowTile, int colTile, int M, float (&acc)[8][8],
    float (&As)[2][16][128], float (&Bs)[2][16][128])
{
    int tid = threadIdx.x;
    int tx = tid & 15, ty = tid >> 4;
    #pragma unroll
    for (int i = 0; i < 8; i++)
        #pragma unroll
        for (int j = 0; j < 8; j++) acc[i][j] = 0.f;

    int lrow = tid & 127;
    int khalf = (tid >> 7) * 8;
    const float* Ag = A + (size_t)(rowTile + lrow) * DIMc + khalf;
    const float* Wg = W + (size_t)(colTile + lrow) * DIMc + khalf;
    bool arow_ok = (rowTile + lrow) < M;
    const float4 z4 = make_float4(0.f, 0.f, 0.f, 0.f);

    float4 ra0 = arow_ok ? *(const float4*)(Ag + 0) : z4;
    float4 ra1 = arow_ok ? *(const float4*)(Ag + 4) : z4;
    float4 rb0 = *(const float4*)(Wg + 0);
    float4 rb1 = *(const float4*)(Wg + 4);
    As[0][khalf+0][lrow] = ra0.x; As[0][khalf+1][lrow] = ra0.y;
    As[0][khalf+2][lrow] = ra0.z; As[0][khalf+3][lrow] = ra0.w;
    As[0][khalf+4][lrow] = ra1.x; As[0][khalf+5][lrow] = ra1.y;
    As[0][khalf+6][lrow] = ra1.z; As[0][khalf+7][lrow] = ra1.w;
    Bs[0][khalf+0][lrow] = rb0.x; Bs[0][khalf+1][lrow] = rb0.y;
    Bs[0][khalf+2][lrow] = rb0.z; Bs[0][khalf+3][lrow] = rb0.w;
    Bs[0][khalf+4][lrow] = rb1.x; Bs[0][khalf+5][lrow] = rb1.y;
    Bs[0][khalf+6][lrow] = rb1.z; Bs[0][khalf+7][lrow] = rb1.w;
    __syncthreads();

    int buf = 0;
    for (int k0 = 16; k0 <= DIMc; k0 += 16) {
        bool more = k0 < DIMc;
        if (more) {
            ra0 = arow_ok ? *(const float4*)(Ag + k0) : z4;
            ra1 = arow_ok ? *(const float4*)(Ag + k0 + 4) : z4;
            rb0 = *(const float4*)(Wg + k0);
            rb1 = *(const float4*)(Wg + k0 + 4);
        }
        #pragma unroll
        for (int kk = 0; kk < 16; kk++) {
            float a[8], b[8];
            #pragma unroll
            for (int i = 0; i < 4; i++) {
                a[i]   = As[buf][kk][ty*4 + i];
                a[i+4] = As[buf][kk][ty*4 + i + 64];
                b[i]   = Bs[buf][kk][tx*4 + i];
                b[i+4] = Bs[buf][kk][tx*4 + i + 64];
            }
            #pragma unroll
            for (int i = 0; i < 8; i++)
                #pragma unroll
                for (int j = 0; j < 8; j++)
                    acc[i][j] = fmaf(a[i], b[j], acc[i][j]);
        }
        if (more) {
            int nb = buf ^ 1;
            As[nb][khalf+0][lrow] = ra0.x; As[nb][khalf+1][lrow] = ra0.y;
            As[nb][khalf+2][lrow] = ra0.z; As[nb][khalf+3][lrow] = ra0.w;
            As[nb][khalf+4][lrow] = ra1.x; As[nb][khalf+5][lrow] = ra1.y;
            As[nb][khalf+6][lrow] = ra1.z; As[nb][khalf+7][lrow] = ra1.w;
            Bs[nb][khalf+0][lrow] = rb0.x; Bs[nb][khalf+1][lrow] = rb0.y;
            Bs[nb][khalf+2][lrow] = rb0.z; Bs[nb][khalf+3][lrow] = rb0.w;
            Bs[nb][khalf+4][lrow] = rb1.x; Bs[nb][khalf+5][lrow] = rb1.y;
            Bs[nb][khalf+6][lrow] = rb1.z; Bs[nb][khalf+7][lrow] = rb1.w;
            __syncthreads();
            buf = nb;
        }
    }
}

// full-row GEMM with update epilogue: nv = old + relu(C); wout write; smode 0/1/2
__global__ __launch_bounds__(256, 2) void gemm_update_kernel(
    const float* __restrict__ A, const float* __restrict__ W,
    const float* __restrict__ oldv, float* __restrict__ outv, float* __restrict__ sumv,
    int M, int wout, int smode)
{
    __shared__ float As[2][16][128];
    __shared__ float Bs[2][16][128];
    float acc[8][8];
    int rowTile = blockIdx.y * 128, colTile = blockIdx.x * 128;
    gemm_core(A, W, rowTile, colTile, M, acc, As, Bs);
    int tid = threadIdx.x, tx = tid & 15, ty = tid >> 4;
    #pragma unroll
    for (int i = 0; i < 8; i++) {
        int gr = rowTile + ty*4 + (i & 3) + ((i >> 2) * 64);
        if (gr < M) {
            #pragma unroll
            for (int j = 0; j < 8; j++) {
                int gc = colTile + tx*4 + (j & 3) + ((j >> 2) * 64);
                size_t idx = (size_t)gr * DIMc + gc;
                float v = fmaxf(acc[i][j], 0.f);
                float o = oldv[idx];
                float nv = o + v;
                if (wout) outv[idx] = nv;
                if (smode == 1) sumv[idx] = o + nv;
                else if (smode == 2) sumv[idx] = sumv[idx] + nv;
            }
        }
    }
}

// compact G1 GEMM: rows compact; oldv indexed by orig id via list; out compact; count on device
__global__ __launch_bounds__(256, 2) void gemm_gc_kernel(
    const float* __restrict__ A, const float* __restrict__ W,
    const float* __restrict__ oldv, float* __restrict__ outv, int side)
{
    int M = side ? g_scnt_sel : g_jcnt_sel;
    const int* list = side ? g_slist : g_jlist;
    int rowTile = blockIdx.y * 128;
    if (rowTile >= M) return;
    __shared__ float As[2][16][128];
    __shared__ float Bs[2][16][128];
    float acc[8][8];
    int colTile = blockIdx.x * 128;
    gemm_core(A, W, rowTile, colTile, M, acc, As, Bs);
    int tid = threadIdx.x, tx = tid & 15, ty = tid >> 4;
    #pragma unroll
    for (int i = 0; i < 8; i++) {
        int gr = rowTile + ty*4 + (i & 3) + ((i >> 2) * 64);
        if (gr < M) {
            int orig = list[gr];
            #pragma unroll
            for (int j = 0; j < 8; j++) {
                int gc = colTile + tx*4 + (j & 3) + ((j >> 2) * 64);
                float v = fmaxf(acc[i][j], 0.f);
                outv[(size_t)gr * DIMc + gc] = oldv[(size_t)orig * DIMc + gc] + v;
            }
        }
    }
}

// selected GEMM: dst[i,:] = base0[ids[i]] + 2*base1[map? map[ids[i]] : ids[i]] + relu(Ac@W^T)
__global__ __launch_bounds__(256, 2) void gemm_sel_kernel(
    const float* __restrict__ e_j_f,
    const float* __restrict__ Wj2, const float* __restrict__ Wja2, const float* __restrict__ Wsa2,
    const int* __restrict__ j_ids, const int* __restrict__ s_ids)
{
    __shared__ float As[2][16][128];
    __shared__ float Bs[2][16][128];
    const float* A; const float* W; const float* base0; const float* base1;
    const int* map1; float* dst; const int* ids;
    switch (blockIdx.z) {
        case 0: A = g_Tjec; W = Wj2;  base0 = e_j_f; base1 = g_Ej;  map1 = 0;      dst = g_ejsel; ids = j_ids; break;
        case 1: A = g_Tjgc; W = Wja2; base0 = g_Gj;  base1 = g_Gj1; map1 = g_jmap; dst = g_gjsel; ids = j_ids; break;
        default: A = g_Tsgc; W = Wsa2; base0 = g_Gs; base1 = g_Gs1; map1 = g_smap; dst = g_gssel; ids = s_ids; break;
    }
    float acc[8][8];
    int rowTile = blockIdx.y * 128, colTile = blockIdx.x * 128;
    gemm_core(A, W, rowTile, colTile, Bc, acc, As, Bs);
    int tid = threadIdx.x, tx = tid & 15, ty = tid >> 4;
    #pragma unroll
    for (int i = 0; i < 8; i++) {
        int gr = rowTile + ty*4 + (i & 3) + ((i >> 2) * 64);
        int id = ids[gr];
        int id1 = map1 ? map1[id] : id;
        #pragma unroll
        for (int j = 0; j < 8; j++) {
            int gc = colTile + tx*4 + (j & 3) + ((j >> 2) * 64);
            float v = fmaxf(acc[i][j], 0.f);
            dst[(size_t)gr * DIMc + gc] =
                base0[(size_t)id * DIMc + gc] + 2.f * base1[(size_t)id1 * DIMc + gc] + v;
        }
    }
}

// ---------------- GEMM + exp + per-(row,group) sum ----------------
__global__ __launch_bounds__(256, 2) void expsum_kernel(
    const float* __restrict__ A, const float* __restrict__ Bm,
    float* __restrict__ sumexp, int ngroups)
{
    __shared__ float As[2][16][128];
    __shared__ float Bs[2][16][128];
    __shared__ float red[128];
    float acc[8][8];
    int rowTile = blockIdx.y * 128, colTile = blockIdx.x * 128;
    gemm_core(A, Bm, rowTile, colTile, 1 << 30, acc, As, Bs);
    int tid = threadIdx.x, tx = tid & 15, ty = tid >> 4;
    float rsum[8];
    #pragma unroll
    for (int i = 0; i < 8; i++) {
        rsum[i] = 0.f;
        #pragma unroll
        for (int j = 0; j < 8; j++) rsum[i] += expf(acc[i][j] * 5.0f);  // 1/TEMP = 5
    }
    if (tid < 128) red[tid] = 0.f;
    __syncthreads();
    #pragma unroll
    for (int i = 0; i < 8; i++) {
        int r = ty*4 + (i & 3) + ((i >> 2) * 64);
        atomicAdd(&red[r], rsum[i]);
    }
    __syncthreads();
    if (tid < 128) {
        int gr = rowTile + tid;
        int group = blockIdx.x >> 3;
        atomicAdd(&sumexp[(size_t)gr * ngroups + group], red[tid]);
    }
}

// ---------------- combined gather: negemb + essel ----------------
__global__ void gatherNE_kernel(const int* __restrict__ negs, const int* __restrict__ s_ids) {
    int row = blockIdx.x;
    const float4* src = (const float4*)g_sEs;
    if (row < NEGRc) {
        int id = negs[row];
        ((float4*)g_negemb)[(size_t)row * D4c + threadIdx.x] = src[(size_t)id * D4c + threadIdx.x];
    } else {
        int r = row - NEGRc;
        int id = s_ids[r];
        ((float4*)g_essel)[(size_t)r * D4c + threadIdx.x] = src[(size_t)id * D4c + threadIdx.x];
    }
}

// ---------------- pos score ----------------
__global__ void pos_kernel() {
    int w = (blockIdx.x * blockDim.x + threadIdx.x) >> 5;
    int lane = threadIdx.x & 31;
    if (w >= Bc) return;
    const float4* gj = (const float4*)g_gjsel + (size_t)w * D4c;
    const float4* ej = (const float4*)g_ejsel + (size_t)w * D4c;
    const float4* gs = (const float4*)g_gssel + (size_t)w * D4c;
    const float4* es = (const float4*)g_essel + (size_t)w * D4c;
    float4 a0 = gj[lane], a1 = gj[lane+32], b0 = ej[lane], b1 = ej[lane+32];
    float4 c0 = gs[lane], c1 = gs[lane+32], d0 = es[lane], d1 = es[lane+32];
    float s1 = a0.x*b0.x + a0.y*b0.y + a0.z*b0.z + a0.w*b0.w
             + a1.x*b1.x + a1.y*b1.y + a1.z*b1.z + a1.w*b1.w;
    float s2 = c0.x*d0.x + c0.y*d0.y + c0.z*d0.z + c0.w*d0.w
             + c1.x*d1.x + c1.y*d1.y + c1.z*d1.z + c1.w*d1.w;
    #pragma unroll
    for (int o = 16; o; o >>= 1) {
        s1 += __shfl_xor_sync(0xffffffffu, s1, o);
        s2 += __shfl_xor_sync(0xffffffffu, s2, o);
    }
    if (lane == 0) {
        float c1v = fminf(fmaxf(s1 * 5.0f, -1.f), 1.f);
        float c2v = fminf(fmaxf(s2 * 5.0f, -1.f), 1.f);
        atomicAdd(&g_scalars[0], c1v);
        atomicAdd(&g_scalars[1], c2v);
    }
}

// ---------------- weight L2 regularizer ----------------
__global__ void wsq_kernel(const float* __restrict__ a, const float* __restrict__ b,
                           const float* __restrict__ c, const float* __restrict__ d) {
    float s = 0.f;
    for (int i = blockIdx.x * blockDim.x + threadIdx.x; i < WSZc; i += gridDim.x * blockDim.x) {
        float x;
        x = a[i]; s += x * x;
        x = b[i]; s += x * x;
        x = c[i]; s += x * x;
        x = d[i]; s += x * x;
    }
    #pragma unroll
    for (int o = 16; o; o >>= 1) s += __shfl_xor_sync(0xffffffffu, s, o);
    __shared__ float sh[8];
    int lane = threadIdx.x & 31, wid = threadIdx.x >> 5;
    if (lane == 0) sh[wid] = s;
    __syncthreads();
    if (threadIdx.x == 0) {
        float t = 0.f;
        for (int i = 0; i < (int)(blockDim.x >> 5); i++) t += sh[i];
        atomicAdd(&g_scalars[2], t);
    }
}

// ---------------- finalize ----------------
__device__ double blk_reduce_1024(double v) {
    __shared__ double sh[32];
    __syncthreads();
    int lane = threadIdx.x & 31, wid = threadIdx.x >> 5;
    #pragma unroll
    for (int o = 16; o; o >>= 1) v += __shfl_down_sync(0xffffffffu, v, o);
    if (lane == 0) sh[wid] = v;
    __syncthreads();
    v = (threadIdx.x < 32) ? sh[threadIdx.x] : 0.0;
    if (wid == 0) {
        #pragma unroll
        for (int o = 16; o; o >>= 1) v += __shfl_down_sync(0xffffffffu, v, o);
    }
    return v;
}

__global__ void finalize_kernel(float* __restrict__ out) {
    int tid = threadIdx.x;
    double a = (tid < Bc) ? log((double)g_sumexp_j[tid] + 1e-8) : 0.0;
    double negj = blk_reduce_1024(a);
    double b = 0.0;
    for (int i = tid; i < Bc * NNEGc; i += 1024)
        b += log((double)g_sumexp_s[i] + 1e-8);
    double negs = blk_reduce_1024(b);
    if (tid == 0) {
        double pos = (double)g_scalars[0] / Bc + (double)g_scalars[1] / Bc;
        double neg = negj / Bc + negs / (double)(Bc * NNEGc);
        double cl = (-pos + neg) * 0.2;
        double reg = 1e-4 * (double)g_scalars[2];
        out[0] = (float)(cl + reg);
        out[1] = (float)cl;
        out[2] = (float)reg;
    }
}

// ---------------- launch ----------------
#define SYM(p, s) do { void* _t = 0; cudaGetSymbolAddress(&_t, s); p = (decltype(p))_t; } while (0)

extern "C" void kernel_launch(void* const* d_in, const int* in_sizes, int n_in,
                              void* d_out, int out_size) {
    (void)in_sizes; (void)n_in; (void)out_size;
    const float* e_j_f   = (const float*)d_in[0];
    const float* e_s_f   = (const float*)d_in[1];
    const float* aug_e_j = (const float*)d_in[2];
    const float* aug_e_s = (const float*)d_in[3];
    const float* val_j   = (const float*)d_in[4];
    const float* val_s   = (const float*)d_in[5];
    const float* W_j     = (const float*)d_in[6];
    const float* W_s     = (const float*)d_in[7];
    const float* W_j_aug = (const float*)d_in[8];
    const float* W_s_aug = (const float*)d_in[9];
    const int* row_j = (const int*)d_in[10];
    const int* col_j = (const int*)d_in[11];
    const int* row_s = (const int*)d_in[12];
    const int* col_s = (const int*)d_in[13];
    const int* j_ids = (const int*)d_in[14];
    const int* s_ids = (const int*)d_in[15];
    const int* negs  = (const int*)d_in[16];
    float* out = (float*)d_out;

    float *Ej, *Es, *Gj, *Gs, *Gj1, *Gs1, *sEs, *Tje, *Tjg, *Tse, *Tsg;
    float *gjsel, *ejsel, *gssel, *negemb, *sumexp_j, *sumexp_s;
    SYM(Ej, g_Ej); SYM(Es, g_Es); SYM(Gj, g_Gj); SYM(Gs, g_Gs);
    SYM(Gj1, g_Gj1); SYM(Gs1, g_Gs1); SYM(sEs, g_sEs);
    SYM(Tje, g_Tje); SYM(Tjg, g_Tjg); SYM(Tse, g_Tse); SYM(Tsg, g_Tsg);
    SYM(gjsel, g_gjsel); SYM(ejsel, g_ejsel); SYM(gssel, g_gssel);
    SYM(negemb, g_negemb); SYM(sumexp_j, g_sumexp_j); SYM(sumexp_s, g_sumexp_s);

    static int inited = 0;
    static cudaStream_t s1;
    static cudaEvent_t evStart, evL2n, evCsr, evGspmm, evEj, evTse, evG, evSel, evGat, evLoss;
    if (!inited) {
        cudaStreamCreateWithFlags(&s1, cudaStreamNonBlocking);
        cudaEventCreateWithFlags(&evStart, cudaEventDisableTiming);
        cudaEventCreateWithFlags(&evL2n,   cudaEventDisableTiming);
        cudaEventCreateWithFlags(&evCsr,   cudaEventDisableTiming);
        cudaEventCreateWithFlags(&evGspmm, cudaEventDisableTiming);
        cudaEventCreateWithFlags(&evEj,    cudaEventDisableTiming);
        cudaEventCreateWithFlags(&evTse,   cudaEventDisableTiming);
        cudaEventCreateWithFlags(&evG,     cudaEventDisableTiming);
        cudaEventCreateWithFlags(&evSel,   cudaEventDisableTiming);
        cudaEventCreateWithFlags(&evGat,   cudaEventDisableTiming);
        cudaEventCreateWithFlags(&evLoss,  cudaEventDisableTiming);
        inited = 1;
    }

    const int EB = (Ec + 255) / 256;         // 6250
    const int RB = 6250;

    zero_kernel<<<256, 256>>>();
    cudaEventRecord(evStart, 0);
    cudaStreamWaitEvent(s1, evStart, 0);

    // side: initial l2norm + wsq
    {
        dim3 g(RB, 2);
        l2norm4_kernel<<<g, 256, 0, s1>>>((const float4*)aug_e_j, (float4*)Gj,
                                          (const float4*)aug_e_s, (float4*)Gs,
                                          (const float4*)aug_e_j, (float4*)Gj,
                                          (const float4*)aug_e_s, (float4*)Gs, NJc);
        wsq_kernel<<<256, 256, 0, s1>>>(W_j, W_s, W_j_aug, W_s_aug);
        cudaEventRecord(evL2n, s1);
    }
    // default: CSR build
    count_kernel<<<EB, 256>>>(row_j, col_s);
    scan2_kernel<<<2, 1024>>>();
    scatter_kernel<<<EB, 256>>>(row_j, col_j, val_j, row_s, col_s, val_s);
    cudaEventRecord(evCsr, 0);

    // side: mark neighbor sets + compact + compact G SPMMs (needs CSR + Gj/Gs from l2norm)
    cudaStreamWaitEvent(s1, evCsr, 0);
    mark_kernel<<<128, 256, 0, s1>>>(j_ids, s_ids);
    compact_kernel<<<(NJc + 255) / 256, 256, 0, s1>>>();
    {
        dim3 gg(RB, 2);
        spmmG2_kernel<<<gg, 256, 0, s1>>>((const float4*)Gs, (const float4*)Gj);
    }
    cudaEventRecord(evGspmm, s1);

    // default: E-path L1 SPMM (both sides)
    cudaStreamWaitEvent(0, evL2n, 0);
    {
        dim3 sg(RB, 2);
        spmmE2_kernel<<<sg, 256>>>((const float4*)e_s_f, (const float4*)e_j_f);
    }
    dim3 gemm_grid(2, 391);
    gemm_update_kernel<<<gemm_grid, 256>>>(Tje, W_j, e_j_f, Ej, (float*)0, NJc, 1, 0);
    cudaEventRecord(evEj, 0);

    // side: full Tse2 SPMM into freed g_Tje
    cudaStreamWaitEvent(s1, evEj, 0);
    spmmL2_tse_kernel<<<RB, 256, 0, s1>>>((const float4*)Ej, (float4*)Tje);
    cudaEventRecord(evTse, s1);

    // default: Es GEMM (+sum), then compact G1 GEMMs
    gemm_update_kernel<<<gemm_grid, 256>>>(Tse, W_s, e_s_f, Es, sEs, NSc, 1, 1);
    cudaStreamWaitEvent(0, evGspmm, 0);
    gemm_gc_kernel<<<gemm_grid, 256>>>(Tjg, W_j_aug, Gj, Gj1, 0);
    gemm_gc_kernel<<<gemm_grid, 256>>>(Tsg, W_s_aug, Gs, Gs1, 1);
    cudaEventRecord(evG, 0);

    // side: compacted selected chain
    cudaStreamWaitEvent(s1, evG, 0);
    spmmL2_sel_kernel<<<256, 256, 0, s1>>>((const float4*)Es, (const float4*)Gs1,
                                           (const float4*)Gj1, j_ids, s_ids);
    {
        dim3 sg(2, 8, 3);
        gemm_sel_kernel<<<sg, 256, 0, s1>>>(e_j_f, W_j + DIMc*DIMc, W_j_aug + DIMc*DIMc,
                                            W_s_aug + DIMc*DIMc, j_ids, s_ids);
    }
    l2norm4_kernel<<<dim3(128, 3), 256, 0, s1>>>(
        (const float4*)ejsel, (float4*)ejsel,
        (const float4*)gjsel, (float4*)gjsel,
        (const float4*)gssel, (float4*)gssel,
        (const float4*)gssel, (float4*)gssel, Bc);
    cudaEventRecord(evSel, s1);

    // default: full Es L2 chain
    cudaStreamWaitEvent(0, evTse, 0);
    gemm_update_kernel<<<gemm_grid, 256>>>(Tje, W_s + DIMc*DIMc, Es, (float*)0, sEs, NSc, 0, 2);
    l2norm4_kernel<<<dim3(RB, 1), 256>>>((const float4*)sEs, (float4*)sEs,
                                         (const float4*)sEs, (float4*)sEs,
                                         (const float4*)sEs, (float4*)sEs,
                                         (const float4*)sEs, (float4*)sEs, NSc);
    gatherNE_kernel<<<NEGRc + Bc, 64>>>(negs, s_ids);
    cudaEventRecord(evGat, 0);

    // side: small losses
    cudaStreamWaitEvent(s1, evGat, 0);
    {
        dim3 lg(Bc / 128, Bc / 128);
        expsum_kernel<<<lg, 256, 0, s1>>>(gjsel, ejsel, sumexp_j, 1);
        pos_kernel<<<Bc / 8, 256, 0, s1>>>();
        cudaEventRecord(evLoss, s1);
    }
    // default: big expsum
    cudaStreamWaitEvent(0, evSel, 0);
    {
        dim3 ng(NEGRc / 128, Bc / 128);
        expsum_kernel<<<ng, 256>>>(gssel, negemb, sumexp_s, NNEGc);
    }
    cudaStreamWaitEvent(0, evLoss, 0);
    finalize_kernel<<<1, 1024>>>(out);
}

// round 15
// speedup vs baseline: 1.9809x; 1.0547x over previous
#include <cuda_runtime.h>
#include <math.h>

#define NJc 50000
#define NSc 50000
#define Ec  1600000
#define DIMc 256
#define D4c  64
#define Lc   2
#define Bc   1024
#define NNEGc 32
#define NEGRc (NNEGc*Bc)
#define WSZc (Lc*DIMc*DIMc)

// ---------------- scratch (device globals; no allocation allowed) ----------------
__device__ float g_Ej[NJc*DIMc];
__device__ float g_Es[NSc*DIMc];
__device__ float g_Gj[NJc*DIMc];      // layer-0 G_j (preserved)
__device__ float g_Gs[NSc*DIMc];      // layer-0 G_s (preserved)
__device__ float g_Gj1[NJc*DIMc];     // layer-1 G_j, COMPACT rows (jlist order)
__device__ float g_Gs1[NSc*DIMc];     // layer-1 G_s, COMPACT rows (slist order)
__device__ float g_sEs[NSc*DIMc];     // layer-1 partial sum E0+E1 (full rows)
__device__ float g_Tje[NJc*DIMc];
__device__ float g_Tjg[NJc*DIMc];     // compact G SPMM out (j side)
__device__ float g_Tse[NSc*DIMc];     // L1 s-side SPMM; later compact final sEs
__device__ float g_Tsg[NSc*DIMc];     // compact G SPMM out (s side)
__device__ float g_Tjec[Bc*DIMc];
__device__ float g_Tjgc[Bc*DIMc];
__device__ float g_Tsgc[Bc*DIMc];
__device__ int   g_cnt_j[NJc];
__device__ int   g_cnt_s[NSc];
__device__ int   g_ptr_j[NJc+1];
__device__ int   g_ptr_s[NSc+1];
__device__ int   g_cur_j[NJc];
__device__ int   g_cur_s[NSc];
__device__ int   g_ccol_j[Ec];
__device__ float g_cval_j[Ec];
__device__ int   g_ccol_s[Ec];
__device__ float g_cval_s[Ec];
// neighbor-set machinery
__device__ int   g_jmark[NJc];
__device__ int   g_smark[NSc];
__device__ int   g_nmark[NSc];        // negs ∪ s_ids
__device__ int   g_jlist[NJc];
__device__ int   g_slist[NSc];
__device__ int   g_nlist[NSc];
__device__ int   g_jmap[NJc];
__device__ int   g_smap[NSc];
__device__ int   g_nmap[NSc];
__device__ int   g_jcnt_sel;
__device__ int   g_scnt_sel;
__device__ int   g_ncnt_sel;
__device__ float g_gjsel[Bc*DIMc];
__device__ float g_ejsel[Bc*DIMc];
__device__ float g_gssel[Bc*DIMc];
__device__ float g_essel[Bc*DIMc];
__device__ float g_negemb[NEGRc*DIMc];
__device__ float g_sumexp_j[Bc];
__device__ float g_sumexp_s[Bc*NNEGc];
__device__ float g_scalars[8];   // [0]=pos_j sum, [1]=pos_s sum, [2]=wsq

// ---------------- small utility kernels ----------------
__global__ void zero_kernel() {
    int i = blockIdx.x * blockDim.x + threadIdx.x;
    int st = gridDim.x * blockDim.x;
    for (int k = i; k < NJc; k += st) { g_cnt_j[k] = 0; g_jmark[k] = 0; }
    for (int k = i; k < NSc; k += st) { g_cnt_s[k] = 0; g_smark[k] = 0; g_nmark[k] = 0; }
    for (int k = i; k < Bc; k += st) g_sumexp_j[k] = 0.f;
    for (int k = i; k < Bc*NNEGc; k += st) g_sumexp_s[k] = 0.f;
    if (i < 8) g_scalars[i] = 0.f;
    if (i == 8) { g_jcnt_sel = 0; g_scnt_sel = 0; g_ncnt_sel = 0; }
}

__global__ void mark_neg_kernel(const int* __restrict__ negs, const int* __restrict__ s_ids) {
    int i = blockIdx.x * blockDim.x + threadIdx.x;
    if (i < NEGRc) g_nmark[negs[i]] = 1;
    else if (i < NEGRc + Bc) g_nmark[s_ids[i - NEGRc]] = 1;
}

__global__ void count_kernel(const int* __restrict__ row_j, const int* __restrict__ col_s) {
    int i = blockIdx.x * blockDim.x + threadIdx.x;
    if (i < Ec) {
        atomicAdd(&g_cnt_j[row_j[i]], 1);
        atomicAdd(&g_cnt_s[col_s[i]], 1);
    }
}

__global__ void scan2_kernel() {
    const int* cnt = blockIdx.x ? g_cnt_s : g_cnt_j;
    int* ptr = blockIdx.x ? g_ptr_s : g_ptr_j;
    int* cur = blockIdx.x ? g_cur_s : g_cur_j;
    int n = blockIdx.x ? NSc : NJc;
    __shared__ int warp_sums[32];
    __shared__ int s_carry;
    int tid = threadIdx.x;
    if (tid == 0) { s_carry = 0; ptr[0] = 0; }
    __syncthreads();
    for (int base = 0; base < n; base += 1024) {
        int i = base + tid;
        int v = (i < n) ? cnt[i] : 0;
        int inc = v;
        #pragma unroll
        for (int off = 1; off < 32; off <<= 1) {
            int t = __shfl_up_sync(0xffffffffu, inc, off);
            if ((tid & 31) >= off) inc += t;
        }
        if ((tid & 31) == 31) warp_sums[tid >> 5] = inc;
        __syncthreads();
        if (tid < 32) {
            int ws = warp_sums[tid];
            int wi = ws;
            #pragma unroll
            for (int off = 1; off < 32; off <<= 1) {
                int t = __shfl_up_sync(0xffffffffu, wi, off);
                if (tid >= off) wi += t;
            }
            warp_sums[tid] = wi - ws;
        }
        __syncthreads();
        int excl = inc - v + warp_sums[tid >> 5];
        int carry = s_carry;
        if (i < n) {
            int start = carry + excl;
            cur[i] = start;
            ptr[i + 1] = start + v;
        }
        __syncthreads();
        if (tid == 1023) s_carry = carry + excl + v;
        __syncthreads();
    }
}

__global__ void scatter_kernel(const int* __restrict__ row_j, const int* __restrict__ col_j,
                               const float* __restrict__ val_j,
                               const int* __restrict__ row_s, const int* __restrict__ col_s,
                               const float* __restrict__ val_s) {
    int i = blockIdx.x * blockDim.x + threadIdx.x;
    if (i >= Ec) return;
    int p = atomicAdd(&g_cur_j[row_j[i]], 1);
    g_ccol_j[p] = col_j[i]; g_cval_j[p] = val_j[i];
    int q = atomicAdd(&g_cur_s[col_s[i]], 1);
    g_ccol_s[q] = row_s[i]; g_cval_s[q] = val_s[i];
}

// mark neighbor sets: Sset = N(j_ids) via CSR_j cols + s_ids; Jset = N(s_ids) via CSR_s + j_ids
__global__ void mark_kernel(const int* __restrict__ j_ids, const int* __restrict__ s_ids) {
    int w = blockIdx.x * (blockDim.x >> 5) + (threadIdx.x >> 5);
    int lane = threadIdx.x & 31;
    if (w >= Bc) return;
    int r = j_ids[w];
    if (lane == 0) g_jmark[r] = 1;
    for (int p = g_ptr_j[r] + lane; p < g_ptr_j[r+1]; p += 32) g_smark[g_ccol_j[p]] = 1;
    int rs = s_ids[w];
    if (lane == 0) g_smark[rs] = 1;
    for (int p = g_ptr_s[rs] + lane; p < g_ptr_s[rs+1]; p += 32) g_jmark[g_ccol_s[p]] = 1;
}

__global__ void compact_kernel() {
    int i = blockIdx.x * blockDim.x + threadIdx.x;
    if (i < NJc && g_jmark[i]) {
        int p = atomicAdd(&g_jcnt_sel, 1);
        g_jlist[p] = i; g_jmap[i] = p;
    }
    if (i < NSc && g_smark[i]) {
        int p = atomicAdd(&g_scnt_sel, 1);
        g_slist[p] = i; g_smap[i] = p;
    }
    if (i < NSc && g_nmark[i]) {
        int p = atomicAdd(&g_ncnt_sel, 1);
        g_nlist[p] = i; g_nmap[i] = p;
    }
}

// ---------------- fused row l2 normalize over up to 4 arrays ----------------
__global__ void l2norm4_kernel(const float4* s0, float4* d0, const float4* s1, float4* d1,
                               const float4* s2, float4* d2, const float4* s3, float4* d3,
                               int n) {
    const float4* src; float4* dst;
    switch (blockIdx.y) {
        case 0: src = s0; dst = d0; break;
        case 1: src = s1; dst = d1; break;
        case 2: src = s2; dst = d2; break;
        default: src = s3; dst = d3; break;
    }
    int w = (blockIdx.x * blockDim.x + threadIdx.x) >> 5;
    int lane = threadIdx.x & 31;
    if (w >= n) return;
    const float4* s = src + (size_t)w * D4c;
    float4 u0 = s[lane], u1 = s[lane + 32];
    float ss = u0.x*u0.x + u0.y*u0.y + u0.z*u0.z + u0.w*u0.w
             + u1.x*u1.x + u1.y*u1.y + u1.z*u1.z + u1.w*u1.w;
    #pragma unroll
    for (int o = 16; o; o >>= 1) ss += __shfl_xor_sync(0xffffffffu, ss, o);
    float inv = 1.f / fmaxf(sqrtf(ss), 1e-12f);
    float4* d = dst + (size_t)w * D4c;
    d[lane]      = make_float4(u0.x*inv, u0.y*inv, u0.z*inv, u0.w*inv);
    d[lane + 32] = make_float4(u1.x*inv, u1.y*inv, u1.z*inv, u1.w*inv);
}

// compact in-place l2norm on g_Tse rows [0, g_ncnt_sel)
__global__ void l2normC_kernel() {
    int w = (blockIdx.x * blockDim.x + threadIdx.x) >> 5;
    int lane = threadIdx.x & 31;
    if (w >= g_ncnt_sel) return;
    float4* s = (float4*)g_Tse + (size_t)w * D4c;
    float4 u0 = s[lane], u1 = s[lane + 32];
    float ss = u0.x*u0.x + u0.y*u0.y + u0.z*u0.z + u0.w*u0.w
             + u1.x*u1.x + u1.y*u1.y + u1.z*u1.z + u1.w*u1.w;
    #pragma unroll
    for (int o = 16; o; o >>= 1) ss += __shfl_xor_sync(0xffffffffu, ss, o);
    float inv = 1.f / fmaxf(sqrtf(ss), 1e-12f);
    s[lane]      = make_float4(u0.x*inv, u0.y*inv, u0.z*inv, u0.w*inv);
    s[lane + 32] = make_float4(u1.x*inv, u1.y*inv, u1.z*inv, u1.w*inv);
}

// ---------------- SPMM row bodies ----------------
__device__ __forceinline__ void fma4(float4& acc, float v, const float4& u) {
    acc.x = fmaf(v, u.x, acc.x);
    acc.y = fmaf(v, u.y, acc.y);
    acc.z = fmaf(v, u.z, acc.z);
    acc.w = fmaf(v, u.w, acc.w);
}

__device__ __forceinline__ void spmm_row1(
    const int* __restrict__ ptr, const int* __restrict__ cols, const float* __restrict__ vals,
    const float4* __restrict__ X, float4* __restrict__ O, int src, int dst, int lane)
{
    int s = ptr[src], e = ptr[src + 1];
    float4 z = make_float4(0.f, 0.f, 0.f, 0.f);
    float4 a0 = z, a1 = z;
    int p = s;
    for (; p + 4 <= e; p += 4) {
        int c0 = cols[p], c1 = cols[p+1], c2 = cols[p+2], c3 = cols[p+3];
        float v0 = vals[p], v1 = vals[p+1], v2 = vals[p+2], v3 = vals[p+3];
        const float4* x0 = X + (size_t)c0 * D4c;
        const float4* x1 = X + (size_t)c1 * D4c;
        const float4* x2 = X + (size_t)c2 * D4c;
        const float4* x3 = X + (size_t)c3 * D4c;
        float4 p00 = x0[lane], p01 = x0[lane + 32];
        float4 p10 = x1[lane], p11 = x1[lane + 32];
        float4 p20 = x2[lane], p21 = x2[lane + 32];
        float4 p30 = x3[lane], p31 = x3[lane + 32];
        fma4(a0, v0, p00); fma4(a1, v0, p01);
        fma4(a0, v1, p10); fma4(a1, v1, p11);
        fma4(a0, v2, p20); fma4(a1, v2, p21);
        fma4(a0, v3, p30); fma4(a1, v3, p31);
    }
    for (; p < e; p++) {
        int c0 = cols[p]; float v0 = vals[p];
        const float4* x0 = X + (size_t)c0 * D4c;
        float4 p00 = x0[lane], p01 = x0[lane + 32];
        fma4(a0, v0, p00); fma4(a1, v0, p01);
    }
    O[(size_t)dst * D4c + lane] = a0;
    O[(size_t)dst * D4c + 32 + lane] = a1;
}

__device__ __forceinline__ void spmm_row1m(
    const int* __restrict__ ptr, const int* __restrict__ cols, const float* __restrict__ vals,
    const float4* __restrict__ X, const int* __restrict__ map,
    float4* __restrict__ O, int src, int dst, int lane)
{
    int s = ptr[src], e = ptr[src + 1];
    float4 z = make_float4(0.f, 0.f, 0.f, 0.f);
    float4 a0 = z, a1 = z;
    for (int p = s; p < e; p++) {
        int c0 = map[cols[p]]; float v0 = vals[p];
        const float4* x0 = X + (size_t)c0 * D4c;
        float4 p00 = x0[lane], p01 = x0[lane + 32];
        fma4(a0, v0, p00); fma4(a1, v0, p01);
    }
    O[(size_t)dst * D4c + lane] = a0;
    O[(size_t)dst * D4c + 32 + lane] = a1;
}

__device__ __forceinline__ void spmm_row2m(
    const int* __restrict__ ptr, const int* __restrict__ cols, const float* __restrict__ vals,
    const float4* __restrict__ X1, const float4* __restrict__ X2, const int* __restrict__ map2,
    float4* __restrict__ O1, float4* __restrict__ O2, int src, int dst, int lane)
{
    int s = ptr[src], e = ptr[src + 1];
    float4 z = make_float4(0.f, 0.f, 0.f, 0.f);
    float4 a0 = z, a1 = z, b0 = z, b1 = z;
    for (int p = s; p < e; p++) {
        int c0 = cols[p]; float v0 = vals[p];
        int c0m = map2[c0];
        const float4* x10 = X1 + (size_t)c0 * D4c;
        const float4* x20 = X2 + (size_t)c0m * D4c;
        float4 p0 = x10[lane], p1 = x10[lane + 32];
        float4 q0 = x20[lane], q1 = x20[lane + 32];
        fma4(a0, v0, p0); fma4(a1, v0, p1); fma4(b0, v0, q0); fma4(b1, v0, q1);
    }
    O1[(size_t)dst * D4c + lane] = a0; O1[(size_t)dst * D4c + 32 + lane] = a1;
    O2[(size_t)dst * D4c + lane] = b0; O2[(size_t)dst * D4c + 32 + lane] = b1;
}

// ---------------- E-path L1 SPMM, both sides in one launch ----------------
__global__ __launch_bounds__(256) void spmmE2_kernel(
    const float4* __restrict__ e_s_f, const float4* __restrict__ e_j_f)
{
    int w = blockIdx.x * 8 + (threadIdx.x >> 5);
    int lane = threadIdx.x & 31;
    if (w >= NJc) return;
    if (blockIdx.y == 0) spmm_row1(g_ptr_j, g_ccol_j, g_cval_j, e_s_f, (float4*)g_Tje, w, w, lane);
    else                 spmm_row1(g_ptr_s, g_ccol_s, g_cval_s, e_j_f, (float4*)g_Tse, w, w, lane);
}

// ---------------- G-path L1 SPMM on COMPACT rows, both sides ----------------
__global__ __launch_bounds__(256) void spmmG2_kernel(
    const float4* __restrict__ Gs0, const float4* __restrict__ Gj0)
{
    int w = blockIdx.x * 8 + (threadIdx.x >> 5);
    int lane = threadIdx.x & 31;
    if (blockIdx.y == 0) {
        if (w >= g_jcnt_sel) return;
        spmm_row1(g_ptr_j, g_ccol_j, g_cval_j, Gs0, (float4*)g_Tjg, g_jlist[w], w, lane);
    } else {
        if (w >= g_scnt_sel) return;
        spmm_row1(g_ptr_s, g_ccol_s, g_cval_s, Gj0, (float4*)g_Tsg, g_slist[w], w, lane);
    }
}

// ---------------- L2 COMPACT Tse2 = A_s^T @ Ej1 on nlist rows -> g_Tje ----------------
__global__ __launch_bounds__(256) void spmmL2_tse_kernel(
    const float4* __restrict__ Ej, float4* __restrict__ Odst)
{
    int w = blockIdx.x * 8 + (threadIdx.x >> 5);
    int lane = threadIdx.x & 31;
    if (w >= g_ncnt_sel) return;
    spmm_row1(g_ptr_s, g_ccol_s, g_cval_s, Ej, Odst, g_nlist[w], w, lane);
}

// ---------------- L2 compacted selected rows (reads compact G1 via maps) ----------------
__global__ __launch_bounds__(256) void spmmL2_sel_kernel(
    const float4* __restrict__ Es, const float4* __restrict__ Gs1c, const float4* __restrict__ Gj1c,
    const int* __restrict__ j_ids, const int* __restrict__ s_ids)
{
    int gid = blockIdx.x;
    int warp = threadIdx.x >> 5;
    int lane = threadIdx.x & 31;
    if (gid < 128) {
        int i = gid * 8 + warp;
        int row = j_ids[i];
        spmm_row2m(g_ptr_j, g_ccol_j, g_cval_j, Es, Gs1c, g_smap,
                   (float4*)g_Tjec, (float4*)g_Tjgc, row, i, lane);
    } else {
        int i = (gid - 128) * 8 + warp;
        int row = s_ids[i];
        spmm_row1m(g_ptr_s, g_ccol_s, g_cval_s, Gj1c, g_jmap, (float4*)g_Tsgc, row, i, lane);
    }
}

// ---------------- GEMM core (double-buffered 128x128x16 NT) ----------------
__device__ __forceinline__ void gemm_core(
    const float* __restrict__ A, const float* __restrict__ W,
    int rowTile, int colTile, int M, float (&acc)[8][8],
    float (&As)[2][16][128], float (&Bs)[2][16][128])
{
    int tid = threadIdx.x;
    int tx = tid & 15, ty = tid >> 4;
    #pragma unroll
    for (int i = 0; i < 8; i++)
        #pragma unroll
        for (int j = 0; j < 8; j++) acc[i][j] = 0.f;

    int lrow = tid & 127;
    int khalf = (tid >> 7) * 8;
    const float* Ag = A + (size_t)(rowTile + lrow) * DIMc + khalf;
    const float* Wg = W + (size_t)(colTile + lrow) * DIMc + khalf;
    bool arow_ok = (rowTile + lrow) < M;
    const float4 z4 = make_float4(0.f, 0.f, 0.f, 0.f);

    float4 ra0 = arow_ok ? *(const float4*)(Ag + 0) : z4;
    float4 ra1 = arow_ok ? *(const float4*)(Ag + 4) : z4;
    float4 rb0 = *(const float4*)(Wg + 0);
    float4 rb1 = *(const float4*)(Wg + 4);
    As[0][khalf+0][lrow] = ra0.x; As[0][khalf+1][lrow] = ra0.y;
    As[0][khalf+2][lrow] = ra0.z; As[0][khalf+3][lrow] = ra0.w;
    As[0][khalf+4][lrow] = ra1.x; As[0][khalf+5][lrow] = ra1.y;
    As[0][khalf+6][lrow] = ra1.z; As[0][khalf+7][lrow] = ra1.w;
    Bs[0][khalf+0][lrow] = rb0.x; Bs[0][khalf+1][lrow] = rb0.y;
    Bs[0][khalf+2][lrow] = rb0.z; Bs[0][khalf+3][lrow] = rb0.w;
    Bs[0][khalf+4][lrow] = rb1.x; Bs[0][khalf+5][lrow] = rb1.y;
    Bs[0][khalf+6][lrow] = rb1.z; Bs[0][khalf+7][lrow] = rb1.w;
    __syncthreads();

    int buf = 0;
    for (int k0 = 16; k0 <= DIMc; k0 += 16) {
        bool more = k0 < DIMc;
        if (more) {
            ra0 = arow_ok ? *(const float4*)(Ag + k0) : z4;
            ra1 = arow_ok ? *(const float4*)(Ag + k0 + 4) : z4;
            rb0 = *(const float4*)(Wg + k0);
            rb1 = *(const float4*)(Wg + k0 + 4);
        }
        #pragma unroll
        for (int kk = 0; kk < 16; kk++) {
            float a[8], b[8];
            #pragma unroll
            for (int i = 0; i < 4; i++) {
                a[i]   = As[buf][kk][ty*4 + i];
                a[i+4] = As[buf][kk][ty*4 + i + 64];
                b[i]   = Bs[buf][kk][tx*4 + i];
                b[i+4] = Bs[buf][kk][tx*4 + i + 64];
            }
            #pragma unroll
            for (int i = 0; i < 8; i++)
                #pragma unroll
                for (int j = 0; j < 8; j++)
                    acc[i][j] = fmaf(a[i], b[j], acc[i][j]);
        }
        if (more) {
            int nb = buf ^ 1;
            As[nb][khalf+0][lrow] = ra0.x; As[nb][khalf+1][lrow] = ra0.y;
            As[nb][khalf+2][lrow] = ra0.z; As[nb][khalf+3][lrow] = ra0.w;
            As[nb][khalf+4][lrow] = ra1.x; As[nb][khalf+5][lrow] = ra1.y;
            As[nb][khalf+6][lrow] = ra1.z; As[nb][khalf+7][lrow] = ra1.w;
            Bs[nb][khalf+0][lrow] = rb0.x; Bs[nb][khalf+1][lrow] = rb0.y;
            Bs[nb][khalf+2][lrow] = rb0.z; Bs[nb][khalf+3][lrow] = rb0.w;
            Bs[nb][khalf+4][lrow] = rb1.x; Bs[nb][khalf+5][lrow] = rb1.y;
            Bs[nb][khalf+6][lrow] = rb1.z; Bs[nb][khalf+7][lrow] = rb1.w;
            __syncthreads();
            buf = nb;
        }
    }
}

// full-row GEMM with update epilogue: nv = old + relu(C); wout write; smode 0/1
__global__ __launch_bounds__(256, 2) void gemm_update_kernel(
    const float* __restrict__ A, const float* __restrict__ W,
    const float* __restrict__ oldv, float* __restrict__ outv, float* __restrict__ sumv,
    int M, int wout, int smode)
{
    __shared__ float As[2][16][128];
    __shared__ float Bs[2][16][128];
    float acc[8][8];
    int rowTile = blockIdx.y * 128, colTile = blockIdx.x * 128;
    gemm_core(A, W, rowTile, colTile, M, acc, As, Bs);
    int tid = threadIdx.x, tx = tid & 15, ty = tid >> 4;
    #pragma unroll
    for (int i = 0; i < 8; i++) {
        int gr = rowTile + ty*4 + (i & 3) + ((i >> 2) * 64);
        if (gr < M) {
            #pragma unroll
            for (int j = 0; j < 8; j++) {
                int gc = colTile + tx*4 + (j & 3) + ((j >> 2) * 64);
                size_t idx = (size_t)gr * DIMc + gc;
                float v = fmaxf(acc[i][j], 0.f);
                float o = oldv[idx];
                float nv = o + v;
                if (wout) outv[idx] = nv;
                if (smode == 1) sumv[idx] = o + nv;
            }
        }
    }
}

// compact G1 GEMM: rows compact; oldv indexed by orig id via list; out compact
__global__ __launch_bounds__(256, 2) void gemm_gc_kernel(
    const float* __restrict__ A, const float* __restrict__ W,
    const float* __restrict__ oldv, float* __restrict__ outv, int side)
{
    int M = side ? g_scnt_sel : g_jcnt_sel;
    const int* list = side ? g_slist : g_jlist;
    int rowTile = blockIdx.y * 128;
    if (rowTile >= M) return;
    __shared__ float As[2][16][128];
    __shared__ float Bs[2][16][128];
    float acc[8][8];
    int colTile = blockIdx.x * 128;
    gemm_core(A, W, rowTile, colTile, M, acc, As, Bs);
    int tid = threadIdx.x, tx = tid & 15, ty = tid >> 4;
    #pragma unroll
    for (int i = 0; i < 8; i++) {
        int gr = rowTile + ty*4 + (i & 3) + ((i >> 2) * 64);
        if (gr < M) {
            int orig = list[gr];
            #pragma unroll
            for (int j = 0; j < 8; j++) {
                int gc = colTile + tx*4 + (j & 3) + ((j >> 2) * 64);
                float v = fmaxf(acc[i][j], 0.f);
                outv[(size_t)gr * DIMc + gc] = oldv[(size_t)orig * DIMc + gc] + v;
            }
        }
    }
}

// compact Es2 GEMM: rows = nlist; out g_Tse[w] = sEs_partial[orig] + Es[orig] + relu(C)
__global__ __launch_bounds__(256, 2) void gemm_es2c_kernel(const float* __restrict__ W)
{
    int M = g_ncnt_sel;
    int rowTile = blockIdx.y * 128;
    if (rowTile >= M) return;
    __shared__ float As[2][16][128];
    __shared__ float Bs[2][16][128];
    float acc[8][8];
    int colTile = blockIdx.x * 128;
    gemm_core(g_Tje, W, rowTile, colTile, M, acc, As, Bs);
    int tid = threadIdx.x, tx = tid & 15, ty = tid >> 4;
    #pragma unroll
    for (int i = 0; i < 8; i++) {
        int gr = rowTile + ty*4 + (i & 3) + ((i >> 2) * 64);
        if (gr < M) {
            int orig = g_nlist[gr];
            #pragma unroll
            for (int j = 0; j < 8; j++) {
                int gc = colTile + tx*4 + (j & 3) + ((j >> 2) * 64);
                size_t src = (size_t)orig * DIMc + gc;
                float v = fmaxf(acc[i][j], 0.f);
                g_Tse[(size_t)gr * DIMc + gc] = g_sEs[src] + g_Es[src] + v;
            }
        }
    }
}

// selected GEMM: dst[i,:] = base0[ids[i]] + 2*base1[map? map[ids[i]] : ids[i]] + relu(Ac@W^T)
__global__ __launch_bounds__(256, 2) void gemm_sel_kernel(
    const float* __restrict__ e_j_f,
    const float* __restrict__ Wj2, const float* __restrict__ Wja2, const float* __restrict__ Wsa2,
    const int* __restrict__ j_ids, const int* __restrict__ s_ids)
{
    __shared__ float As[2][16][128];
    __shared__ float Bs[2][16][128];
    const float* A; const float* W; const float* base0; const float* base1;
    const int* map1; float* dst; const int* ids;
    switch (blockIdx.z) {
        case 0: A = g_Tjec; W = Wj2;  base0 = e_j_f; base1 = g_Ej;  map1 = 0;      dst = g_ejsel; ids = j_ids; break;
        case 1: A = g_Tjgc; W = Wja2; base0 = g_Gj;  base1 = g_Gj1; map1 = g_jmap; dst = g_gjsel; ids = j_ids; break;
        default: A = g_Tsgc; W = Wsa2; base0 = g_Gs; base1 = g_Gs1; map1 = g_smap; dst = g_gssel; ids = s_ids; break;
    }
    float acc[8][8];
    int rowTile = blockIdx.y * 128, colTile = blockIdx.x * 128;
    gemm_core(A, W, rowTile, colTile, Bc, acc, As, Bs);
    int tid = threadIdx.x, tx = tid & 15, ty = tid >> 4;
    #pragma unroll
    for (int i = 0; i < 8; i++) {
        int gr = rowTile + ty*4 + (i & 3) + ((i >> 2) * 64);
        int id = ids[gr];
        int id1 = map1 ? map1[id] : id;
        #pragma unroll
        for (int j = 0; j < 8; j++) {
            int gc = colTile + tx*4 + (j & 3) + ((j >> 2) * 64);
            float v = fmaxf(acc[i][j], 0.f);
            dst[(size_t)gr * DIMc + gc] =
                base0[(size_t)id * DIMc + gc] + 2.f * base1[(size_t)id1 * DIMc + gc] + v;
        }
    }
}

// ---------------- GEMM + exp + per-(row,group) sum ----------------
__global__ __launch_bounds__(256, 2) void expsum_kernel(
    const float* __restrict__ A, const float* __restrict__ Bm,
    float* __restrict__ sumexp, int ngroups)
{
    __shared__ float As[2][16][128];
    __shared__ float Bs[2][16][128];
    __shared__ float red[128];
    float acc[8][8];
    int rowTile = blockIdx.y * 128, colTile = blockIdx.x * 128;
    gemm_core(A, Bm, rowTile, colTile, 1 << 30, acc, As, Bs);
    int tid = threadIdx.x, tx = tid & 15, ty = tid >> 4;
    float rsum[8];
    #pragma unroll
    for (int i = 0; i < 8; i++) {
        rsum[i] = 0.f;
        #pragma unroll
        for (int j = 0; j < 8; j++) rsum[i] += expf(acc[i][j] * 5.0f);  // 1/TEMP = 5
    }
    if (tid < 128) red[tid] = 0.f;
    __syncthreads();
    #pragma unroll
    for (int i = 0; i < 8; i++) {
        int r = ty*4 + (i & 3) + ((i >> 2) * 64);
        atomicAdd(&red[r], rsum[i]);
    }
    __syncthreads();
    if (tid < 128) {
        int gr = rowTile + tid;
        int group = blockIdx.x >> 3;
        atomicAdd(&sumexp[(size_t)gr * ngroups + group], red[tid]);
    }
}

// ---------------- combined gather from compact sEs (g_Tse) via nmap ----------------
__global__ void gatherNE_kernel(const int* __restrict__ negs, const int* __restrict__ s_ids) {
    int row = blockIdx.x;
    const float4* src = (const float4*)g_Tse;
    if (row < NEGRc) {
        int id = g_nmap[negs[row]];
        ((float4*)g_negemb)[(size_t)row * D4c + threadIdx.x] = src[(size_t)id * D4c + threadIdx.x];
    } else {
        int r = row - NEGRc;
        int id = g_nmap[s_ids[r]];
        ((float4*)g_essel)[(size_t)r * D4c + threadIdx.x] = src[(size_t)id * D4c + threadIdx.x];
    }
}

// ---------------- pos score ----------------
__global__ void pos_kernel() {
    int w = (blockIdx.x * blockDim.x + threadIdx.x) >> 5;
    int lane = threadIdx.x & 31;
    if (w >= Bc) return;
    const float4* gj = (const float4*)g_gjsel + (size_t)w * D4c;
    const float4* ej = (const float4*)g_ejsel + (size_t)w * D4c;
    const float4* gs = (const float4*)g_gssel + (size_t)w * D4c;
    const float4* es = (const float4*)g_essel + (size_t)w * D4c;
    float4 a0 = gj[lane], a1 = gj[lane+32], b0 = ej[lane], b1 = ej[lane+32];
    float4 c0 = gs[lane], c1 = gs[lane+32], d0 = es[lane], d1 = es[lane+32];
    float s1 = a0.x*b0.x + a0.y*b0.y + a0.z*b0.z + a0.w*b0.w
             + a1.x*b1.x + a1.y*b1.y + a1.z*b1.z + a1.w*b1.w;
    float s2 = c0.x*d0.x + c0.y*d0.y + c0.z*d0.z + c0.w*d0.w
             + c1.x*d1.x + c1.y*d1.y + c1.z*d1.z + c1.w*d1.w;
    #pragma unroll
    for (int o = 16; o; o >>= 1) {
        s1 += __shfl_xor_sync(0xffffffffu, s1, o);
        s2 += __shfl_xor_sync(0xffffffffu, s2, o);
    }
    if (lane == 0) {
        float c1v = fminf(fmaxf(s1 * 5.0f, -1.f), 1.f);
        float c2v = fminf(fmaxf(s2 * 5.0f, -1.f), 1.f);
        atomicAdd(&g_scalars[0], c1v);
        atomicAdd(&g_scalars[1], c2v);
    }
}

// ---------------- weight L2 regularizer ----------------
__global__ void wsq_kernel(const float* __restrict__ a, const float* __restrict__ b,
                           const float* __restrict__ c, const float* __restrict__ d) {
    float s = 0.f;
    for (int i = blockIdx.x * blockDim.x + threadIdx.x; i < WSZc; i += gridDim.x * blockDim.x) {
        float x;
        x = a[i]; s += x * x;
        x = b[i]; s += x * x;
        x = c[i]; s += x * x;
        x = d[i]; s += x * x;
    }
    #pragma unroll
    for (int o = 16; o; o >>= 1) s += __shfl_xor_sync(0xffffffffu, s, o);
    __shared__ float sh[8];
    int lane = threadIdx.x & 31, wid = threadIdx.x >> 5;
    if (lane == 0) sh[wid] = s;
    __syncthreads();
    if (threadIdx.x == 0) {
        float t = 0.f;
        for (int i = 0; i < (int)(blockDim.x >> 5); i++) t += sh[i];
        atomicAdd(&g_scalars[2], t);
    }
}

// ---------------- finalize ----------------
__device__ double blk_reduce_1024(double v) {
    __shared__ double sh[32];
    __syncthreads();
    int lane = threadIdx.x & 31, wid = threadIdx.x >> 5;
    #pragma unroll
    for (int o = 16; o; o >>= 1) v += __shfl_down_sync(0xffffffffu, v, o);
    if (lane == 0) sh[wid] = v;
    __syncthreads();
    v = (threadIdx.x < 32) ? sh[threadIdx.x] : 0.0;
    if (wid == 0) {
        #pragma unroll
        for (int o = 16; o; o >>= 1) v += __shfl_down_sync(0xffffffffu, v, o);
    }
    return v;
}

__global__ void finalize_kernel(float* __restrict__ out) {
    int tid = threadIdx.x;
    double a = (tid < Bc) ? log((double)g_sumexp_j[tid] + 1e-8) : 0.0;
    double negj = blk_reduce_1024(a);
    double b = 0.0;
    for (int i = tid; i < Bc * NNEGc; i += 1024)
        b += log((double)g_sumexp_s[i] + 1e-8);
    double negs = blk_reduce_1024(b);
    if (tid == 0) {
        double pos = (double)g_scalars[0] / Bc + (double)g_scalars[1] / Bc;
        double neg = negj / Bc + negs / (double)(Bc * NNEGc);
        double cl = (-pos + neg) * 0.2;
        double reg = 1e-4 * (double)g_scalars[2];
        out[0] = (float)(cl + reg);
        out[1] = (float)cl;
        out[2] = (float)reg;
    }
}

// ---------------- launch ----------------
#define SYM(p, s) do { void* _t = 0; cudaGetSymbolAddress(&_t, s); p = (decltype(p))_t; } while (0)

extern "C" void kernel_launch(void* const* d_in, const int* in_sizes, int n_in,
                              void* d_out, int out_size) {
    (void)in_sizes; (void)n_in; (void)out_size;
    const float* e_j_f   = (const float*)d_in[0];
    const float* e_s_f   = (const float*)d_in[1];
    const float* aug_e_j = (const float*)d_in[2];
    const float* aug_e_s = (const float*)d_in[3];
    const float* val_j   = (const float*)d_in[4];
    const float* val_s   = (const float*)d_in[5];
    const float* W_j     = (const float*)d_in[6];
    const float* W_s     = (const float*)d_in[7];
    const float* W_j_aug = (const float*)d_in[8];
    const float* W_s_aug = (const float*)d_in[9];
    const int* row_j = (const int*)d_in[10];
    const int* col_j = (const int*)d_in[11];
    const int* row_s = (const int*)d_in[12];
    const int* col_s = (const int*)d_in[13];
    const int* j_ids = (const int*)d_in[14];
    const int* s_ids = (const int*)d_in[15];
    const int* negs  = (const int*)d_in[16];
    float* out = (float*)d_out;

    float *Ej, *Es, *Gj, *Gs, *Gj1, *Gs1, *sEs, *Tje, *Tjg, *Tse, *Tsg;
    float *gjsel, *ejsel, *gssel, *negemb, *sumexp_j, *sumexp_s;
    SYM(Ej, g_Ej); SYM(Es, g_Es); SYM(Gj, g_Gj); SYM(Gs, g_Gs);
    SYM(Gj1, g_Gj1); SYM(Gs1, g_Gs1); SYM(sEs, g_sEs);
    SYM(Tje, g_Tje); SYM(Tjg, g_Tjg); SYM(Tse, g_Tse); SYM(Tsg, g_Tsg);
    SYM(gjsel, g_gjsel); SYM(ejsel, g_ejsel); SYM(gssel, g_gssel);
    SYM(negemb, g_negemb); SYM(sumexp_j, g_sumexp_j); SYM(sumexp_s, g_sumexp_s);

    static int inited = 0;
    static cudaStream_t s1;
    static cudaEvent_t evStart, evL2n, evCsr, evGspmm, evEj, evTse, evG, evSel, evGat, evLoss;
    if (!inited) {
        cudaStreamCreateWithFlags(&s1, cudaStreamNonBlocking);
        cudaEventCreateWithFlags(&evStart, cudaEventDisableTiming);
        cudaEventCreateWithFlags(&evL2n,   cudaEventDisableTiming);
        cudaEventCreateWithFlags(&evCsr,   cudaEventDisableTiming);
        cudaEventCreateWithFlags(&evGspmm, cudaEventDisableTiming);
        cudaEventCreateWithFlags(&evEj,    cudaEventDisableTiming);
        cudaEventCreateWithFlags(&evTse,   cudaEventDisableTiming);
        cudaEventCreateWithFlags(&evG,     cudaEventDisableTiming);
        cudaEventCreateWithFlags(&evSel,   cudaEventDisableTiming);
        cudaEventCreateWithFlags(&evGat,   cudaEventDisableTiming);
        cudaEventCreateWithFlags(&evLoss,  cudaEventDisableTiming);
        inited = 1;
    }

    const int EB = (Ec + 255) / 256;         // 6250
    const int RB = 6250;

    zero_kernel<<<256, 256>>>();
    mark_neg_kernel<<<(NEGRc + Bc + 255) / 256, 256>>>(negs, s_ids);
    cudaEventRecord(evStart, 0);
    cudaStreamWaitEvent(s1, evStart, 0);

    // side: initial l2norm + wsq
    {
        dim3 g(RB, 2);
        l2norm4_kernel<<<g, 256, 0, s1>>>((const float4*)aug_e_j, (float4*)Gj,
                                          (const float4*)aug_e_s, (float4*)Gs,
                                          (const float4*)aug_e_j, (float4*)Gj,
                                          (const float4*)aug_e_s, (float4*)Gs, NJc);
        wsq_kernel<<<256, 256, 0, s1>>>(W_j, W_s, W_j_aug, W_s_aug);
        cudaEventRecord(evL2n, s1);
    }
    // default: CSR build
    count_kernel<<<EB, 256>>>(row_j, col_s);
    scan2_kernel<<<2, 1024>>>();
    scatter_kernel<<<EB, 256>>>(row_j, col_j, val_j, row_s, col_s, val_s);
    cudaEventRecord(evCsr, 0);

    // side: mark + compact + compact G SPMMs
    cudaStreamWaitEvent(s1, evCsr, 0);
    mark_kernel<<<128, 256, 0, s1>>>(j_ids, s_ids);
    compact_kernel<<<(NJc + 255) / 256, 256, 0, s1>>>();
    {
        dim3 gg(RB, 2);
        spmmG2_kernel<<<gg, 256, 0, s1>>>((const float4*)Gs, (const float4*)Gj);
    }
    cudaEventRecord(evGspmm, s1);

    // default: E-path L1 SPMM (both sides)
    cudaStreamWaitEvent(0, evL2n, 0);
    {
        dim3 sg(RB, 2);
        spmmE2_kernel<<<sg, 256>>>((const float4*)e_s_f, (const float4*)e_j_f);
    }
    dim3 gemm_grid(2, 391);
    gemm_update_kernel<<<gemm_grid, 256>>>(Tje, W_j, e_j_f, Ej, (float*)0, NJc, 1, 0);
    cudaEventRecord(evEj, 0);

    // side: compact Tse2 SPMM into freed g_Tje (needs nlist from compact: same stream order ok)
    cudaStreamWaitEvent(s1, evEj, 0);
    spmmL2_tse_kernel<<<RB, 256, 0, s1>>>((const float4*)Ej, (float4*)Tje);
    cudaEventRecord(evTse, s1);

    // default: Es GEMM (+partial sum), then compact G1 GEMMs
    gemm_update_kernel<<<gemm_grid, 256>>>(Tse, W_s, e_s_f, Es, sEs, NSc, 1, 1);
    cudaStreamWaitEvent(0, evGspmm, 0);
    gemm_gc_kernel<<<gemm_grid, 256>>>(Tjg, W_j_aug, Gj, Gj1, 0);
    gemm_gc_kernel<<<gemm_grid, 256>>>(Tsg, W_s_aug, Gs, Gs1, 1);
    cudaEventRecord(evG, 0);

    // side: compacted selected chain
    cudaStreamWaitEvent(s1, evG, 0);
    spmmL2_sel_kernel<<<256, 256, 0, s1>>>((const float4*)Es, (const float4*)Gs1,
                                           (const float4*)Gj1, j_ids, s_ids);
    {
        dim3 sg(2, 8, 3);
        gemm_sel_kernel<<<sg, 256, 0, s1>>>(e_j_f, W_j + DIMc*DIMc, W_j_aug + DIMc*DIMc,
                                            W_s_aug + DIMc*DIMc, j_ids, s_ids);
    }
    l2norm4_kernel<<<dim3(128, 3), 256, 0, s1>>>(
        (const float4*)ejsel, (float4*)ejsel,
        (const float4*)gjsel, (float4*)gjsel,
        (const float4*)gssel, (float4*)gssel,
        (const float4*)gssel, (float4*)gssel, Bc);
    cudaEventRecord(evSel, s1);

    // default: compact Es L2 chain (GEMM writes compact sEs into g_Tse, l2norm, gather)
    cudaStreamWaitEvent(0, evTse, 0);
    gemm_es2c_kernel<<<gemm_grid, 256>>>(W_s + DIMc*DIMc);
    l2normC_kernel<<<RB, 256>>>();
    gatherNE_kernel<<<NEGRc + Bc, 64>>>(negs, s_ids);
    cudaEventRecord(evGat, 0);

    // side: small losses
    cudaStreamWaitEvent(s1, evGat, 0);
    {
        dim3 lg(Bc / 128, Bc / 128);
        expsum_kernel<<<lg, 256, 0, s1>>>(gjsel, ejsel, sumexp_j, 1);
        pos_kernel<<<Bc / 8, 256, 0, s1>>>();
        cudaEventRecord(evLoss, s1);
    }
    // default: big expsum
    cudaStreamWaitEvent(0, evSel, 0);
    {
        dim3 ng(NEGRc / 128, Bc / 128);
        expsum_kernel<<<ng, 256>>>(gssel, negemb, sumexp_s, NNEGc);
    }
    cudaStreamWaitEvent(0, evLoss, 0);
    finalize_kernel<<<1, 1024>>>(out);
}

// round 17
// speedup vs baseline: 2.0338x; 1.0267x over previous
#include <cuda_runtime.h>
#include <math.h>

#define NJc 50000
#define NSc 50000
#define Ec  1600000
#define DIMc 256
#define D4c  64
#define Lc   2
#define Bc   1024
#define NNEGc 32
#define NEGRc (NNEGc*Bc)
#define WSZc (Lc*DIMc*DIMc)

// ---------------- scratch (device globals; no allocation allowed) ----------------
__device__ float g_Ej[NJc*DIMc];
__device__ float g_Es[NSc*DIMc];      // written only at umark rows (scatter)
__device__ float g_Gj[NJc*DIMc];      // layer-0 G_j (preserved)
__device__ float g_Gs[NSc*DIMc];      // layer-0 G_s (preserved)
__device__ float g_Gj1[NJc*DIMc];     // layer-1 G_j, COMPACT rows (jlist order)
__device__ float g_Gs1[NSc*DIMc];     // layer-1 G_s, COMPACT rows (slist order)
__device__ float g_sEs[NSc*DIMc];     // E0+E1 partial sum, valid at umark rows
__device__ float g_Tje[NJc*DIMc];     // L1 j-side SPMM; later compact Tse2
__device__ float g_Tjg[NJc*DIMc];     // compact G SPMM out (j side)
__device__ float g_Tse[NSc*DIMc];     // compact L1 s-side SPMM (ulist); later compact final sEs
__device__ float g_Tsg[NSc*DIMc];     // compact G SPMM out (s side)
__device__ float g_Tjec[Bc*DIMc];
__device__ float g_Tjgc[Bc*DIMc];
__device__ float g_Tsgc[Bc*DIMc];
__device__ int   g_cnt_j[NJc];
__device__ int   g_cnt_s[NSc];
__device__ int   g_ptr_j[NJc+1];
__device__ int   g_ptr_s[NSc+1];
__device__ int   g_cur_j[NJc];
__device__ int   g_cur_s[NSc];
__device__ int   g_ccol_j[Ec];
__device__ float g_cval_j[Ec];
__device__ int   g_ccol_s[Ec];
__device__ float g_cval_s[Ec];
// neighbor-set machinery
__device__ int   g_jmark[NJc];
__device__ int   g_smark[NSc];
__device__ int   g_nmark[NSc];        // negs ∪ s_ids
__device__ int   g_jlist[NJc];
__device__ int   g_slist[NSc];
__device__ int   g_nlist[NSc];
__device__ int   g_ulist[NSc];        // smark ∪ nmark
__device__ int   g_jmap[NJc];
__device__ int   g_smap[NSc];
__device__ int   g_nmap[NSc];
__device__ int   g_jcnt_sel;
__device__ int   g_scnt_sel;
__device__ int   g_ncnt_sel;
__device__ int   g_ucnt_sel;
__device__ float g_gjsel[Bc*DIMc];
__device__ float g_ejsel[Bc*DIMc];
__device__ float g_gssel[Bc*DIMc];
__device__ float g_essel[Bc*DIMc];
__device__ float g_negemb[NEGRc*DIMc];
__device__ float g_sumexp_j[Bc];
__device__ float g_sumexp_s[Bc*NNEGc];
__device__ float g_scalars[8];   // [0]=pos_j sum, [1]=pos_s sum, [2]=wsq

// ---------------- small utility kernels ----------------
__global__ void zero_kernel() {
    int i = blockIdx.x * blockDim.x + threadIdx.x;
    int st = gridDim.x * blockDim.x;
    for (int k = i; k < NJc; k += st) { g_cnt_j[k] = 0; g_jmark[k] = 0; }
    for (int k = i; k < NSc; k += st) { g_cnt_s[k] = 0; g_smark[k] = 0; g_nmark[k] = 0; }
    for (int k = i; k < Bc; k += st) g_sumexp_j[k] = 0.f;
    for (int k = i; k < Bc*NNEGc; k += st) g_sumexp_s[k] = 0.f;
    if (i < 8) g_scalars[i] = 0.f;
    if (i == 8) { g_jcnt_sel = 0; g_scnt_sel = 0; g_ncnt_sel = 0; g_ucnt_sel = 0; }
}

__global__ void mark_neg_kernel(const int* __restrict__ negs, const int* __restrict__ s_ids) {
    int i = blockIdx.x * blockDim.x + threadIdx.x;
    if (i < NEGRc) g_nmark[negs[i]] = 1;
    else if (i < NEGRc + Bc) g_nmark[s_ids[i - NEGRc]] = 1;
}

__global__ void count_kernel(const int* __restrict__ row_j, const int* __restrict__ col_s) {
    int i = blockIdx.x * blockDim.x + threadIdx.x;
    if (i < Ec) {
        atomicAdd(&g_cnt_j[row_j[i]], 1);
        atomicAdd(&g_cnt_s[col_s[i]], 1);
    }
}

__global__ void scan2_kernel() {
    const int* cnt = blockIdx.x ? g_cnt_s : g_cnt_j;
    int* ptr = blockIdx.x ? g_ptr_s : g_ptr_j;
    int* cur = blockIdx.x ? g_cur_s : g_cur_j;
    int n = blockIdx.x ? NSc : NJc;
    __shared__ int warp_sums[32];
    __shared__ int s_carry;
    int tid = threadIdx.x;
    if (tid == 0) { s_carry = 0; ptr[0] = 0; }
    __syncthreads();
    for (int base = 0; base < n; base += 1024) {
        int i = base + tid;
        int v = (i < n) ? cnt[i] : 0;
        int inc = v;
        #pragma unroll
        for (int off = 1; off < 32; off <<= 1) {
            int t = __shfl_up_sync(0xffffffffu, inc, off);
            if ((tid & 31) >= off) inc += t;
        }
        if ((tid & 31) == 31) warp_sums[tid >> 5] = inc;
        __syncthreads();
        if (tid < 32) {
            int ws = warp_sums[tid];
            int wi = ws;
            #pragma unroll
            for (int off = 1; off < 32; off <<= 1) {
                int t = __shfl_up_sync(0xffffffffu, wi, off);
                if (tid >= off) wi += t;
            }
            warp_sums[tid] = wi - ws;
        }
        __syncthreads();
        int excl = inc - v + warp_sums[tid >> 5];
        int carry = s_carry;
        if (i < n) {
            int start = carry + excl;
            cur[i] = start;
            ptr[i + 1] = start + v;
        }
        __syncthreads();
        if (tid == 1023) s_carry = carry + excl + v;
        __syncthreads();
    }
}

__global__ void scatter_kernel(const int* __restrict__ row_j, const int* __restrict__ col_j,
                               const float* __restrict__ val_j,
                               const int* __restrict__ row_s, const int* __restrict__ col_s,
                               const float* __restrict__ val_s) {
    int i = blockIdx.x * blockDim.x + threadIdx.x;
    if (i >= Ec) return;
    int p = atomicAdd(&g_cur_j[row_j[i]], 1);
    g_ccol_j[p] = col_j[i]; g_cval_j[p] = val_j[i];
    int q = atomicAdd(&g_cur_s[col_s[i]], 1);
    g_ccol_s[q] = row_s[i]; g_cval_s[q] = val_s[i];
}

// mark neighbor sets: Sset = N(j_ids) via CSR_j cols + s_ids; Jset = N(s_ids) via CSR_s + j_ids
__global__ void mark_kernel(const int* __restrict__ j_ids, const int* __restrict__ s_ids) {
    int w = blockIdx.x * (blockDim.x >> 5) + (threadIdx.x >> 5);
    int lane = threadIdx.x & 31;
    if (w >= Bc) return;
    int r = j_ids[w];
    if (lane == 0) g_jmark[r] = 1;
    for (int p = g_ptr_j[r] + lane; p < g_ptr_j[r+1]; p += 32) g_smark[g_ccol_j[p]] = 1;
    int rs = s_ids[w];
    if (lane == 0) g_smark[rs] = 1;
    for (int p = g_ptr_s[rs] + lane; p < g_ptr_s[rs+1]; p += 32) g_jmark[g_ccol_s[p]] = 1;
}

__global__ void compact_kernel() {
    int i = blockIdx.x * blockDim.x + threadIdx.x;
    if (i < NJc && g_jmark[i]) {
        int p = atomicAdd(&g_jcnt_sel, 1);
        g_jlist[p] = i; g_jmap[i] = p;
    }
    if (i < NSc) {
        int sm = g_smark[i], nm = g_nmark[i];
        if (sm) {
            int p = atomicAdd(&g_scnt_sel, 1);
            g_slist[p] = i; g_smap[i] = p;
        }
        if (nm) {
            int p = atomicAdd(&g_ncnt_sel, 1);
            g_nlist[p] = i; g_nmap[i] = p;
        }
        if (sm | nm) {
            int p = atomicAdd(&g_ucnt_sel, 1);
            g_ulist[p] = i;
        }
    }
}

// ---------------- fused row l2 normalize over up to 4 arrays ----------------
__global__ void l2norm4_kernel(const float4* s0, float4* d0, const float4* s1, float4* d1,
                               const float4* s2, float4* d2, const float4* s3, float4* d3,
                               int n) {
    const float4* src; float4* dst;
    switch (blockIdx.y) {
        case 0: src = s0; dst = d0; break;
        case 1: src = s1; dst = d1; break;
        case 2: src = s2; dst = d2; break;
        default: src = s3; dst = d3; break;
    }
    int w = (blockIdx.x * blockDim.x + threadIdx.x) >> 5;
    int lane = threadIdx.x & 31;
    if (w >= n) return;
    const float4* s = src + (size_t)w * D4c;
    float4 u0 = s[lane], u1 = s[lane + 32];
    float ss = u0.x*u0.x + u0.y*u0.y + u0.z*u0.z + u0.w*u0.w
             + u1.x*u1.x + u1.y*u1.y + u1.z*u1.z + u1.w*u1.w;
    #pragma unroll
    for (int o = 16; o; o >>= 1) ss += __shfl_xor_sync(0xffffffffu, ss, o);
    float inv = 1.f / fmaxf(sqrtf(ss), 1e-12f);
    float4* d = dst + (size_t)w * D4c;
    d[lane]      = make_float4(u0.x*inv, u0.y*inv, u0.z*inv, u0.w*inv);
    d[lane + 32] = make_float4(u1.x*inv, u1.y*inv, u1.z*inv, u1.w*inv);
}

// compact in-place l2norm on g_Tse rows [0, g_ncnt_sel)
__global__ void l2normC_kernel() {
    int w = (blockIdx.x * blockDim.x + threadIdx.x) >> 5;
    int lane = threadIdx.x & 31;
    if (w >= g_ncnt_sel) return;
    float4* s = (float4*)g_Tse + (size_t)w * D4c;
    float4 u0 = s[lane], u1 = s[lane + 32];
    float ss = u0.x*u0.x + u0.y*u0.y + u0.z*u0.z + u0.w*u0.w
             + u1.x*u1.x + u1.y*u1.y + u1.z*u1.z + u1.w*u1.w;
    #pragma unroll
    for (int o = 16; o; o >>= 1) ss += __shfl_xor_sync(0xffffffffu, ss, o);
    float inv = 1.f / fmaxf(sqrtf(ss), 1e-12f);
    s[lane]      = make_float4(u0.x*inv, u0.y*inv, u0.z*inv, u0.w*inv);
    s[lane + 32] = make_float4(u1.x*inv, u1.y*inv, u1.z*inv, u1.w*inv);
}

// ---------------- SPMM row bodies ----------------
__device__ __forceinline__ void fma4(float4& acc, float v, const float4& u) {
    acc.x = fmaf(v, u.x, acc.x);
    acc.y = fmaf(v, u.y, acc.y);
    acc.z = fmaf(v, u.z, acc.z);
    acc.w = fmaf(v, u.w, acc.w);
}

__device__ __forceinline__ void spmm_row1(
    const int* __restrict__ ptr, const int* __restrict__ cols, const float* __restrict__ vals,
    const float4* __restrict__ X, float4* __restrict__ O, int src, int dst, int lane)
{
    int s = ptr[src], e = ptr[src + 1];
    float4 z = make_float4(0.f, 0.f, 0.f, 0.f);
    float4 a0 = z, a1 = z;
    int p = s;
    for (; p + 4 <= e; p += 4) {
        int c0 = cols[p], c1 = cols[p+1], c2 = cols[p+2], c3 = cols[p+3];
        float v0 = vals[p], v1 = vals[p+1], v2 = vals[p+2], v3 = vals[p+3];
        const float4* x0 = X + (size_t)c0 * D4c;
        const float4* x1 = X + (size_t)c1 * D4c;
        const float4* x2 = X + (size_t)c2 * D4c;
        const float4* x3 = X + (size_t)c3 * D4c;
        float4 p00 = x0[lane], p01 = x0[lane + 32];
        float4 p10 = x1[lane], p11 = x1[lane + 32];
        float4 p20 = x2[lane], p21 = x2[lane + 32];
        float4 p30 = x3[lane], p31 = x3[lane + 32];
        fma4(a0, v0, p00); fma4(a1, v0, p01);
        fma4(a0, v1, p10); fma4(a1, v1, p11);
        fma4(a0, v2, p20); fma4(a1, v2, p21);
        fma4(a0, v3, p30); fma4(a1, v3, p31);
    }
    for (; p < e; p++) {
        int c0 = cols[p]; float v0 = vals[p];
        const float4* x0 = X + (size_t)c0 * D4c;
        float4 p00 = x0[lane], p01 = x0[lane + 32];
        fma4(a0, v0, p00); fma4(a1, v0, p01);
    }
    O[(size_t)dst * D4c + lane] = a0;
    O[(size_t)dst * D4c + 32 + lane] = a1;
}

__device__ __forceinline__ void spmm_row1m(
    const int* __restrict__ ptr, const int* __restrict__ cols, const float* __restrict__ vals,
    const float4* __restrict__ X, const int* __restrict__ map,
    float4* __restrict__ O, int src, int dst, int lane)
{
    int s = ptr[src], e = ptr[src + 1];
    float4 z = make_float4(0.f, 0.f, 0.f, 0.f);
    float4 a0 = z, a1 = z;
    for (int p = s; p < e; p++) {
        int c0 = map[cols[p]]; float v0 = vals[p];
        const float4* x0 = X + (size_t)c0 * D4c;
        float4 p00 = x0[lane], p01 = x0[lane + 32];
        fma4(a0, v0, p00); fma4(a1, v0, p01);
    }
    O[(size_t)dst * D4c + lane] = a0;
    O[(size_t)dst * D4c + 32 + lane] = a1;
}

__device__ __forceinline__ void spmm_row2m(
    const int* __restrict__ ptr, const int* __restrict__ cols, const float* __restrict__ vals,
    const float4* __restrict__ X1, const float4* __restrict__ X2, const int* __restrict__ map2,
    float4* __restrict__ O1, float4* __restrict__ O2, int src, int dst, int lane)
{
    int s = ptr[src], e = ptr[src + 1];
    float4 z = make_float4(0.f, 0.f, 0.f, 0.f);
    float4 a0 = z, a1 = z, b0 = z, b1 = z;
    for (int p = s; p < e; p++) {
        int c0 = cols[p]; float v0 = vals[p];
        int c0m = map2[c0];
        const float4* x10 = X1 + (size_t)c0 * D4c;
        const float4* x20 = X2 + (size_t)c0m * D4c;
        float4 p0 = x10[lane], p1 = x10[lane + 32];
        float4 q0 = x20[lane], q1 = x20[lane + 32];
        fma4(a0, v0, p0); fma4(a1, v0, p1); fma4(b0, v0, q0); fma4(b1, v0, q1);
    }
    O1[(size_t)dst * D4c + lane] = a0; O1[(size_t)dst * D4c + 32 + lane] = a1;
    O2[(size_t)dst * D4c + lane] = b0; O2[(size_t)dst * D4c + 32 + lane] = b1;
}

// ---------------- E-path L1 SPMM: j side (full) ----------------
__global__ __launch_bounds__(256) void spmmEj_kernel(const float4* __restrict__ e_s_f)
{
    int w = blockIdx.x * 8 + (threadIdx.x >> 5);
    int lane = threadIdx.x & 31;
    if (w >= NJc) return;
    spmm_row1(g_ptr_j, g_ccol_j, g_cval_j, e_s_f, (float4*)g_Tje, w, w, lane);
}

// ---------------- E-path L1 SPMM: s side on COMPACT ulist rows ----------------
__global__ __launch_bounds__(256) void spmmEsC_kernel(const float4* __restrict__ e_j_f)
{
    int w = blockIdx.x * 8 + (threadIdx.x >> 5);
    int lane = threadIdx.x & 31;
    if (w >= g_ucnt_sel) return;
    spmm_row1(g_ptr_s, g_ccol_s, g_cval_s, e_j_f, (float4*)g_Tse, g_ulist[w], w, lane);
}

// ---------------- G-path L1 SPMM on COMPACT rows, both sides ----------------
__global__ __launch_bounds__(256) void spmmG2_kernel(
    const float4* __restrict__ Gs0, const float4* __restrict__ Gj0)
{
    int w = blockIdx.x * 8 + (threadIdx.x >> 5);
    int lane = threadIdx.x & 31;
    if (blockIdx.y == 0) {
        if (w >= g_jcnt_sel) return;
        spmm_row1(g_ptr_j, g_ccol_j, g_cval_j, Gs0, (float4*)g_Tjg, g_jlist[w], w, lane);
    } else {
        if (w >= g_scnt_sel) return;
        spmm_row1(g_ptr_s, g_ccol_s, g_cval_s, Gj0, (float4*)g_Tsg, g_slist[w], w, lane);
    }
}

// ---------------- L2 COMPACT Tse2 = A_s^T @ Ej1 on nlist rows -> g_Tje ----------------
__global__ __launch_bounds__(256) void spmmL2_tse_kernel(
    const float4* __restrict__ Ej, float4* __restrict__ Odst)
{
    int w = blockIdx.x * 8 + (threadIdx.x >> 5);
    int lane = threadIdx.x & 31;
    if (w >= g_ncnt_sel) return;
    spmm_row1(g_ptr_s, g_ccol_s, g_cval_s, Ej, Odst, g_nlist[w], w, lane);
}

// ---------------- L2 compacted selected rows (reads compact G1 via maps) ----------------
__global__ __launch_bounds__(256) void spmmL2_sel_kernel(
    const float4* __restrict__ Es, const float4* __restrict__ Gs1c, const float4* __restrict__ Gj1c,
    const int* __restrict__ j_ids, const int* __restrict__ s_ids)
{
    int gid = blockIdx.x;
    int warp = threadIdx.x >> 5;
    int lane = threadIdx.x & 31;
    if (gid < 128) {
        int i = gid * 8 + warp;
        int row = j_ids[i];
        spmm_row2m(g_ptr_j, g_ccol_j, g_cval_j, Es, Gs1c, g_smap,
                   (float4*)g_Tjec, (float4*)g_Tjgc, row, i, lane);
    } else {
        int i = (gid - 128) * 8 + warp;
        int row = s_ids[i];
        spmm_row1m(g_ptr_s, g_ccol_s, g_cval_s, Gj1c, g_jmap, (float4*)g_Tsgc, row, i, lane);
    }
}

// ---------------- GEMM core (double-buffered 128x128x16 NT) ----------------
__device__ __forceinline__ void gemm_core(
    const float* __restrict__ A, const float* __restrict__ W,
    int rowTile, int colTile, int M, float (&acc)[8][8],
    float (&As)[2][16][128], float (&Bs)[2][16][128])
{
    int tid = threadIdx.x;
    int tx = tid & 15, ty = tid >> 4;
    #pragma unroll
    for (int i = 0; i < 8; i++)
        #pragma unroll
        for (int j = 0; j < 8; j++) acc[i][j] = 0.f;

    int lrow = tid & 127;
    int khalf = (tid >> 7) * 8;
    const float* Ag = A + (size_t)(rowTile + lrow) * DIMc + khalf;
    const float* Wg = W + (size_t)(colTile + lrow) * DIMc + khalf;
    bool arow_ok = (rowTile + lrow) < M;
    const float4 z4 = make_float4(0.f, 0.f, 0.f, 0.f);

    float4 ra0 = arow_ok ? *(const float4*)(Ag + 0) : z4;
    float4 ra1 = arow_ok ? *(const float4*)(Ag + 4) : z4;
    float4 rb0 = *(const float4*)(Wg + 0);
    float4 rb1 = *(const float4*)(Wg + 4);
    As[0][khalf+0][lrow] = ra0.x; As[0][khalf+1][lrow] = ra0.y;
    As[0][khalf+2][lrow] = ra0.z; As[0][khalf+3][lrow] = ra0.w;
    As[0][khalf+4][lrow] = ra1.x; As[0][khalf+5][lrow] = ra1.y;
    As[0][khalf+6][lrow] = ra1.z; As[0][khalf+7][lrow] = ra1.w;
    Bs[0][khalf+0][lrow] = rb0.x; Bs[0][khalf+1][lrow] = rb0.y;
    Bs[0][khalf+2][lrow] = rb0.z; Bs[0][khalf+3][lrow] = rb0.w;
    Bs[0][khalf+4][lrow] = rb1.x; Bs[0][khalf+5][lrow] = rb1.y;
    Bs[0][khalf+6][lrow] = rb1.z; Bs[0][khalf+7][lrow] = rb1.w;
    __syncthreads();

    int buf = 0;
    for (int k0 = 16; k0 <= DIMc; k0 += 16) {
        bool more = k0 < DIMc;
        if (more) {
            ra0 = arow_ok ? *(const float4*)(Ag + k0) : z4;
            ra1 = arow_ok ? *(const float4*)(Ag + k0 + 4) : z4;
            rb0 = *(const float4*)(Wg + k0);
            rb1 = *(const float4*)(Wg + k0 + 4);
        }
        #pragma unroll
        for (int kk = 0; kk < 16; kk++) {
            float a[8], b[8];
            #pragma unroll
            for (int i = 0; i < 4; i++) {
                a[i]   = As[buf][kk][ty*4 + i];
                a[i+4] = As[buf][kk][ty*4 + i + 64];
                b[i]   = Bs[buf][kk][tx*4 + i];
                b[i+4] = Bs[buf][kk][tx*4 + i + 64];
            }
            #pragma unroll
            for (int i = 0; i < 8; i++)
                #pragma unroll
                for (int j = 0; j < 8; j++)
                    acc[i][j] = fmaf(a[i], b[j], acc[i][j]);
        }
        if (more) {
            int nb = buf ^ 1;
            As[nb][khalf+0][lrow] = ra0.x; As[nb][khalf+1][lrow] = ra0.y;
            As[nb][khalf+2][lrow] = ra0.z; As[nb][khalf+3][lrow] = ra0.w;
            As[nb][khalf+4][lrow] = ra1.x; As[nb][khalf+5][lrow] = ra1.y;
            As[nb][khalf+6][lrow] = ra1.z; As[nb][khalf+7][lrow] = ra1.w;
            Bs[nb][khalf+0][lrow] = rb0.x; Bs[nb][khalf+1][lrow] = rb0.y;
            Bs[nb][khalf+2][lrow] = rb0.z; Bs[nb][khalf+3][lrow] = rb0.w;
            Bs[nb][khalf+4][lrow] = rb1.x; Bs[nb][khalf+5][lrow] = rb1.y;
            Bs[nb][khalf+6][lrow] = rb1.z; Bs[nb][khalf+7][lrow] = rb1.w;
            __syncthreads();
            buf = nb;
        }
    }
}

// full-row GEMM with update epilogue: nv = old + relu(C); wout write; smode 0/1
__global__ __launch_bounds__(256, 2) void gemm_update_kernel(
    const float* __restrict__ A, const float* __restrict__ W,
    const float* __restrict__ oldv, float* __restrict__ outv, float* __restrict__ sumv,
    int M, int wout, int smode)
{
    __shared__ float As[2][16][128];
    __shared__ float Bs[2][16][128];
    float acc[8][8];
    int rowTile = blockIdx.y * 128, colTile = blockIdx.x * 128;
    gemm_core(A, W, rowTile, colTile, M, acc, As, Bs);
    int tid = threadIdx.x, tx = tid & 15, ty = tid >> 4;
    #pragma unroll
    for (int i = 0; i < 8; i++) {
        int gr = rowTile + ty*4 + (i & 3) + ((i >> 2) * 64);
        if (gr < M) {
            #pragma unroll
            for (int j = 0; j < 8; j++) {
                int gc = colTile + tx*4 + (j & 3) + ((j >> 2) * 64);
                size_t idx = (size_t)gr * DIMc + gc;
                float v = fmaxf(acc[i][j], 0.f);
                float o = oldv[idx];
                float nv = o + v;
                if (wout) outv[idx] = nv;
                if (smode == 1) sumv[idx] = o + nv;
            }
        }
    }
}

// compact Es GEMM: rows ulist; scatter Es[orig] = e_s_f[orig]+relu; sEs[orig] = old+new
__global__ __launch_bounds__(256, 2) void gemm_esc_kernel(
    const float* __restrict__ W, const float* __restrict__ e_s_f)
{
    int M = g_ucnt_sel;
    int rowTile = blockIdx.y * 128;
    if (rowTile >= M) return;
    __shared__ float As[2][16][128];
    __shared__ float Bs[2][16][128];
    float acc[8][8];
    int colTile = blockIdx.x * 128;
    gemm_core(g_Tse, W, rowTile, colTile, M, acc, As, Bs);
    int tid = threadIdx.x, tx = tid & 15, ty = tid >> 4;
    #pragma unroll
    for (int i = 0; i < 8; i++) {
        int gr = rowTile + ty*4 + (i & 3) + ((i >> 2) * 64);
        if (gr < M) {
            int orig = g_ulist[gr];
            #pragma unroll
            for (int j = 0; j < 8; j++) {
                int gc = colTile + tx*4 + (j & 3) + ((j >> 2) * 64);
                size_t idx = (size_t)orig * DIMc + gc;
                float v = fmaxf(acc[i][j], 0.f);
                float o = e_s_f[idx];
                float nv = o + v;
                g_Es[idx] = nv;
                g_sEs[idx] = o + nv;
            }
        }
    }
}

// compact G1 GEMM: rows compact; oldv indexed by orig id via list; out compact
__global__ __launch_bounds__(256, 2) void gemm_gc_kernel(
    const float* __restrict__ A, const float* __restrict__ W,
    const float* __restrict__ oldv, float* __restrict__ outv, int side)
{
    int M = side ? g_scnt_sel : g_jcnt_sel;
    const int* list = side ? g_slist : g_jlist;
    int rowTile = blockIdx.y * 128;
    if (rowTile >= M) return;
    __shared__ float As[2][16][128];
    __shared__ float Bs[2][16][128];
    float acc[8][8];
    int colTile = blockIdx.x * 128;
    gemm_core(A, W, rowTile, colTile, M, acc, As, Bs);
    int tid = threadIdx.x, tx = tid & 15, ty = tid >> 4;
    #pragma unroll
    for (int i = 0; i < 8; i++) {
        int gr = rowTile + ty*4 + (i & 3) + ((i >> 2) * 64);
        if (gr < M) {
            int orig = list[gr];
            #pragma unroll
            for (int j = 0; j < 8; j++) {
                int gc = colTile + tx*4 + (j & 3) + ((j >> 2) * 64);
                float v = fmaxf(acc[i][j], 0.f);
                outv[(size_t)gr * DIMc + gc] = oldv[(size_t)orig * DIMc + gc] + v;
            }
        }
    }
}

// compact Es2 GEMM: rows = nlist; out g_Tse[w] = sEs_partial[orig] + Es[orig] + relu(C)
__global__ __launch_bounds__(256, 2) void gemm_es2c_kernel(const float* __restrict__ W)
{
    int M = g_ncnt_sel;
    int rowTile = blockIdx.y * 128;
    if (rowTile >= M) return;
    __shared__ float As[2][16][128];
    __shared__ float Bs[2][16][128];
    float acc[8][8];
    int colTile = blockIdx.x * 128;
    gemm_core(g_Tje, W, rowTile, colTile, M, acc, As, Bs);
    int tid = threadIdx.x, tx = tid & 15, ty = tid >> 4;
    #pragma unroll
    for (int i = 0; i < 8; i++) {
        int gr = rowTile + ty*4 + (i & 3) + ((i >> 2) * 64);
        if (gr < M) {
            int orig = g_nlist[gr];
            #pragma unroll
            for (int j = 0; j < 8; j++) {
                int gc = colTile + tx*4 + (j & 3) + ((j >> 2) * 64);
                size_t src = (size_t)orig * DIMc + gc;
                float v = fmaxf(acc[i][j], 0.f);
                g_Tse[(size_t)gr * DIMc + gc] = g_sEs[src] + g_Es[src] + v;
            }
        }
    }
}

// selected GEMM: dst[i,:] = base0[ids[i]] + 2*base1[map? map[ids[i]] : ids[i]] + relu(Ac@W^T)
__global__ __launch_bounds__(256, 2) void gemm_sel_kernel(
    const float* __restrict__ e_j_f,
    const float* __restrict__ Wj2, const float* __restrict__ Wja2, const float* __restrict__ Wsa2,
    const int* __restrict__ j_ids, const int* __restrict__ s_ids)
{
    __shared__ float As[2][16][128];
    __shared__ float Bs[2][16][128];
    const float* A; const float* W; const float* base0; const float* base1;
    const int* map1; float* dst; const int* ids;
    switch (blockIdx.z) {
        case 0: A = g_Tjec; W = Wj2;  base0 = e_j_f; base1 = g_Ej;  map1 = 0;      dst = g_ejsel; ids = j_ids; break;
        case 1: A = g_Tjgc; W = Wja2; base0 = g_Gj;  base1 = g_Gj1; map1 = g_jmap; dst = g_gjsel; ids = j_ids; break;
        default: A = g_Tsgc; W = Wsa2; base0 = g_Gs; base1 = g_Gs1; map1 = g_smap; dst = g_gssel; ids = s_ids; break;
    }
    float acc[8][8];
    int rowTile = blockIdx.y * 128, colTile = blockIdx.x * 128;
    gemm_core(A, W, rowTile, colTile, Bc, acc, As, Bs);
    int tid = threadIdx.x, tx = tid & 15, ty = tid >> 4;
    #pragma unroll
    for (int i = 0; i < 8; i++) {
        int gr = rowTile + ty*4 + (i & 3) + ((i >> 2) * 64);
        int id = ids[gr];
        int id1 = map1 ? map1[id] : id;
        #pragma unroll
        for (int j = 0; j < 8; j++) {
            int gc = colTile + tx*4 + (j & 3) + ((j >> 2) * 64);
            float v = fmaxf(acc[i][j], 0.f);
            dst[(size_t)gr * DIMc + gc] =
                base0[(size_t)id * DIMc + gc] + 2.f * base1[(size_t)id1 * DIMc + gc] + v;
        }
    }
}

// ---------------- GEMM + exp + per-(row,group) sum ----------------
__global__ __launch_bounds__(256, 2) void expsum_kernel(
    const float* __restrict__ A, const float* __restrict__ Bm,
    float* __restrict__ sumexp, int ngroups)
{
    __shared__ float As[2][16][128];
    __shared__ float Bs[2][16][128];
    __shared__ float red[128];
    float acc[8][8];
    int rowTile = blockIdx.y * 128, colTile = blockIdx.x * 128;
    gemm_core(A, Bm, rowTile, colTile, 1 << 30, acc, As, Bs);
    int tid = threadIdx.x, tx = tid & 15, ty = tid >> 4;
    float rsum[8];
    #pragma unroll
    for (int i = 0; i < 8; i++) {
        rsum[i] = 0.f;
        #pragma unroll
        for (int j = 0; j < 8; j++) rsum[i] += expf(acc[i][j] * 5.0f);  // 1/TEMP = 5
    }
    if (tid < 128) red[tid] = 0.f;
    __syncthreads();
    #pragma unroll
    for (int i = 0; i < 8; i++) {
        int r = ty*4 + (i & 3) + ((i >> 2) * 64);
        atomicAdd(&red[r], rsum[i]);
    }
    __syncthreads();
    if (tid < 128) {
        int gr = rowTile + tid;
        int group = blockIdx.x >> 3;
        atomicAdd(&sumexp[(size_t)gr * ngroups + group], red[tid]);
    }
}

// ---------------- combined gather from compact sEs (g_Tse) via nmap ----------------
__global__ void gatherNE_kernel(const int* __restrict__ negs, const int* __restrict__ s_ids) {
    int row = blockIdx.x;
    const float4* src = (const float4*)g_Tse;
    if (row < NEGRc) {
        int id = g_nmap[negs[row]];
        ((float4*)g_negemb)[(size_t)row * D4c + threadIdx.x] = src[(size_t)id * D4c + threadIdx.x];
    } else {
        int r = row - NEGRc;
        int id = g_nmap[s_ids[r]];
        ((float4*)g_essel)[(size_t)r * D4c + threadIdx.x] = src[(size_t)id * D4c + threadIdx.x];
    }
}

// ---------------- pos score ----------------
__global__ void pos_kernel() {
    int w = (blockIdx.x * blockDim.x + threadIdx.x) >> 5;
    int lane = threadIdx.x & 31;
    if (w >= Bc) return;
    const float4* gj = (const float4*)g_gjsel + (size_t)w * D4c;
    const float4* ej = (const float4*)g_ejsel + (size_t)w * D4c;
    const float4* gs = (const float4*)g_gssel + (size_t)w * D4c;
    const float4* es = (const float4*)g_essel + (size_t)w * D4c;
    float4 a0 = gj[lane], a1 = gj[lane+32], b0 = ej[lane], b1 = ej[lane+32];
    float4 c0 = gs[lane], c1 = gs[lane+32], d0 = es[lane], d1 = es[lane+32];
    float s1 = a0.x*b0.x + a0.y*b0.y + a0.z*b0.z + a0.w*b0.w
             + a1.x*b1.x + a1.y*b1.y + a1.z*b1.z + a1.w*b1.w;
    float s2 = c0.x*d0.x + c0.y*d0.y + c0.z*d0.z + c0.w*d0.w
             + c1.x*d1.x + c1.y*d1.y + c1.z*d1.z + c1.w*d1.w;
    #pragma unroll
    for (int o = 16; o; o >>= 1) {
        s1 += __shfl_xor_sync(0xffffffffu, s1, o);
        s2 += __shfl_xor_sync(0xffffffffu, s2, o);
    }
    if (lane == 0) {
        float c1v = fminf(fmaxf(s1 * 5.0f, -1.f), 1.f);
        float c2v = fminf(fmaxf(s2 * 5.0f, -1.f), 1.f);
        atomicAdd(&g_scalars[0], c1v);
        atomicAdd(&g_scalars[1], c2v);
    }
}

// ---------------- weight L2 regularizer ----------------
__global__ void wsq_kernel(const float* __restrict__ a, const float* __restrict__ b,
                           const float* __restrict__ c, const float* __restrict__ d) {
    float s = 0.f;
    for (int i = blockIdx.x * blockDim.x + threadIdx.x; i < WSZc; i += gridDim.x * blockDim.x) {
        float x;
        x = a[i]; s += x * x;
        x = b[i]; s += x * x;
        x = c[i]; s += x * x;
        x = d[i]; s += x * x;
    }
    #pragma unroll
    for (int o = 16; o; o >>= 1) s += __shfl_xor_sync(0xffffffffu, s, o);
    __shared__ float sh[8];
    int lane = threadIdx.x & 31, wid = threadIdx.x >> 5;
    if (lane == 0) sh[wid] = s;
    __syncthreads();
    if (threadIdx.x == 0) {
        float t = 0.f;
        for (int i = 0; i < (int)(blockDim.x >> 5); i++) t += sh[i];
        atomicAdd(&g_scalars[2], t);
    }
}

// ---------------- finalize ----------------
__device__ double blk_reduce_1024(double v) {
    __shared__ double sh[32];
    __syncthreads();
    int lane = threadIdx.x & 31, wid = threadIdx.x >> 5;
    #pragma unroll
    for (int o = 16; o; o >>= 1) v += __shfl_down_sync(0xffffffffu, v, o);
    if (lane == 0) sh[wid] = v;
    __syncthreads();
    v = (threadIdx.x < 32) ? sh[threadIdx.x] : 0.0;
    if (wid == 0) {
        #pragma unroll
        for (int o = 16; o; o >>= 1) v += __shfl_down_sync(0xffffffffu, v, o);
    }
    return v;
}

__global__ void finalize_kernel(float* __restrict__ out) {
    int tid = threadIdx.x;
    double a = (tid < Bc) ? log((double)g_sumexp_j[tid] + 1e-8) : 0.0;
    double negj = blk_reduce_1024(a);
    double b = 0.0;
    for (int i = tid; i < Bc * NNEGc; i += 1024)
        b += log((double)g_sumexp_s[i] + 1e-8);
    double negs = blk_reduce_1024(b);
    if (tid == 0) {
        double pos = (double)g_scalars[0] / Bc + (double)g_scalars[1] / Bc;
        double neg = negj / Bc + negs / (double)(Bc * NNEGc);
        double cl = (-pos + neg) * 0.2;
        double reg = 1e-4 * (double)g_scalars[2];
        out[0] = (float)(cl + reg);
        out[1] = (float)cl;
        out[2] = (float)reg;
    }
}

// ---------------- launch ----------------
#define SYM(p, s) do { void* _t = 0; cudaGetSymbolAddress(&_t, s); p = (decltype(p))_t; } while (0)

extern "C" void kernel_launch(void* const* d_in, const int* in_sizes, int n_in,
                              void* d_out, int out_size) {
    (void)in_sizes; (void)n_in; (void)out_size;
    const float* e_j_f   = (const float*)d_in[0];
    const float* e_s_f   = (const float*)d_in[1];
    const float* aug_e_j = (const float*)d_in[2];
    const float* aug_e_s = (const float*)d_in[3];
    const float* val_j   = (const float*)d_in[4];
    const float* val_s   = (const float*)d_in[5];
    const float* W_j     = (const float*)d_in[6];
    const float* W_s     = (const float*)d_in[7];
    const float* W_j_aug = (const float*)d_in[8];
    const float* W_s_aug = (const float*)d_in[9];
    const int* row_j = (const int*)d_in[10];
    const int* col_j = (const int*)d_in[11];
    const int* row_s = (const int*)d_in[12];
    const int* col_s = (const int*)d_in[13];
    const int* j_ids = (const int*)d_in[14];
    const int* s_ids = (const int*)d_in[15];
    const int* negs  = (const int*)d_in[16];
    float* out = (float*)d_out;

    float *Ej, *Es, *Gj, *Gs, *Gj1, *Gs1, *Tje, *Tjg, *Tse, *Tsg;
    float *gjsel, *ejsel, *gssel, *negemb, *sumexp_j, *sumexp_s;
    SYM(Ej, g_Ej); SYM(Es, g_Es); SYM(Gj, g_Gj); SYM(Gs, g_Gs);
    SYM(Gj1, g_Gj1); SYM(Gs1, g_Gs1);
    SYM(Tje, g_Tje); SYM(Tjg, g_Tjg); SYM(Tse, g_Tse); SYM(Tsg, g_Tsg);
    SYM(gjsel, g_gjsel); SYM(ejsel, g_ejsel); SYM(gssel, g_gssel);
    SYM(negemb, g_negemb); SYM(sumexp_j, g_sumexp_j); SYM(sumexp_s, g_sumexp_s);

    static int inited = 0;
    static cudaStream_t s1;
    static cudaEvent_t evStart, evL2n, evCsr, evCmp, evGspmm, evEj, evTse, evG, evSel, evGat, evLoss;
    if (!inited) {
        cudaStreamCreateWithFlags(&s1, cudaStreamNonBlocking);
        cudaEventCreateWithFlags(&evStart, cudaEventDisableTiming);
        cudaEventCreateWithFlags(&evL2n,   cudaEventDisableTiming);
        cudaEventCreateWithFlags(&evCsr,   cudaEventDisableTiming);
        cudaEventCreateWithFlags(&evCmp,   cudaEventDisableTiming);
        cudaEventCreateWithFlags(&evGspmm, cudaEventDisableTiming);
        cudaEventCreateWithFlags(&evEj,    cudaEventDisableTiming);
        cudaEventCreateWithFlags(&evTse,   cudaEventDisableTiming);
        cudaEventCreateWithFlags(&evG,     cudaEventDisableTiming);
        cudaEventCreateWithFlags(&evSel,   cudaEventDisableTiming);
        cudaEventCreateWithFlags(&evGat,   cudaEventDisableTiming);
        cudaEventCreateWithFlags(&evLoss,  cudaEventDisableTiming);
        inited = 1;
    }

    const int EB = (Ec + 255) / 256;         // 6250
    const int RB = 6250;

    zero_kernel<<<256, 256>>>();
    mark_neg_kernel<<<(NEGRc + Bc + 255) / 256, 256>>>(negs, s_ids);
    cudaEventRecord(evStart, 0);
    cudaStreamWaitEvent(s1, evStart, 0);

    // side: initial l2norm + wsq
    {
        dim3 g(RB, 2);
        l2norm4_kernel<<<g, 256, 0, s1>>>((const float4*)aug_e_j, (float4*)Gj,
                                          (const float4*)aug_e_s, (float4*)Gs,
                                          (const float4*)aug_e_j, (float4*)Gj,
                                          (const float4*)aug_e_s, (float4*)Gs, NJc);
        wsq_kernel<<<256, 256, 0, s1>>>(W_j, W_s, W_j_aug, W_s_aug);
        cudaEventRecord(evL2n, s1);
    }
    // default: CSR build
    count_kernel<<<EB, 256>>>(row_j, col_s);
    scan2_kernel<<<2, 1024>>>();
    scatter_kernel<<<EB, 256>>>(row_j, col_j, val_j, row_s, col_s, val_s);
    cudaEventRecord(evCsr, 0);

    // side: mark + compact (evCmp), then compact G SPMMs
    cudaStreamWaitEvent(s1, evCsr, 0);
    mark_kernel<<<128, 256, 0, s1>>>(j_ids, s_ids);
    compact_kernel<<<(NJc + 255) / 256, 256, 0, s1>>>();
    cudaEventRecord(evCmp, s1);
    {
        dim3 gg(RB, 2);
        spmmG2_kernel<<<gg, 256, 0, s1>>>((const float4*)Gs, (const float4*)Gj);
    }
    cudaEventRecord(evGspmm, s1);

    // default: E-path L1 SPMM j side (full, no compaction dep) then compact s side
    spmmEj_kernel<<<RB, 256>>>((const float4*)e_s_f);
    cudaStreamWaitEvent(0, evCmp, 0);
    spmmEsC_kernel<<<RB, 256>>>((const float4*)e_j_f);
    dim3 gemm_grid(2, 391);
    gemm_update_kernel<<<gemm_grid, 256>>>(Tje, W_j, e_j_f, Ej, (float*)0, NJc, 1, 0);
    cudaEventRecord(evEj, 0);

    // side: compact Tse2 SPMM into freed g_Tje
    cudaStreamWaitEvent(s1, evEj, 0);
    spmmL2_tse_kernel<<<RB, 256, 0, s1>>>((const float4*)Ej, (float4*)Tje);
    cudaEventRecord(evTse, s1);

    // default: compact Es GEMM (scatter Es/sEs), then compact G1 GEMMs
    gemm_esc_kernel<<<gemm_grid, 256>>>(W_s, e_s_f);
    cudaStreamWaitEvent(0, evGspmm, 0);
    gemm_gc_kernel<<<gemm_grid, 256>>>(Tjg, W_j_aug, Gj, Gj1, 0);
    gemm_gc_kernel<<<gemm_grid, 256>>>(Tsg, W_s_aug, Gs, Gs1, 1);
    cudaEventRecord(evG, 0);

    // side: compacted selected chain
    cudaStreamWaitEvent(s1, evG, 0);
    spmmL2_sel_kernel<<<256, 256, 0, s1>>>((const float4*)Es, (const float4*)Gs1,
                                           (const float4*)Gj1, j_ids, s_ids);
    {
        dim3 sg(2, 8, 3);
        gemm_sel_kernel<<<sg, 256, 0, s1>>>(e_j_f, W_j + DIMc*DIMc, W_j_aug + DIMc*DIMc,
                                            W_s_aug + DIMc*DIMc, j_ids, s_ids);
    }
    l2norm4_kernel<<<dim3(128, 3), 256, 0, s1>>>(
        (const float4*)ejsel, (float4*)ejsel,
        (const float4*)gjsel, (float4*)gjsel,
        (const float4*)gssel, (float4*)gssel,
        (const float4*)gssel, (float4*)gssel, Bc);
    cudaEventRecord(evSel, s1);

    // default: compact Es L2 chain (GEMM writes compact sEs into g_Tse, l2norm, gather)
    cudaStreamWaitEvent(0, evTse, 0);
    gemm_es2c_kernel<<<gemm_grid, 256>>>(W_s + DIMc*DIMc);
    l2normC_kernel<<<RB, 256>>>();
    gatherNE_kernel<<<NEGRc + Bc, 64>>>(negs, s_ids);
    cudaEventRecord(evGat, 0);

    // side: small losses
    cudaStreamWaitEvent(s1, evGat, 0);
    {
        dim3 lg(Bc / 128, Bc / 128);
        expsum_kernel<<<lg, 256, 0, s1>>>(gjsel, ejsel, sumexp_j, 1);
        pos_kernel<<<Bc / 8, 256, 0, s1>>>();
        cudaEventRecord(evLoss, s1);
    }
    // default: big expsum
    cudaStreamWaitEvent(0, evSel, 0);
    {
        dim3 ng(NEGRc / 128, Bc / 128);
        expsum_kernel<<<ng, 256>>>(gssel, negemb, sumexp_s, NNEGc);
    }
    cudaStreamWaitEvent(0, evLoss, 0);
    finalize_kernel<<<1, 1024>>>(out);
}